// round 2
// baseline (speedup 1.0000x reference)
#include <cuda_runtime.h>

#define NN  50000
#define EE  800000
#define DD  512
#define KK  128
#define TJc 4
#define SSc 128
#define DD2 1024
#define EPSC 1e-5f

// ---------------- scratch (device globals; no allocations allowed) ----------
__device__ float g_xw  [(size_t)NN * DD];        // x @ gcn_W
__device__ float g_bufL[(size_t)NN * DD];        // GCN agg -> BN1l input
__device__ float g_ht  [(size_t)NN * DD];        // packed ht [N, TJ*S]
__device__ float g_v   [(size_t)TJc * NN * SSc]; // v per t, contiguous [t][N][S]
__device__ float g_comb[(size_t)NN * DD];        // wave comb
__device__ float g_bufA[(size_t)NN * DD];        // fusion out -> BN1a input
__device__ float g_h   [(size_t)NN * DD];        // h = bnL + bnA
__device__ float g_mid [(size_t)NN * DD2];       // ff hidden
__device__ float g_ff  [(size_t)NN * DD];        // ff out -> BN2 input
__device__ float g_norm[EE];
__device__ float g_deg [NN];                     // deg -> dinv
__device__ float g_u   [TJc * KK * SSc];
__device__ float g_u2  [TJc * KK * SSc];
__device__ float g_stats[6 * DD];                // 3 BNs x {sum, sumsq}
__device__ float g_coef [6 * DD];                // 3 BNs x {scale, shift}
__device__ float g_linW2[DD * DD];               // packed lin_W [D, TJ*S]
__device__ int   g_is64;                         // edge_index dtype flag

// ---------------- edge-index dtype detection --------------------------------
// int64 values < 2^31: every odd 32-bit word is 0. int32 data: odd words are
// real edge indices (random in [0,50000)) -> essentially never all zero.
__global__ void detect_k(const int* __restrict__ ei32) {
    __shared__ int any;
    if (threadIdx.x == 0) any = 0;
    __syncthreads();
    int v = 0;
    for (int i = threadIdx.x; i < 1024; i += blockDim.x)
        v |= ei32[2 * i + 1];
    if (v) atomicOr(&any, 1);
    __syncthreads();
    if (threadIdx.x == 0) g_is64 = (any == 0) ? 1 : 0;
}

__device__ __forceinline__ int edge_at(const void* ei, long long pos) {
    return g_is64 ? (int)((const long long*)ei)[pos] : ((const int*)ei)[pos];
}

// ---------------- zero scratch that is atomically accumulated ---------------
__global__ void zero_scratch_k() {
    int stride = gridDim.x * blockDim.x;
    int i0 = blockIdx.x * blockDim.x + threadIdx.x;
    for (size_t i = i0; i < (size_t)NN * DD; i += stride) g_bufL[i] = 0.f;
    for (int i = i0; i < NN; i += stride) g_deg[i] = 0.f;
    for (int i = i0; i < TJc * KK * SSc; i += stride) { g_u[i] = 0.f; g_u2[i] = 0.f; }
    for (int i = i0; i < 6 * DD; i += stride) g_stats[i] = 0.f;
}

// ---------------- generic tiled SGEMM: C[M x (grid.x*128)] = A*B ------------
template <bool BIAS, bool RELU>
__global__ void __launch_bounds__(256) sgemm_k(
    const float* __restrict__ A, int lda,
    const float* __restrict__ B, int ldb,
    float* __restrict__ C, int ldc,
    const float* __restrict__ bias,
    int M, int Kd)
{
    __shared__ float As[16][128];
    __shared__ float Bs[16][128];
    const int m0 = blockIdx.y * 128;
    const int n0 = blockIdx.x * 128;
    const int tid = threadIdx.x;
    const int ty = tid >> 4, tx = tid & 15;
    float acc[8][8] = {};

    for (int k0 = 0; k0 < Kd; k0 += 16) {
        #pragma unroll
        for (int l = 0; l < 2; l++) {
            int i = tid + l * 256;
            int r = i >> 2, c4 = (i & 3) * 4;
            float4 v = make_float4(0.f, 0.f, 0.f, 0.f);
            if (m0 + r < M)
                v = *reinterpret_cast<const float4*>(&A[(size_t)(m0 + r) * lda + k0 + c4]);
            As[c4 + 0][r] = v.x; As[c4 + 1][r] = v.y;
            As[c4 + 2][r] = v.z; As[c4 + 3][r] = v.w;
        }
        #pragma unroll
        for (int l = 0; l < 2; l++) {
            int i = tid + l * 256;
            int r = i >> 5, c = (i & 31) * 4;
            float4 v = *reinterpret_cast<const float4*>(&B[(size_t)(k0 + r) * ldb + n0 + c]);
            *reinterpret_cast<float4*>(&Bs[r][c]) = v;
        }
        __syncthreads();
        #pragma unroll
        for (int kk = 0; kk < 16; kk++) {
            float4 a0 = *reinterpret_cast<const float4*>(&As[kk][ty * 8]);
            float4 a1 = *reinterpret_cast<const float4*>(&As[kk][ty * 8 + 4]);
            float4 b0 = *reinterpret_cast<const float4*>(&Bs[kk][tx * 8]);
            float4 b1 = *reinterpret_cast<const float4*>(&Bs[kk][tx * 8 + 4]);
            float a[8] = {a0.x, a0.y, a0.z, a0.w, a1.x, a1.y, a1.z, a1.w};
            float b[8] = {b0.x, b0.y, b0.z, b0.w, b1.x, b1.y, b1.z, b1.w};
            #pragma unroll
            for (int i = 0; i < 8; i++)
                #pragma unroll
                for (int j = 0; j < 8; j++)
                    acc[i][j] = fmaf(a[i], b[j], acc[i][j]);
        }
        __syncthreads();
    }
    #pragma unroll
    for (int i = 0; i < 8; i++) {
        int m = m0 + ty * 8 + i;
        if (m >= M) continue;
        #pragma unroll
        for (int j = 0; j < 8; j += 4) {
            int n = n0 + tx * 8 + j;
            float4 v = make_float4(acc[i][j], acc[i][j + 1], acc[i][j + 2], acc[i][j + 3]);
            if (BIAS) {
                v.x += bias[n]; v.y += bias[n + 1]; v.z += bias[n + 2]; v.w += bias[n + 3];
            }
            if (RELU) {
                v.x = fmaxf(v.x, 0.f); v.y = fmaxf(v.y, 0.f);
                v.z = fmaxf(v.z, 0.f); v.w = fmaxf(v.w, 0.f);
            }
            *reinterpret_cast<float4*>(&C[(size_t)m * ldc + n]) = v;
        }
    }
}

// ------------ tall reduction: C[128,128] += evc^T[128,N] * B[N,128] ---------
__global__ void __launch_bounds__(256) atb_k(
    const float* __restrict__ evc,
    const float* __restrict__ B, int ldb,
    float* __restrict__ C)
{
    __shared__ float Es[16][128];
    __shared__ float Hs[16][128];
    const int chunk = (NN + gridDim.x - 1) / gridDim.x;
    const int nStart = blockIdx.x * chunk;
    const int nEnd = min(nStart + chunk, NN);
    const int tid = threadIdx.x;
    const int ty = tid >> 4, tx = tid & 15;
    float acc[8][8] = {};

    for (int n0 = nStart; n0 < nEnd; n0 += 16) {
        #pragma unroll
        for (int l = 0; l < 2; l++) {
            int i = tid + l * 256;
            int r = i >> 5, c = (i & 31) * 4;
            int n = n0 + r;
            float4 ve = make_float4(0.f, 0.f, 0.f, 0.f);
            float4 vh = make_float4(0.f, 0.f, 0.f, 0.f);
            if (n < nEnd) {
                ve = *reinterpret_cast<const float4*>(&evc[(size_t)n * KK + c]);
                vh = *reinterpret_cast<const float4*>(&B[(size_t)n * ldb + c]);
            }
            *reinterpret_cast<float4*>(&Es[r][c]) = ve;
            *reinterpret_cast<float4*>(&Hs[r][c]) = vh;
        }
        __syncthreads();
        #pragma unroll
        for (int kk = 0; kk < 16; kk++) {
            float4 a0 = *reinterpret_cast<const float4*>(&Es[kk][ty * 8]);
            float4 a1 = *reinterpret_cast<const float4*>(&Es[kk][ty * 8 + 4]);
            float4 b0 = *reinterpret_cast<const float4*>(&Hs[kk][tx * 8]);
            float4 b1 = *reinterpret_cast<const float4*>(&Hs[kk][tx * 8 + 4]);
            float a[8] = {a0.x, a0.y, a0.z, a0.w, a1.x, a1.y, a1.z, a1.w};
            float b[8] = {b0.x, b0.y, b0.z, b0.w, b1.x, b1.y, b1.z, b1.w};
            #pragma unroll
            for (int i = 0; i < 8; i++)
                #pragma unroll
                for (int j = 0; j < 8; j++)
                    acc[i][j] = fmaf(a[i], b[j], acc[i][j]);
        }
        __syncthreads();
    }
    #pragma unroll
    for (int i = 0; i < 8; i++)
        #pragma unroll
        for (int j = 0; j < 8; j++)
            atomicAdd(&C[(ty * 8 + i) * 128 + tx * 8 + j], acc[i][j]);
}

// ---------------- graph kernels ---------------------------------------------
__global__ void deg_k(const void* __restrict__ ei) {
    int e = blockIdx.x * blockDim.x + threadIdx.x;
    if (e < EE) atomicAdd(&g_deg[edge_at(ei, (long long)EE + e)], 1.0f);
}
__global__ void dinv_k() {
    int n = blockIdx.x * blockDim.x + threadIdx.x;
    if (n < NN) g_deg[n] = rsqrtf(g_deg[n] + 1.0f);
}
__global__ void norm_k(const void* __restrict__ ei) {
    int e = blockIdx.x * blockDim.x + threadIdx.x;
    if (e < EE) g_norm[e] = g_deg[edge_at(ei, e)] * g_deg[edge_at(ei, (long long)EE + e)];
}
__global__ void scatter_k(const void* __restrict__ ei) {
    long long idx = (long long)blockIdx.x * blockDim.x + threadIdx.x;   // EE*128 total
    int e = (int)(idx >> 7);
    int c = ((int)idx & 127) * 4;
    int src = edge_at(ei, e);
    int dst = edge_at(ei, (long long)EE + e);
    float nrm = g_norm[e];
    float4 v = *reinterpret_cast<const float4*>(&g_xw[(size_t)src * DD + c]);
    float* o = &g_bufL[(size_t)dst * DD + c];
    atomicAdd(o + 0, nrm * v.x);
    atomicAdd(o + 1, nrm * v.y);
    atomicAdd(o + 2, nrm * v.z);
    atomicAdd(o + 3, nrm * v.w);
}

// bufL = x + (agg + dinv^2*xw + gcn_b); accumulate BN0 stats
__global__ void finish_gcn_k(const float* __restrict__ x, const float* __restrict__ gcn_b) {
    const int c = threadIdx.x;                // 512
    const int r0 = blockIdx.x * 128;
    const int rEnd = min(r0 + 128, NN);
    const float bc = gcn_b[c];
    float s = 0.f, s2 = 0.f;
    for (int r = r0; r < rEnd; r++) {
        size_t o = (size_t)r * DD + c;
        float dv = g_deg[r];
        float v = x[o] + g_bufL[o] + dv * dv * g_xw[o] + bc;
        g_bufL[o] = v;
        s += v; s2 += v * v;
    }
    atomicAdd(&g_stats[0 * DD + c], s);
    atomicAdd(&g_stats[1 * DD + c], s2);
}

// buf = x + buf; accumulate BN stats (bn = 1 or 2)
__global__ void addx_stats_k(const float* __restrict__ x, float* __restrict__ buf, int bn) {
    const int c = threadIdx.x;
    const int r0 = blockIdx.x * 128;
    const int rEnd = min(r0 + 128, NN);
    float s = 0.f, s2 = 0.f;
    for (int r = r0; r < rEnd; r++) {
        size_t o = (size_t)r * DD + c;
        float v = x[o] + buf[o];
        buf[o] = v;
        s += v; s2 += v * v;
    }
    atomicAdd(&g_stats[(bn * 2 + 0) * DD + c], s);
    atomicAdd(&g_stats[(bn * 2 + 1) * DD + c], s2);
}

__global__ void finalize_k(int bn, const float* __restrict__ gamma, const float* __restrict__ beta) {
    int c = threadIdx.x;  // 512
    float s  = g_stats[(bn * 2 + 0) * DD + c];
    float s2 = g_stats[(bn * 2 + 1) * DD + c];
    float m = s * (1.0f / NN);
    float var = s2 * (1.0f / NN) - m * m;
    float a = gamma[c] * rsqrtf(var + EPSC);
    g_coef[(bn * 2 + 0) * DD + c] = a;
    g_coef[(bn * 2 + 1) * DD + c] = beta[c] - m * a;
}

__global__ void apply_sum_k() {   // g_h = bn0(bufL) + bn1(bufA)
    int idx = blockIdx.x * blockDim.x + threadIdx.x;
    if (idx >= NN * DD) return;
    int c = idx & (DD - 1);
    g_h[idx] = g_bufL[idx] * g_coef[c] + g_coef[DD + c]
             + g_bufA[idx] * g_coef[2 * DD + c] + g_coef[3 * DD + c];
}
__global__ void bn2_apply_k(float* __restrict__ out) {
    int idx = blockIdx.x * blockDim.x + threadIdx.x;
    if (idx >= NN * DD) return;
    int c = idx & (DD - 1);
    out[idx] = g_ff[idx] * g_coef[4 * DD + c] + g_coef[5 * DD + c];
}

// ---------------- wave helpers ----------------------------------------------
__global__ void pack_linw_k(const float* __restrict__ linW) {
    int idx = blockIdx.x * blockDim.x + threadIdx.x;
    if (idx >= DD * DD) return;
    int d = idx >> 9, j = idx & 511;
    int t = j >> 7, s = j & 127;
    g_linW2[idx] = linW[t * (DD * SSc) + d * SSc + s];
}
__global__ void scale_sig_k(float* __restrict__ u, const float* __restrict__ fs) {
    int idx = blockIdx.x * blockDim.x + threadIdx.x;
    if (idx >= TJc * KK * SSc) return;
    int t = idx >> 14;           // / (K*S)
    int k = (idx >> 7) & 127;
    u[idx] *= fs[k * TJc + t];   // filter_signals[0][k][t]
}

// ---------------- launch -----------------------------------------------------
#define GSYM(p, s) do { void* _t; cudaGetSymbolAddress(&_t, s); (p) = (float*)_t; } while (0)

extern "C" void kernel_launch(void* const* d_in, const int* in_sizes, int n_in,
                              void* d_out, int out_size) {
    const float* x        = (const float*)d_in[0];
    const void*  ei       = d_in[1];
    const float* evc      = (const float*)d_in[2];
    const float* fs       = (const float*)d_in[3];
    const float* gcn_W    = (const float*)d_in[4];
    const float* gcn_b    = (const float*)d_in[5];
    const float* lin_W    = (const float*)d_in[6];
    const float* lin_b    = (const float*)d_in[7];
    const float* fusion_W = (const float*)d_in[8];
    const float* fusion_b = (const float*)d_in[9];
    const float* bn1l_g   = (const float*)d_in[10];
    const float* bn1l_b   = (const float*)d_in[11];
    const float* bn1a_g   = (const float*)d_in[12];
    const float* bn1a_b   = (const float*)d_in[13];
    const float* bn2_g    = (const float*)d_in[14];
    const float* bn2_b    = (const float*)d_in[15];
    const float* ff1_W    = (const float*)d_in[16];
    const float* ff1_b    = (const float*)d_in[17];
    const float* ff2_W    = (const float*)d_in[18];
    const float* ff2_b    = (const float*)d_in[19];
    float* out = (float*)d_out;

    float *p_xw, *p_bufL, *p_ht, *p_v, *p_comb, *p_bufA, *p_h, *p_mid, *p_ff;
    float *p_u, *p_u2, *p_linW2;
    GSYM(p_xw, g_xw);   GSYM(p_bufL, g_bufL); GSYM(p_ht, g_ht);
    GSYM(p_v, g_v);     GSYM(p_comb, g_comb); GSYM(p_bufA, g_bufA);
    GSYM(p_h, g_h);     GSYM(p_mid, g_mid);   GSYM(p_ff, g_ff);
    GSYM(p_u, g_u);     GSYM(p_u2, g_u2);     GSYM(p_linW2, g_linW2);

    const int MB = (NN + 127) / 128;           // 391 row tiles
    dim3 gD(DD / 128, MB);                     // 512 cols
    dim3 gS(SSc / 128, MB);                    // 128 cols
    dim3 gF(DD2 / 128, MB);                    // 1024 cols

    detect_k<<<1, 256>>>((const int*)ei);
    zero_scratch_k<<<2048, 256>>>();

    // ---- GCN branch ----
    sgemm_k<false, false><<<gD, 256>>>(x, DD, gcn_W, DD, p_xw, DD, nullptr, NN, DD);
    deg_k<<<(EE + 255) / 256, 256>>>(ei);
    dinv_k<<<(NN + 255) / 256, 256>>>();
    norm_k<<<(EE + 255) / 256, 256>>>(ei);
    scatter_k<<<(EE * 128) / 256, 256>>>(ei);
    finish_gcn_k<<<MB, DD>>>(x, gcn_b);        // -> g_bufL + BN0 stats

    // ---- Wave branch ----
    pack_linw_k<<<(DD * DD + 255) / 256, 256>>>(lin_W);
    sgemm_k<true, false><<<gD, 256>>>(x, DD, p_linW2, DD, p_ht, DD, lin_b, NN, DD);
    for (int t = 0; t < TJc; t++)
        atb_k<<<128, 256>>>(evc, p_ht + t * SSc, DD, p_u + t * KK * SSc);
    scale_sig_k<<<(TJc * KK * SSc + 255) / 256, 256>>>(p_u, fs);
    for (int t = 0; t < TJc; t++)
        sgemm_k<false, true><<<gS, 256>>>(evc, KK, p_u + t * KK * SSc, SSc,
                                          p_v + (size_t)t * NN * SSc, SSc, nullptr, NN, KK);
    for (int t = 0; t < TJc; t++)
        atb_k<<<128, 256>>>(evc, p_v + (size_t)t * NN * SSc, SSc, p_u2 + t * KK * SSc);
    scale_sig_k<<<(TJc * KK * SSc + 255) / 256, 256>>>(p_u2, fs);
    for (int t = 0; t < TJc; t++)
        sgemm_k<false, false><<<gS, 256>>>(evc, KK, p_u2 + t * KK * SSc, SSc,
                                           p_comb + t * SSc, DD, nullptr, NN, KK);
    sgemm_k<true, true><<<gD, 256>>>(p_comb, DD, fusion_W, DD, p_bufA, DD, fusion_b, NN, DD);
    addx_stats_k<<<MB, DD>>>(x, p_bufA, 1);    // -> g_bufA + BN1 stats

    // ---- combine + BN ----
    finalize_k<<<1, DD>>>(0, bn1l_g, bn1l_b);
    finalize_k<<<1, DD>>>(1, bn1a_g, bn1a_b);
    apply_sum_k<<<(NN * DD + 255) / 256, 256>>>();   // -> g_h

    // ---- feed-forward ----
    sgemm_k<true, true><<<gF, 256>>>(p_h, DD, ff1_W, DD2, p_mid, DD2, ff1_b, NN, DD);
    sgemm_k<true, false><<<gD, 256>>>(p_mid, DD2, ff2_W, DD, p_ff, DD, ff2_b, NN, DD2);
    addx_stats_k<<<MB, DD>>>(p_h, p_ff, 2);    // -> g_ff + BN2 stats
    finalize_k<<<1, DD>>>(2, bn2_g, bn2_b);
    bn2_apply_k<<<(NN * DD + 255) / 256, 256>>>(out);
}

// round 3
// speedup vs baseline: 2.1197x; 2.1197x over previous
#include <cuda_runtime.h>
#include <cstdint>

#define NN  50000
#define EE  800000
#define DD  512
#define KK  128
#define TJc 4
#define SSc 128
#define DD2 1024
#define EPSC 1e-5f

// ---------------- scratch (device globals; no allocations allowed) ----------
__device__ float g_xw  [(size_t)NN * DD];
__device__ float g_bufL[(size_t)NN * DD];
__device__ float g_ht  [(size_t)NN * DD];
__device__ float g_v   [(size_t)TJc * NN * SSc];
__device__ float g_comb[(size_t)NN * DD];
__device__ float g_bufA[(size_t)NN * DD];
__device__ float g_h   [(size_t)NN * DD];
__device__ float g_mid [(size_t)NN * DD2];
__device__ float g_ff  [(size_t)NN * DD];
__device__ float g_norm[EE];
__device__ float g_deg [NN];
__device__ float g_u   [TJc * KK * SSc];
__device__ float g_u2  [TJc * KK * SSc];
__device__ float g_stats[6 * DD];
__device__ float g_coef [6 * DD];
__device__ float g_linW2[DD * DD];
__device__ int   g_is64;

// ---------------- edge-index dtype detection --------------------------------
__global__ void detect_k(const int* __restrict__ ei32) {
    __shared__ int any;
    if (threadIdx.x == 0) any = 0;
    __syncthreads();
    int v = 0;
    for (int i = threadIdx.x; i < 1024; i += blockDim.x)
        v |= ei32[2 * i + 1];
    if (v) atomicOr(&any, 1);
    __syncthreads();
    if (threadIdx.x == 0) g_is64 = (any == 0) ? 1 : 0;
}

__device__ __forceinline__ int edge_at(const void* ei, long long pos) {
    return g_is64 ? (int)((const long long*)ei)[pos] : ((const int*)ei)[pos];
}

// ---------------- zero scratch ----------------------------------------------
__global__ void zero_scratch_k() {
    int stride = gridDim.x * blockDim.x;
    int i0 = blockIdx.x * blockDim.x + threadIdx.x;
    for (size_t i = i0; i < (size_t)NN * DD; i += stride) g_bufL[i] = 0.f;
    for (int i = i0; i < NN; i += stride) g_deg[i] = 0.f;
    for (int i = i0; i < TJc * KK * SSc; i += stride) { g_u[i] = 0.f; g_u2[i] = 0.f; }
    for (int i = i0; i < 6 * DD; i += stride) g_stats[i] = 0.f;
}

// ---------------- TF32 tensor-core GEMM --------------------------------------
__device__ __forceinline__ uint32_t f2tf32(float f) {
    uint32_t u; asm("cvt.rna.tf32.f32 %0, %1;" : "=r"(u) : "f"(f)); return u;
}
__device__ __forceinline__ void mma_tf32(float* c, const uint32_t* a, const uint32_t* b) {
    asm volatile("mma.sync.aligned.m16n8k8.row.col.f32.tf32.tf32.f32 "
        "{%0,%1,%2,%3}, {%4,%5,%6,%7}, {%8,%9}, {%0,%1,%2,%3};"
        : "+f"(c[0]), "+f"(c[1]), "+f"(c[2]), "+f"(c[3])
        : "r"(a[0]), "r"(a[1]), "r"(a[2]), "r"(a[3]), "r"(b[0]), "r"(b[1]));
}

// C[128 x 128-tile] = A[M,Kd] * B[Kd, ncols]; Kd % 32 == 0, cols exact grid.
template <bool BIAS, bool RELU>
__global__ void __launch_bounds__(256) tcgemm_k(
    const float* __restrict__ A, int lda,
    const float* __restrict__ B, int ldb,
    float* __restrict__ C, int ldc,
    const float* __restrict__ bias,
    int M, int Kd)
{
    __shared__ uint32_t As[128][36];   // [m][k], pad 4
    __shared__ uint32_t Bs[32][136];   // [k][n], pad 8
    const int m0 = blockIdx.y * 128;
    const int n0 = blockIdx.x * 128;
    const int tid = threadIdx.x;
    const int lane = tid & 31;
    const int wid = tid >> 5;
    const int g = lane >> 2, t = lane & 3;
    const int wm0 = (wid & 1) * 64;
    const int wn0 = (wid >> 1) * 32;

    float acc[4][4][4] = {};

    for (int k0 = 0; k0 < Kd; k0 += 32) {
        // load A tile: 128 x 32
        #pragma unroll
        for (int l = 0; l < 4; l++) {
            int idx = tid + l * 256;
            int r = idx >> 3, c = (idx & 7) * 4;
            float4 v = make_float4(0.f, 0.f, 0.f, 0.f);
            if (m0 + r < M)
                v = *reinterpret_cast<const float4*>(&A[(size_t)(m0 + r) * lda + k0 + c]);
            uint4 u = make_uint4(f2tf32(v.x), f2tf32(v.y), f2tf32(v.z), f2tf32(v.w));
            *reinterpret_cast<uint4*>(&As[r][c]) = u;
        }
        // load B tile: 32 x 128
        #pragma unroll
        for (int l = 0; l < 4; l++) {
            int idx = tid + l * 256;
            int r = idx >> 5, c = (idx & 31) * 4;
            float4 v = *reinterpret_cast<const float4*>(&B[(size_t)(k0 + r) * ldb + n0 + c]);
            uint4 u = make_uint4(f2tf32(v.x), f2tf32(v.y), f2tf32(v.z), f2tf32(v.w));
            *reinterpret_cast<uint4*>(&Bs[r][c]) = u;
        }
        __syncthreads();
        #pragma unroll
        for (int kk = 0; kk < 4; kk++) {
            uint32_t af[4][4], bf[4][2];
            #pragma unroll
            for (int mf = 0; mf < 4; mf++) {
                int mr = wm0 + mf * 16;
                af[mf][0] = As[mr + g     ][kk * 8 + t];
                af[mf][1] = As[mr + g + 8 ][kk * 8 + t];
                af[mf][2] = As[mr + g     ][kk * 8 + t + 4];
                af[mf][3] = As[mr + g + 8 ][kk * 8 + t + 4];
            }
            #pragma unroll
            for (int nf = 0; nf < 4; nf++) {
                bf[nf][0] = Bs[kk * 8 + t    ][wn0 + nf * 8 + g];
                bf[nf][1] = Bs[kk * 8 + t + 4][wn0 + nf * 8 + g];
            }
            #pragma unroll
            for (int mf = 0; mf < 4; mf++)
                #pragma unroll
                for (int nf = 0; nf < 4; nf++)
                    mma_tf32(acc[mf][nf], af[mf], bf[nf]);
        }
        __syncthreads();
    }

    // epilogue
    #pragma unroll
    for (int mf = 0; mf < 4; mf++) {
        int row0 = m0 + wm0 + mf * 16 + g;
        int row1 = row0 + 8;
        #pragma unroll
        for (int nf = 0; nf < 4; nf++) {
            int n = n0 + wn0 + nf * 8 + 2 * t;
            float b0 = 0.f, b1 = 0.f;
            if (BIAS) { b0 = bias[n]; b1 = bias[n + 1]; }
            float2 v0 = make_float2(acc[mf][nf][0] + b0, acc[mf][nf][1] + b1);
            float2 v1 = make_float2(acc[mf][nf][2] + b0, acc[mf][nf][3] + b1);
            if (RELU) {
                v0.x = fmaxf(v0.x, 0.f); v0.y = fmaxf(v0.y, 0.f);
                v1.x = fmaxf(v1.x, 0.f); v1.y = fmaxf(v1.y, 0.f);
            }
            if (row0 < M) *reinterpret_cast<float2*>(&C[(size_t)row0 * ldc + n]) = v0;
            if (row1 < M) *reinterpret_cast<float2*>(&C[(size_t)row1 * ldc + n]) = v1;
        }
    }
}

// ------------ tall reduction: C[128,128] += evc^T[128,N] * B[N,128] ---------
__global__ void __launch_bounds__(256) atb_k(
    const float* __restrict__ evc,
    const float* __restrict__ B, int ldb,
    float* __restrict__ C)
{
    __shared__ float Es[16][128];
    __shared__ float Hs[16][128];
    const int chunk = (NN + gridDim.x - 1) / gridDim.x;
    const int nStart = blockIdx.x * chunk;
    const int nEnd = min(nStart + chunk, NN);
    const int tid = threadIdx.x;
    const int ty = tid >> 4, tx = tid & 15;
    float acc[8][8] = {};

    for (int n0 = nStart; n0 < nEnd; n0 += 16) {
        #pragma unroll
        for (int l = 0; l < 2; l++) {
            int i = tid + l * 256;
            int r = i >> 5, c = (i & 31) * 4;
            int n = n0 + r;
            float4 ve = make_float4(0.f, 0.f, 0.f, 0.f);
            float4 vh = make_float4(0.f, 0.f, 0.f, 0.f);
            if (n < nEnd) {
                ve = *reinterpret_cast<const float4*>(&evc[(size_t)n * KK + c]);
                vh = *reinterpret_cast<const float4*>(&B[(size_t)n * ldb + c]);
            }
            *reinterpret_cast<float4*>(&Es[r][c]) = ve;
            *reinterpret_cast<float4*>(&Hs[r][c]) = vh;
        }
        __syncthreads();
        #pragma unroll
        for (int kk = 0; kk < 16; kk++) {
            float4 a0 = *reinterpret_cast<const float4*>(&Es[kk][ty * 8]);
            float4 a1 = *reinterpret_cast<const float4*>(&Es[kk][ty * 8 + 4]);
            float4 b0 = *reinterpret_cast<const float4*>(&Hs[kk][tx * 8]);
            float4 b1 = *reinterpret_cast<const float4*>(&Hs[kk][tx * 8 + 4]);
            float a[8] = {a0.x, a0.y, a0.z, a0.w, a1.x, a1.y, a1.z, a1.w};
            float b[8] = {b0.x, b0.y, b0.z, b0.w, b1.x, b1.y, b1.z, b1.w};
            #pragma unroll
            for (int i = 0; i < 8; i++)
                #pragma unroll
                for (int j = 0; j < 8; j++)
                    acc[i][j] = fmaf(a[i], b[j], acc[i][j]);
        }
        __syncthreads();
    }
    #pragma unroll
    for (int i = 0; i < 8; i++)
        #pragma unroll
        for (int j = 0; j < 8; j++)
            atomicAdd(&C[(ty * 8 + i) * 128 + tx * 8 + j], acc[i][j]);
}

// ---------------- graph kernels ---------------------------------------------
__global__ void deg_k(const void* __restrict__ ei) {
    int e = blockIdx.x * blockDim.x + threadIdx.x;
    if (e < EE) atomicAdd(&g_deg[edge_at(ei, (long long)EE + e)], 1.0f);
}
__global__ void dinv_k() {
    int n = blockIdx.x * blockDim.x + threadIdx.x;
    if (n < NN) g_deg[n] = rsqrtf(g_deg[n] + 1.0f);
}
__global__ void norm_k(const void* __restrict__ ei) {
    int e = blockIdx.x * blockDim.x + threadIdx.x;
    if (e < EE) g_norm[e] = g_deg[edge_at(ei, e)] * g_deg[edge_at(ei, (long long)EE + e)];
}
__global__ void scatter_k(const void* __restrict__ ei) {
    long long idx = (long long)blockIdx.x * blockDim.x + threadIdx.x;   // EE*128
    int e = (int)(idx >> 7);
    int c = ((int)idx & 127) * 4;
    int src = edge_at(ei, e);
    int dst = edge_at(ei, (long long)EE + e);
    float nrm = g_norm[e];
    float4 v = *reinterpret_cast<const float4*>(&g_xw[(size_t)src * DD + c]);
    float* o = &g_bufL[(size_t)dst * DD + c];
    asm volatile("red.global.add.v4.f32 [%0], {%1,%2,%3,%4};"
                 :: "l"(o), "f"(nrm * v.x), "f"(nrm * v.y),
                    "f"(nrm * v.z), "f"(nrm * v.w) : "memory");
}

// bufL = x + (agg + dinv^2*xw + gcn_b); accumulate BN0 stats
__global__ void finish_gcn_k(const float* __restrict__ x, const float* __restrict__ gcn_b) {
    const int c = threadIdx.x;
    const int r0 = blockIdx.x * 128;
    const int rEnd = min(r0 + 128, NN);
    const float bc = gcn_b[c];
    float s = 0.f, s2 = 0.f;
    for (int r = r0; r < rEnd; r++) {
        size_t o = (size_t)r * DD + c;
        float dv = g_deg[r];
        float v = x[o] + g_bufL[o] + dv * dv * g_xw[o] + bc;
        g_bufL[o] = v;
        s += v; s2 += v * v;
    }
    atomicAdd(&g_stats[0 * DD + c], s);
    atomicAdd(&g_stats[1 * DD + c], s2);
}

__global__ void addx_stats_k(const float* __restrict__ x, float* __restrict__ buf, int bn) {
    const int c = threadIdx.x;
    const int r0 = blockIdx.x * 128;
    const int rEnd = min(r0 + 128, NN);
    float s = 0.f, s2 = 0.f;
    for (int r = r0; r < rEnd; r++) {
        size_t o = (size_t)r * DD + c;
        float v = x[o] + buf[o];
        buf[o] = v;
        s += v; s2 += v * v;
    }
    atomicAdd(&g_stats[(bn * 2 + 0) * DD + c], s);
    atomicAdd(&g_stats[(bn * 2 + 1) * DD + c], s2);
}

__global__ void finalize_k(int bn, const float* __restrict__ gamma, const float* __restrict__ beta) {
    int c = threadIdx.x;
    float s  = g_stats[(bn * 2 + 0) * DD + c];
    float s2 = g_stats[(bn * 2 + 1) * DD + c];
    float m = s * (1.0f / NN);
    float var = s2 * (1.0f / NN) - m * m;
    float a = gamma[c] * rsqrtf(var + EPSC);
    g_coef[(bn * 2 + 0) * DD + c] = a;
    g_coef[(bn * 2 + 1) * DD + c] = beta[c] - m * a;
}

__global__ void apply_sum_k() {
    int idx = blockIdx.x * blockDim.x + threadIdx.x;
    if (idx >= NN * DD) return;
    int c = idx & (DD - 1);
    g_h[idx] = g_bufL[idx] * g_coef[c] + g_coef[DD + c]
             + g_bufA[idx] * g_coef[2 * DD + c] + g_coef[3 * DD + c];
}
__global__ void bn2_apply_k(float* __restrict__ out) {
    int idx = blockIdx.x * blockDim.x + threadIdx.x;
    if (idx >= NN * DD) return;
    int c = idx & (DD - 1);
    out[idx] = g_ff[idx] * g_coef[4 * DD + c] + g_coef[5 * DD + c];
}

// ---------------- wave helpers ----------------------------------------------
__global__ void pack_linw_k(const float* __restrict__ linW) {
    int idx = blockIdx.x * blockDim.x + threadIdx.x;
    if (idx >= DD * DD) return;
    int d = idx >> 9, j = idx & 511;
    int t = j >> 7, s = j & 127;
    g_linW2[idx] = linW[t * (DD * SSc) + d * SSc + s];
}
__global__ void scale_sig_k(float* __restrict__ u, const float* __restrict__ fs) {
    int idx = blockIdx.x * blockDim.x + threadIdx.x;
    if (idx >= TJc * KK * SSc) return;
    int t = idx >> 14;
    int k = (idx >> 7) & 127;
    u[idx] *= fs[k * TJc + t];
}

// ---------------- launch -----------------------------------------------------
#define GSYM(p, s) do { void* _t; cudaGetSymbolAddress(&_t, s); (p) = (float*)_t; } while (0)

extern "C" void kernel_launch(void* const* d_in, const int* in_sizes, int n_in,
                              void* d_out, int out_size) {
    const float* x        = (const float*)d_in[0];
    const void*  ei       = d_in[1];
    const float* evc      = (const float*)d_in[2];
    const float* fs       = (const float*)d_in[3];
    const float* gcn_W    = (const float*)d_in[4];
    const float* gcn_b    = (const float*)d_in[5];
    const float* lin_W    = (const float*)d_in[6];
    const float* lin_b    = (const float*)d_in[7];
    const float* fusion_W = (const float*)d_in[8];
    const float* fusion_b = (const float*)d_in[9];
    const float* bn1l_g   = (const float*)d_in[10];
    const float* bn1l_b   = (const float*)d_in[11];
    const float* bn1a_g   = (const float*)d_in[12];
    const float* bn1a_b   = (const float*)d_in[13];
    const float* bn2_g    = (const float*)d_in[14];
    const float* bn2_b    = (const float*)d_in[15];
    const float* ff1_W    = (const float*)d_in[16];
    const float* ff1_b    = (const float*)d_in[17];
    const float* ff2_W    = (const float*)d_in[18];
    const float* ff2_b    = (const float*)d_in[19];
    float* out = (float*)d_out;

    float *p_xw, *p_bufL, *p_ht, *p_v, *p_comb, *p_bufA, *p_h, *p_mid, *p_ff;
    float *p_u, *p_u2, *p_linW2;
    GSYM(p_xw, g_xw);   GSYM(p_bufL, g_bufL); GSYM(p_ht, g_ht);
    GSYM(p_v, g_v);     GSYM(p_comb, g_comb); GSYM(p_bufA, g_bufA);
    GSYM(p_h, g_h);     GSYM(p_mid, g_mid);   GSYM(p_ff, g_ff);
    GSYM(p_u, g_u);     GSYM(p_u2, g_u2);     GSYM(p_linW2, g_linW2);

    const int MB = (NN + 127) / 128;           // 391 row tiles
    dim3 gD(DD / 128, MB);
    dim3 gS(SSc / 128, MB);
    dim3 gF(DD2 / 128, MB);

    detect_k<<<1, 256>>>((const int*)ei);
    zero_scratch_k<<<2048, 256>>>();

    // ---- GCN branch ----
    tcgemm_k<false, false><<<gD, 256>>>(x, DD, gcn_W, DD, p_xw, DD, nullptr, NN, DD);
    deg_k<<<(EE + 255) / 256, 256>>>(ei);
    dinv_k<<<(NN + 255) / 256, 256>>>();
    norm_k<<<(EE + 255) / 256, 256>>>(ei);
    scatter_k<<<(EE * 128) / 256, 256>>>(ei);
    finish_gcn_k<<<MB, DD>>>(x, gcn_b);

    // ---- Wave branch ----
    pack_linw_k<<<(DD * DD + 255) / 256, 256>>>(lin_W);
    tcgemm_k<true, false><<<gD, 256>>>(x, DD, p_linW2, DD, p_ht, DD, lin_b, NN, DD);
    for (int t = 0; t < TJc; t++)
        atb_k<<<128, 256>>>(evc, p_ht + t * SSc, DD, p_u + t * KK * SSc);
    scale_sig_k<<<(TJc * KK * SSc + 255) / 256, 256>>>(p_u, fs);
    for (int t = 0; t < TJc; t++)
        tcgemm_k<false, true><<<gS, 256>>>(evc, KK, p_u + t * KK * SSc, SSc,
                                           p_v + (size_t)t * NN * SSc, SSc, nullptr, NN, KK);
    for (int t = 0; t < TJc; t++)
        atb_k<<<128, 256>>>(evc, p_v + (size_t)t * NN * SSc, SSc, p_u2 + t * KK * SSc);
    scale_sig_k<<<(TJc * KK * SSc + 255) / 256, 256>>>(p_u2, fs);
    for (int t = 0; t < TJc; t++)
        tcgemm_k<false, false><<<gS, 256>>>(evc, KK, p_u2 + t * KK * SSc, SSc,
                                            p_comb + t * SSc, DD, nullptr, NN, KK);
    tcgemm_k<true, true><<<gD, 256>>>(p_comb, DD, fusion_W, DD, p_bufA, DD, fusion_b, NN, DD);
    addx_stats_k<<<MB, DD>>>(x, p_bufA, 1);

    // ---- combine + BN ----
    finalize_k<<<1, DD>>>(0, bn1l_g, bn1l_b);
    finalize_k<<<1, DD>>>(1, bn1a_g, bn1a_b);
    apply_sum_k<<<(NN * DD + 255) / 256, 256>>>();

    // ---- feed-forward ----
    tcgemm_k<true, true><<<gF, 256>>>(p_h, DD, ff1_W, DD2, p_mid, DD2, ff1_b, NN, DD);
    tcgemm_k<true, false><<<gD, 256>>>(p_mid, DD2, ff2_W, DD, p_ff, DD, ff2_b, NN, DD2);
    addx_stats_k<<<MB, DD>>>(p_h, p_ff, 2);
    finalize_k<<<1, DD>>>(2, bn2_g, bn2_b);
    bn2_apply_k<<<(NN * DD + 255) / 256, 256>>>(out);
}

// round 4
// speedup vs baseline: 2.6944x; 1.2711x over previous
#include <cuda_runtime.h>
#include <cstdint>

#define NN  50000
#define EE  800000
#define DD  512
#define KK  128
#define TJc 4
#define SSc 128
#define DD2 1024
#define EPSC 1e-5f

// ---------------- scratch (device globals; no allocations allowed) ----------
__device__ float g_xwht[(size_t)NN * 1024];      // [x@gcn_W | x@lin_W+lin_b]
__device__ float g_bufL[(size_t)NN * DD];
__device__ float g_v   [(size_t)TJc * NN * SSc];
__device__ float g_comb[(size_t)NN * DD];
__device__ float g_bufA[(size_t)NN * DD];
__device__ float g_h   [(size_t)NN * DD];
__device__ float g_mid [(size_t)NN * DD2];
__device__ float g_ff  [(size_t)NN * DD];
__device__ float g_norm[EE];
__device__ float g_deg [NN];
__device__ float g_u   [TJc * KK * SSc];
__device__ float g_u2  [TJc * KK * SSc];
__device__ float g_stats[6 * DD];
__device__ float g_coef [6 * DD];
__device__ float g_bigW [DD * 1024];             // [gcn_W | packed lin_W]
__device__ float g_bigB [1024];
__device__ int   g_is64;

// ---------------- helpers -----------------------------------------------------
__device__ __forceinline__ uint32_t cvt_rna(uint32_t x) {
    uint32_t u; float f = __uint_as_float(x);
    asm("cvt.rna.tf32.f32 %0, %1;" : "=r"(u) : "f"(f)); return u;
}
__device__ __forceinline__ void mma_tf32(float* c, const uint32_t* a, const uint32_t* b) {
    asm volatile("mma.sync.aligned.m16n8k8.row.col.f32.tf32.tf32.f32 "
        "{%0,%1,%2,%3}, {%4,%5,%6,%7}, {%8,%9}, {%0,%1,%2,%3};"
        : "+f"(c[0]), "+f"(c[1]), "+f"(c[2]), "+f"(c[3])
        : "r"(a[0]), "r"(a[1]), "r"(a[2]), "r"(a[3]), "r"(b[0]), "r"(b[1]));
}
__device__ __forceinline__ void cp16(void* sdst, const void* gsrc, bool pred) {
    uint32_t sa = (uint32_t)__cvta_generic_to_shared(sdst);
    int sz = pred ? 16 : 0;
    asm volatile("cp.async.cg.shared.global [%0], [%1], 16, %2;"
                 :: "r"(sa), "l"(gsrc), "r"(sz));
}
#define CP_COMMIT() asm volatile("cp.async.commit_group;")
#define CP_WAIT(n)  asm volatile("cp.async.wait_group %0;" :: "n"(n))

// ---------------- edge-index dtype detection --------------------------------
__global__ void detect_k(const int* __restrict__ ei32) {
    __shared__ int any;
    if (threadIdx.x == 0) any = 0;
    __syncthreads();
    int v = 0;
    for (int i = threadIdx.x; i < 1024; i += blockDim.x)
        v |= ei32[2 * i + 1];
    if (v) atomicOr(&any, 1);
    __syncthreads();
    if (threadIdx.x == 0) g_is64 = (any == 0) ? 1 : 0;
}
__device__ __forceinline__ int edge_at(const void* ei, long long pos) {
    return g_is64 ? (int)((const long long*)ei)[pos] : ((const int*)ei)[pos];
}

// ---------------- zero scratch ----------------------------------------------
__global__ void zero_scratch_k() {
    int stride = gridDim.x * blockDim.x;
    int i0 = blockIdx.x * blockDim.x + threadIdx.x;
    for (size_t i = i0; i < (size_t)NN * DD; i += stride) g_bufL[i] = 0.f;
    for (int i = i0; i < NN; i += stride) g_deg[i] = 0.f;
    for (int i = i0; i < TJc * KK * SSc; i += stride) { g_u[i] = 0.f; g_u2[i] = 0.f; }
    for (int i = i0; i < 6 * DD; i += stride) g_stats[i] = 0.f;
}

// ---------------- pipelined TF32 GEMM ----------------------------------------
// C[128 x 128] tiles = A[M,Kd] * B[Kd, ncols]; Kd % 32 == 0, cols exact grid.
// blockIdx.z batches B/C by bTs/cTs elements.
template <bool BIAS, bool RELU>
__global__ void __launch_bounds__(256) tcgemm_k(
    const float* __restrict__ A, int lda,
    const float* __restrict__ B, int ldb, long long bTs,
    float* __restrict__ C, int ldc, long long cTs,
    const float* __restrict__ bias,
    int M, int Kd)
{
    extern __shared__ uint32_t dyn[];
    uint32_t (*As)[128][36]  = reinterpret_cast<uint32_t(*)[128][36]>(dyn);
    uint32_t (*Bs)[32][136]  = reinterpret_cast<uint32_t(*)[32][136]>(dyn + 2 * 128 * 36);

    B += (long long)blockIdx.z * bTs;
    C += (long long)blockIdx.z * cTs;

    const int m0 = blockIdx.y * 128;
    const int n0 = blockIdx.x * 128;
    const int tid = threadIdx.x;
    const int lane = tid & 31;
    const int wid = tid >> 5;
    const int g = lane >> 2, t = lane & 3;
    const int wm0 = (wid & 1) * 64;
    const int wn0 = (wid >> 1) * 32;

    float acc[4][4][4] = {};
    const int T = Kd >> 5;

    auto load_tiles = [&](int it, int s) {
        int k0 = it * 32;
        #pragma unroll
        for (int l = 0; l < 4; l++) {
            int idx = tid + l * 256;
            int r = idx >> 3, c = (idx & 7) * 4;
            bool p = (m0 + r < M);
            int row = p ? (m0 + r) : 0;
            cp16(&As[s][r][c], &A[(size_t)row * lda + k0 + c], p);
        }
        #pragma unroll
        for (int l = 0; l < 4; l++) {
            int idx = tid + l * 256;
            int r = idx >> 5, c = (idx & 31) * 4;
            cp16(&Bs[s][r][c], &B[(size_t)(k0 + r) * ldb + n0 + c], true);
        }
    };

    load_tiles(0, 0);
    CP_COMMIT();

    for (int i = 0; i < T; i++) {
        int cur = i & 1;
        if (i + 1 < T) { load_tiles(i + 1, cur ^ 1); CP_COMMIT(); CP_WAIT(1); }
        else          { CP_WAIT(0); }
        __syncthreads();
        #pragma unroll
        for (int kk = 0; kk < 4; kk++) {
            uint32_t af[4][4], bf[4][2];
            #pragma unroll
            for (int mf = 0; mf < 4; mf++) {
                int mr = wm0 + mf * 16;
                af[mf][0] = cvt_rna(As[cur][mr + g    ][kk * 8 + t]);
                af[mf][1] = cvt_rna(As[cur][mr + g + 8][kk * 8 + t]);
                af[mf][2] = cvt_rna(As[cur][mr + g    ][kk * 8 + t + 4]);
                af[mf][3] = cvt_rna(As[cur][mr + g + 8][kk * 8 + t + 4]);
            }
            #pragma unroll
            for (int nf = 0; nf < 4; nf++) {
                bf[nf][0] = cvt_rna(Bs[cur][kk * 8 + t    ][wn0 + nf * 8 + g]);
                bf[nf][1] = cvt_rna(Bs[cur][kk * 8 + t + 4][wn0 + nf * 8 + g]);
            }
            #pragma unroll
            for (int mf = 0; mf < 4; mf++)
                #pragma unroll
                for (int nf = 0; nf < 4; nf++)
                    mma_tf32(acc[mf][nf], af[mf], bf[nf]);
        }
        __syncthreads();
    }

    #pragma unroll
    for (int mf = 0; mf < 4; mf++) {
        int row0 = m0 + wm0 + mf * 16 + g;
        int row1 = row0 + 8;
        #pragma unroll
        for (int nf = 0; nf < 4; nf++) {
            int n = n0 + wn0 + nf * 8 + 2 * t;
            float b0 = 0.f, b1 = 0.f;
            if (BIAS) { b0 = bias[n]; b1 = bias[n + 1]; }
            float2 v0 = make_float2(acc[mf][nf][0] + b0, acc[mf][nf][1] + b1);
            float2 v1 = make_float2(acc[mf][nf][2] + b0, acc[mf][nf][3] + b1);
            if (RELU) {
                v0.x = fmaxf(v0.x, 0.f); v0.y = fmaxf(v0.y, 0.f);
                v1.x = fmaxf(v1.x, 0.f); v1.y = fmaxf(v1.y, 0.f);
            }
            if (row0 < M) *reinterpret_cast<float2*>(&C[(size_t)row0 * ldc + n]) = v0;
            if (row1 < M) *reinterpret_cast<float2*>(&C[(size_t)row1 * ldc + n]) = v1;
        }
    }
}

// ------- tensor-core tall reduction: C[128,128] += evc^T[128,N]*B[N,128] ----
#define ATB_BLKS 64
__global__ void __launch_bounds__(256) atb_k(
    const float* __restrict__ evc,
    const float* __restrict__ B, int ldb, long long bTs,
    float* __restrict__ C)
{
    extern __shared__ uint32_t dyn[];
    uint32_t (*Es)[32][136] = reinterpret_cast<uint32_t(*)[32][136]>(dyn);
    uint32_t (*Hs)[32][136] = reinterpret_cast<uint32_t(*)[32][136]>(dyn + 2 * 32 * 136);

    B += (long long)blockIdx.z * bTs;
    C += (long long)blockIdx.z * (KK * SSc);

    const int chunk = (NN + ATB_BLKS - 1) / ATB_BLKS;      // 782
    const int nStart = blockIdx.x * chunk;
    const int nEnd = min(nStart + chunk, NN);
    const int iters = (chunk + 31) / 32;                   // 25
    const int tid = threadIdx.x;
    const int lane = tid & 31;
    const int wid = tid >> 5;
    const int g = lane >> 2, t = lane & 3;
    const int wm0 = (wid & 1) * 64;
    const int wn0 = (wid >> 1) * 32;

    float acc[4][4][4] = {};

    auto load_tiles = [&](int it, int s) {
        int n0 = nStart + it * 32;
        #pragma unroll
        for (int l = 0; l < 4; l++) {
            int idx = tid + l * 256;
            int r = idx >> 5, c = (idx & 31) * 4;
            bool p = (n0 + r < nEnd);
            int row = p ? (n0 + r) : 0;
            cp16(&Es[s][r][c], &evc[(size_t)row * KK + c], p);
            cp16(&Hs[s][r][c], &B[(size_t)row * ldb + c], p);
        }
    };

    load_tiles(0, 0);
    CP_COMMIT();

    for (int i = 0; i < iters; i++) {
        int cur = i & 1;
        if (i + 1 < iters) { load_tiles(i + 1, cur ^ 1); CP_COMMIT(); CP_WAIT(1); }
        else              { CP_WAIT(0); }
        __syncthreads();
        #pragma unroll
        for (int kk = 0; kk < 4; kk++) {
            uint32_t af[4][4], bf[4][2];
            #pragma unroll
            for (int mf = 0; mf < 4; mf++) {
                int mc = wm0 + mf * 16;
                af[mf][0] = cvt_rna(Es[cur][kk * 8 + t    ][mc + g]);
                af[mf][1] = cvt_rna(Es[cur][kk * 8 + t    ][mc + g + 8]);
                af[mf][2] = cvt_rna(Es[cur][kk * 8 + t + 4][mc + g]);
                af[mf][3] = cvt_rna(Es[cur][kk * 8 + t + 4][mc + g + 8]);
            }
            #pragma unroll
            for (int nf = 0; nf < 4; nf++) {
                bf[nf][0] = cvt_rna(Hs[cur][kk * 8 + t    ][wn0 + nf * 8 + g]);
                bf[nf][1] = cvt_rna(Hs[cur][kk * 8 + t + 4][wn0 + nf * 8 + g]);
            }
            #pragma unroll
            for (int mf = 0; mf < 4; mf++)
                #pragma unroll
                for (int nf = 0; nf < 4; nf++)
                    mma_tf32(acc[mf][nf], af[mf], bf[nf]);
        }
        __syncthreads();
    }

    #pragma unroll
    for (int mf = 0; mf < 4; mf++) {
        int row0 = wm0 + mf * 16 + g;
        #pragma unroll
        for (int nf = 0; nf < 4; nf++) {
            int n = wn0 + nf * 8 + 2 * t;
            float* p0 = &C[(size_t)row0 * SSc + n];
            float* p1 = &C[(size_t)(row0 + 8) * SSc + n];
            asm volatile("red.global.add.v2.f32 [%0], {%1,%2};"
                         :: "l"(p0), "f"(acc[mf][nf][0]), "f"(acc[mf][nf][1]) : "memory");
            asm volatile("red.global.add.v2.f32 [%0], {%1,%2};"
                         :: "l"(p1), "f"(acc[mf][nf][2]), "f"(acc[mf][nf][3]) : "memory");
        }
    }
}

// ---------------- graph kernels ---------------------------------------------
__global__ void deg_k(const void* __restrict__ ei) {
    int e = blockIdx.x * blockDim.x + threadIdx.x;
    if (e < EE) atomicAdd(&g_deg[edge_at(ei, (long long)EE + e)], 1.0f);
}
__global__ void dinv_k() {
    int n = blockIdx.x * blockDim.x + threadIdx.x;
    if (n < NN) g_deg[n] = rsqrtf(g_deg[n] + 1.0f);
}
__global__ void norm_k(const void* __restrict__ ei) {
    int e = blockIdx.x * blockDim.x + threadIdx.x;
    if (e < EE) g_norm[e] = g_deg[edge_at(ei, e)] * g_deg[edge_at(ei, (long long)EE + e)];
}
__global__ void scatter_k(const void* __restrict__ ei) {
    long long idx = (long long)blockIdx.x * blockDim.x + threadIdx.x;   // EE*128
    int e = (int)(idx >> 7);
    int c = ((int)idx & 127) * 4;
    int src = edge_at(ei, e);
    int dst = edge_at(ei, (long long)EE + e);
    float nrm = g_norm[e];
    float4 v = *reinterpret_cast<const float4*>(&g_xwht[(size_t)src * 1024 + c]);
    float* o = &g_bufL[(size_t)dst * DD + c];
    asm volatile("red.global.add.v4.f32 [%0], {%1,%2,%3,%4};"
                 :: "l"(o), "f"(nrm * v.x), "f"(nrm * v.y),
                    "f"(nrm * v.z), "f"(nrm * v.w) : "memory");
}

// bufL = x + (agg + dinv^2*xw + gcn_b); accumulate BN0 stats
__global__ void finish_gcn_k(const float* __restrict__ x, const float* __restrict__ gcn_b) {
    const int c = threadIdx.x;
    const int r0 = blockIdx.x * 128;
    const int rEnd = min(r0 + 128, NN);
    const float bc = gcn_b[c];
    float s = 0.f, s2 = 0.f;
    for (int r = r0; r < rEnd; r++) {
        size_t o = (size_t)r * DD + c;
        float dv = g_deg[r];
        float v = x[o] + g_bufL[o] + dv * dv * g_xwht[(size_t)r * 1024 + c] + bc;
        g_bufL[o] = v;
        s += v; s2 += v * v;
    }
    atomicAdd(&g_stats[0 * DD + c], s);
    atomicAdd(&g_stats[1 * DD + c], s2);
}

__global__ void addx_stats_k(const float* __restrict__ x, float* __restrict__ buf, int bn) {
    const int c = threadIdx.x;
    const int r0 = blockIdx.x * 128;
    const int rEnd = min(r0 + 128, NN);
    float s = 0.f, s2 = 0.f;
    for (int r = r0; r < rEnd; r++) {
        size_t o = (size_t)r * DD + c;
        float v = x[o] + buf[o];
        buf[o] = v;
        s += v; s2 += v * v;
    }
    atomicAdd(&g_stats[(bn * 2 + 0) * DD + c], s);
    atomicAdd(&g_stats[(bn * 2 + 1) * DD + c], s2);
}

__global__ void finalize_k(int bn, const float* __restrict__ gamma, const float* __restrict__ beta) {
    int c = threadIdx.x;
    float s  = g_stats[(bn * 2 + 0) * DD + c];
    float s2 = g_stats[(bn * 2 + 1) * DD + c];
    float m = s * (1.0f / NN);
    float var = s2 * (1.0f / NN) - m * m;
    float a = gamma[c] * rsqrtf(var + EPSC);
    g_coef[(bn * 2 + 0) * DD + c] = a;
    g_coef[(bn * 2 + 1) * DD + c] = beta[c] - m * a;
}

__global__ void apply_sum_k() {
    int idx = blockIdx.x * blockDim.x + threadIdx.x;
    if (idx >= NN * DD) return;
    int c = idx & (DD - 1);
    g_h[idx] = g_bufL[idx] * g_coef[c] + g_coef[DD + c]
             + g_bufA[idx] * g_coef[2 * DD + c] + g_coef[3 * DD + c];
}
__global__ void bn2_apply_k(float* __restrict__ out) {
    int idx = blockIdx.x * blockDim.x + threadIdx.x;
    if (idx >= NN * DD) return;
    int c = idx & (DD - 1);
    out[idx] = g_ff[idx] * g_coef[4 * DD + c] + g_coef[5 * DD + c];
}

// ---------------- wave helpers ----------------------------------------------
__global__ void pack_w_k(const float* __restrict__ gcnW,
                         const float* __restrict__ linW,
                         const float* __restrict__ linB) {
    int idx = blockIdx.x * blockDim.x + threadIdx.x;   // DD*1024
    if (idx >= DD * 1024) return;
    int d = idx >> 10, j = idx & 1023;
    float v;
    if (j < 512) v = gcnW[d * DD + j];
    else {
        int t = (j - 512) >> 7, s = (j - 512) & 127;
        v = linW[t * (DD * SSc) + d * SSc + s];
    }
    g_bigW[idx] = v;
    if (idx < 1024) {
        float b = 0.f;
        if (idx >= 512) { int t = (idx - 512) >> 7, s = (idx - 512) & 127; b = linB[t * SSc + s]; }
        g_bigB[idx] = b;
    }
}
__global__ void scale_sig_k(float* __restrict__ u, const float* __restrict__ fs) {
    int idx = blockIdx.x * blockDim.x + threadIdx.x;
    if (idx >= TJc * KK * SSc) return;
    int t = idx >> 14;
    int k = (idx >> 7) & 127;
    u[idx] *= fs[k * TJc + t];
}

// ---------------- launch -----------------------------------------------------
#define GSYM(p, s) do { void* _t; cudaGetSymbolAddress(&_t, s); (p) = (float*)_t; } while (0)

extern "C" void kernel_launch(void* const* d_in, const int* in_sizes, int n_in,
                              void* d_out, int out_size) {
    const float* x        = (const float*)d_in[0];
    const void*  ei       = d_in[1];
    const float* evc      = (const float*)d_in[2];
    const float* fs       = (const float*)d_in[3];
    const float* gcn_W    = (const float*)d_in[4];
    const float* gcn_b    = (const float*)d_in[5];
    const float* lin_W    = (const float*)d_in[6];
    const float* lin_b    = (const float*)d_in[7];
    const float* fusion_W = (const float*)d_in[8];
    const float* fusion_b = (const float*)d_in[9];
    const float* bn1l_g   = (const float*)d_in[10];
    const float* bn1l_b   = (const float*)d_in[11];
    const float* bn1a_g   = (const float*)d_in[12];
    const float* bn1a_b   = (const float*)d_in[13];
    const float* bn2_g    = (const float*)d_in[14];
    const float* bn2_b    = (const float*)d_in[15];
    const float* ff1_W    = (const float*)d_in[16];
    const float* ff1_b    = (const float*)d_in[17];
    const float* ff2_W    = (const float*)d_in[18];
    const float* ff2_b    = (const float*)d_in[19];
    float* out = (float*)d_out;

    float *p_xwht, *p_bufL, *p_v, *p_comb, *p_bufA, *p_h, *p_mid, *p_ff;
    float *p_u, *p_u2, *p_bigW, *p_bigB;
    GSYM(p_xwht, g_xwht); GSYM(p_bufL, g_bufL); GSYM(p_v, g_v);
    GSYM(p_comb, g_comb); GSYM(p_bufA, g_bufA); GSYM(p_h, g_h);
    GSYM(p_mid, g_mid);   GSYM(p_ff, g_ff);     GSYM(p_u, g_u);
    GSYM(p_u2, g_u2);     GSYM(p_bigW, g_bigW); GSYM(p_bigB, g_bigB);

    const int GEMM_SMEM = (2 * 128 * 36 + 2 * 32 * 136) * 4;   // 71680
    const int ATB_SMEM  = (2 * 32 * 136 * 2) * 4;              // 69632
    cudaFuncSetAttribute(tcgemm_k<true,  false>, cudaFuncAttributeMaxDynamicSharedMemorySize, GEMM_SMEM);
    cudaFuncSetAttribute(tcgemm_k<true,  true >, cudaFuncAttributeMaxDynamicSharedMemorySize, GEMM_SMEM);
    cudaFuncSetAttribute(tcgemm_k<false, true >, cudaFuncAttributeMaxDynamicSharedMemorySize, GEMM_SMEM);
    cudaFuncSetAttribute(tcgemm_k<false, false>, cudaFuncAttributeMaxDynamicSharedMemorySize, GEMM_SMEM);
    cudaFuncSetAttribute(atb_k, cudaFuncAttributeMaxDynamicSharedMemorySize, ATB_SMEM);

    const int MB = (NN + 127) / 128;           // 391
    dim3 gBig(1024 / 128, MB);
    dim3 gD(DD / 128, MB);
    dim3 gF(DD2 / 128, MB);
    dim3 gFwd(1, MB, TJc);
    dim3 gAtb(ATB_BLKS, 1, TJc);

    detect_k<<<1, 256>>>((const int*)ei);
    zero_scratch_k<<<2048, 256>>>();
    pack_w_k<<<(DD * 1024 + 255) / 256, 256>>>(gcn_W, lin_W, lin_b);

    // ---- fused first GEMM: [xw | ht] = x @ [gcn_W | lin_W] ----
    tcgemm_k<true, false><<<gBig, 256, GEMM_SMEM>>>(
        x, DD, p_bigW, 1024, 0, p_xwht, 1024, 0, p_bigB, NN, DD);

    // ---- GCN branch ----
    deg_k<<<(EE + 255) / 256, 256>>>(ei);
    dinv_k<<<(NN + 255) / 256, 256>>>();
    norm_k<<<(EE + 255) / 256, 256>>>(ei);
    scatter_k<<<(EE * 128) / 256, 256>>>(ei);
    finish_gcn_k<<<MB, DD>>>(x, gcn_b);

    // ---- Wave branch (z-batched over t) ----
    atb_k<<<gAtb, 256, ATB_SMEM>>>(evc, p_xwht + 512, 1024, 128, p_u);
    scale_sig_k<<<(TJc * KK * SSc + 255) / 256, 256>>>(p_u, fs);
    tcgemm_k<false, true><<<gFwd, 256, GEMM_SMEM>>>(
        evc, KK, p_u, SSc, KK * SSc, p_v, SSc, (long long)NN * SSc, nullptr, NN, KK);
    atb_k<<<gAtb, 256, ATB_SMEM>>>(evc, p_v, SSc, (long long)NN * SSc, p_u2);
    scale_sig_k<<<(TJc * KK * SSc + 255) / 256, 256>>>(p_u2, fs);
    tcgemm_k<false, false><<<gFwd, 256, GEMM_SMEM>>>(
        evc, KK, p_u2, SSc, KK * SSc, p_comb, DD, SSc, nullptr, NN, KK);
    tcgemm_k<true, true><<<gD, 256, GEMM_SMEM>>>(
        p_comb, DD, fusion_W, DD, 0, p_bufA, DD, 0, fusion_b, NN, DD);
    addx_stats_k<<<MB, DD>>>(x, p_bufA, 1);

    // ---- combine + BN ----
    finalize_k<<<1, DD>>>(0, bn1l_g, bn1l_b);
    finalize_k<<<1, DD>>>(1, bn1a_g, bn1a_b);
    apply_sum_k<<<(NN * DD + 255) / 256, 256>>>();

    // ---- feed-forward ----
    tcgemm_k<true, true><<<gF, 256, GEMM_SMEM>>>(
        p_h, DD, ff1_W, DD2, 0, p_mid, DD2, 0, ff1_b, NN, DD);
    tcgemm_k<true, false><<<gD, 256, GEMM_SMEM>>>(
        p_mid, DD2, ff2_W, DD, 0, p_ff, DD, 0, ff2_b, NN, DD2);
    addx_stats_k<<<MB, DD>>>(p_h, p_ff, 2);
    finalize_k<<<1, DD>>>(2, bn2_g, bn2_b);
    bn2_apply_k<<<(NN * DD + 255) / 256, 256>>>(out);
}

// round 5
// speedup vs baseline: 2.9412x; 1.0916x over previous
#include <cuda_runtime.h>
#include <cstdint>

#define NN  50000
#define EE  800000
#define DD  512
#define KK  128
#define TJc 4
#define SSc 128
#define DD2 1024
#define EPSC 1e-5f

// ---------------- scratch (device globals; no allocations allowed) ----------
__device__ float g_xwht[(size_t)NN * 1024];      // [x@gcn_W | x@lin_W+lin_b]
__device__ float g_bufL[(size_t)NN * DD];
__device__ float g_v   [(size_t)TJc * NN * SSc];
__device__ float g_comb[(size_t)NN * DD];        // tf32-rounded (GEMM-only consumer)
__device__ float g_bufA[(size_t)NN * DD];
__device__ float g_h   [(size_t)NN * DD];
__device__ float g_h32 [(size_t)NN * DD];        // tf32 copy of h for ff1
__device__ float g_mid [(size_t)NN * DD2];       // tf32-rounded (GEMM-only consumer)
__device__ float g_ff  [(size_t)NN * DD];
__device__ float g_xt  [(size_t)NN * DD];        // tf32 copy of x
__device__ float g_evct[(size_t)NN * KK];        // tf32 copy of evc
__device__ float g_norm[EE];
__device__ float g_deg [NN];
__device__ float g_u   [TJc * KK * SSc];
__device__ float g_u2  [TJc * KK * SSc];
__device__ float g_stats[6 * DD];
__device__ float g_coef [6 * DD];
__device__ float g_bigW [DD * 1024];             // tf32 [gcn_W | packed lin_W]
__device__ float g_bigB [1024];
__device__ float g_fWt  [DD * DD];               // tf32 fusion_W
__device__ float g_f1Wt [DD * DD2];              // tf32 ff1_W
__device__ float g_f2Wt [DD2 * DD];              // tf32 ff2_W
__device__ int   g_is64;

// ---------------- helpers -----------------------------------------------------
__device__ __forceinline__ float tf32r(float f) {
    uint32_t u; asm("cvt.rna.tf32.f32 %0, %1;" : "=r"(u) : "f"(f));
    return __uint_as_float(u);
}
__device__ __forceinline__ uint32_t cvt_rna(uint32_t x) {
    uint32_t u; float f = __uint_as_float(x);
    asm("cvt.rna.tf32.f32 %0, %1;" : "=r"(u) : "f"(f)); return u;
}
__device__ __forceinline__ void mma_tf32(float* c, const uint32_t* a, const uint32_t* b) {
    asm volatile("mma.sync.aligned.m16n8k8.row.col.f32.tf32.tf32.f32 "
        "{%0,%1,%2,%3}, {%4,%5,%6,%7}, {%8,%9}, {%0,%1,%2,%3};"
        : "+f"(c[0]), "+f"(c[1]), "+f"(c[2]), "+f"(c[3])
        : "r"(a[0]), "r"(a[1]), "r"(a[2]), "r"(a[3]), "r"(b[0]), "r"(b[1]));
}
__device__ __forceinline__ void cp16(void* sdst, const void* gsrc, bool pred) {
    uint32_t sa = (uint32_t)__cvta_generic_to_shared(sdst);
    int sz = pred ? 16 : 0;
    asm volatile("cp.async.cg.shared.global [%0], [%1], 16, %2;"
                 :: "r"(sa), "l"(gsrc), "r"(sz));
}
#define CP_COMMIT() asm volatile("cp.async.commit_group;")
#define CP_WAIT(n)  asm volatile("cp.async.wait_group %0;" :: "n"(n))

// ---------------- edge-index dtype detection --------------------------------
__global__ void detect_k(const int* __restrict__ ei32) {
    __shared__ int any;
    if (threadIdx.x == 0) any = 0;
    __syncthreads();
    int v = 0;
    for (int i = threadIdx.x; i < 1024; i += blockDim.x)
        v |= ei32[2 * i + 1];
    if (v) atomicOr(&any, 1);
    __syncthreads();
    if (threadIdx.x == 0) g_is64 = (any == 0) ? 1 : 0;
}
__device__ __forceinline__ int edge_at(const void* ei, long long pos) {
    return g_is64 ? (int)((const long long*)ei)[pos] : ((const int*)ei)[pos];
}

// ---------------- zero / round helpers ---------------------------------------
__global__ void zero_scratch_k() {
    int stride = gridDim.x * blockDim.x;
    int i0 = blockIdx.x * blockDim.x + threadIdx.x;
    for (size_t i = i0; i < (size_t)NN * DD; i += stride) g_bufL[i] = 0.f;
    for (int i = i0; i < NN; i += stride) g_deg[i] = 0.f;
    for (int i = i0; i < TJc * KK * SSc; i += stride) { g_u[i] = 0.f; g_u2[i] = 0.f; }
    for (int i = i0; i < 6 * DD; i += stride) g_stats[i] = 0.f;
}
__global__ void round_k(const float* __restrict__ in, float* __restrict__ o, long long n) {
    long long i = (long long)blockIdx.x * blockDim.x + threadIdx.x;
    long long stride = (long long)gridDim.x * blockDim.x;
    for (; i < n / 4; i += stride) {
        float4 v = reinterpret_cast<const float4*>(in)[i];
        v.x = tf32r(v.x); v.y = tf32r(v.y); v.z = tf32r(v.z); v.w = tf32r(v.w);
        reinterpret_cast<float4*>(o)[i] = v;
    }
}

// ---------------- pipelined TF32 GEMM (operands pre-rounded) -----------------
template <bool BIAS, bool RELU, bool RND>
__global__ void __launch_bounds__(256, 2) tcgemm_k(
    const float* __restrict__ A, int lda,
    const float* __restrict__ B, int ldb, long long bTs,
    float* __restrict__ C, int ldc, long long cTs,
    const float* __restrict__ bias,
    int M, int Kd)
{
    extern __shared__ uint32_t dyn[];
    uint32_t (*As)[128][36]  = reinterpret_cast<uint32_t(*)[128][36]>(dyn);
    uint32_t (*Bs)[32][136]  = reinterpret_cast<uint32_t(*)[32][136]>(dyn + 2 * 128 * 36);

    B += (long long)blockIdx.z * bTs;
    C += (long long)blockIdx.z * cTs;

    const int m0 = blockIdx.y * 128;
    const int n0 = blockIdx.x * 128;
    const int tid = threadIdx.x;
    const int lane = tid & 31;
    const int wid = tid >> 5;
    const int g = lane >> 2, t = lane & 3;
    const int wm0 = (wid & 1) * 64;
    const int wn0 = (wid >> 1) * 32;

    float acc[4][4][4] = {};
    const int T = Kd >> 5;

    auto load_tiles = [&](int it, int s) {
        int k0 = it * 32;
        #pragma unroll
        for (int l = 0; l < 4; l++) {
            int idx = tid + l * 256;
            int r = idx >> 3, c = (idx & 7) * 4;
            bool p = (m0 + r < M);
            int row = p ? (m0 + r) : 0;
            cp16(&As[s][r][c], &A[(size_t)row * lda + k0 + c], p);
        }
        #pragma unroll
        for (int l = 0; l < 4; l++) {
            int idx = tid + l * 256;
            int r = idx >> 5, c = (idx & 31) * 4;
            cp16(&Bs[s][r][c], &B[(size_t)(k0 + r) * ldb + n0 + c], true);
        }
    };

    load_tiles(0, 0);
    CP_COMMIT();

    for (int i = 0; i < T; i++) {
        int cur = i & 1;
        if (i + 1 < T) { load_tiles(i + 1, cur ^ 1); CP_COMMIT(); CP_WAIT(1); }
        else          { CP_WAIT(0); }
        __syncthreads();
        #pragma unroll
        for (int kk = 0; kk < 4; kk++) {
            uint32_t af[4][4], bf[4][2];
            #pragma unroll
            for (int mf = 0; mf < 4; mf++) {
                int mr = wm0 + mf * 16;
                af[mf][0] = As[cur][mr + g    ][kk * 8 + t];
                af[mf][1] = As[cur][mr + g + 8][kk * 8 + t];
                af[mf][2] = As[cur][mr + g    ][kk * 8 + t + 4];
                af[mf][3] = As[cur][mr + g + 8][kk * 8 + t + 4];
            }
            #pragma unroll
            for (int nf = 0; nf < 4; nf++) {
                bf[nf][0] = Bs[cur][kk * 8 + t    ][wn0 + nf * 8 + g];
                bf[nf][1] = Bs[cur][kk * 8 + t + 4][wn0 + nf * 8 + g];
            }
            #pragma unroll
            for (int mf = 0; mf < 4; mf++)
                #pragma unroll
                for (int nf = 0; nf < 4; nf++)
                    mma_tf32(acc[mf][nf], af[mf], bf[nf]);
        }
        __syncthreads();
    }

    #pragma unroll
    for (int mf = 0; mf < 4; mf++) {
        int row0 = m0 + wm0 + mf * 16 + g;
        int row1 = row0 + 8;
        #pragma unroll
        for (int nf = 0; nf < 4; nf++) {
            int n = n0 + wn0 + nf * 8 + 2 * t;
            float b0 = 0.f, b1 = 0.f;
            if (BIAS) { b0 = bias[n]; b1 = bias[n + 1]; }
            float2 v0 = make_float2(acc[mf][nf][0] + b0, acc[mf][nf][1] + b1);
            float2 v1 = make_float2(acc[mf][nf][2] + b0, acc[mf][nf][3] + b1);
            if (RELU) {
                v0.x = fmaxf(v0.x, 0.f); v0.y = fmaxf(v0.y, 0.f);
                v1.x = fmaxf(v1.x, 0.f); v1.y = fmaxf(v1.y, 0.f);
            }
            if (RND) {
                v0.x = tf32r(v0.x); v0.y = tf32r(v0.y);
                v1.x = tf32r(v1.x); v1.y = tf32r(v1.y);
            }
            if (row0 < M) *reinterpret_cast<float2*>(&C[(size_t)row0 * ldc + n]) = v0;
            if (row1 < M) *reinterpret_cast<float2*>(&C[(size_t)row1 * ldc + n]) = v1;
        }
    }
}

// ------- tensor-core tall reduction: C[128,128] += evc^T[128,N]*B[N,128] ----
// A (evc) pre-rounded; B converted on fragment read.
#define ATB_BLKS 64
__global__ void __launch_bounds__(256, 2) atb_k(
    const float* __restrict__ evc,
    const float* __restrict__ B, int ldb, long long bTs,
    float* __restrict__ C)
{
    extern __shared__ uint32_t dyn[];
    uint32_t (*Es)[32][136] = reinterpret_cast<uint32_t(*)[32][136]>(dyn);
    uint32_t (*Hs)[32][136] = reinterpret_cast<uint32_t(*)[32][136]>(dyn + 2 * 32 * 136);

    B += (long long)blockIdx.z * bTs;
    C += (long long)blockIdx.z * (KK * SSc);

    const int chunk = (NN + ATB_BLKS - 1) / ATB_BLKS;
    const int nStart = blockIdx.x * chunk;
    const int nEnd = min(nStart + chunk, NN);
    const int iters = (chunk + 31) / 32;
    const int tid = threadIdx.x;
    const int lane = tid & 31;
    const int wid = tid >> 5;
    const int g = lane >> 2, t = lane & 3;
    const int wm0 = (wid & 1) * 64;
    const int wn0 = (wid >> 1) * 32;

    float acc[4][4][4] = {};

    auto load_tiles = [&](int it, int s) {
        int n0 = nStart + it * 32;
        #pragma unroll
        for (int l = 0; l < 4; l++) {
            int idx = tid + l * 256;
            int r = idx >> 5, c = (idx & 31) * 4;
            bool p = (n0 + r < nEnd);
            int row = p ? (n0 + r) : 0;
            cp16(&Es[s][r][c], &evc[(size_t)row * KK + c], p);
            cp16(&Hs[s][r][c], &B[(size_t)row * ldb + c], p);
        }
    };

    load_tiles(0, 0);
    CP_COMMIT();

    for (int i = 0; i < iters; i++) {
        int cur = i & 1;
        if (i + 1 < iters) { load_tiles(i + 1, cur ^ 1); CP_COMMIT(); CP_WAIT(1); }
        else              { CP_WAIT(0); }
        __syncthreads();
        #pragma unroll
        for (int kk = 0; kk < 4; kk++) {
            uint32_t af[4][4], bf[4][2];
            #pragma unroll
            for (int mf = 0; mf < 4; mf++) {
                int mc = wm0 + mf * 16;
                af[mf][0] = Es[cur][kk * 8 + t    ][mc + g];
                af[mf][1] = Es[cur][kk * 8 + t    ][mc + g + 8];
                af[mf][2] = Es[cur][kk * 8 + t + 4][mc + g];
                af[mf][3] = Es[cur][kk * 8 + t + 4][mc + g + 8];
            }
            #pragma unroll
            for (int nf = 0; nf < 4; nf++) {
                bf[nf][0] = cvt_rna(Hs[cur][kk * 8 + t    ][wn0 + nf * 8 + g]);
                bf[nf][1] = cvt_rna(Hs[cur][kk * 8 + t + 4][wn0 + nf * 8 + g]);
            }
            #pragma unroll
            for (int mf = 0; mf < 4; mf++)
                #pragma unroll
                for (int nf = 0; nf < 4; nf++)
                    mma_tf32(acc[mf][nf], af[mf], bf[nf]);
        }
        __syncthreads();
    }

    #pragma unroll
    for (int mf = 0; mf < 4; mf++) {
        int row0 = wm0 + mf * 16 + g;
        #pragma unroll
        for (int nf = 0; nf < 4; nf++) {
            int n = wn0 + nf * 8 + 2 * t;
            float* p0 = &C[(size_t)row0 * SSc + n];
            float* p1 = &C[(size_t)(row0 + 8) * SSc + n];
            asm volatile("red.global.add.v2.f32 [%0], {%1,%2};"
                         :: "l"(p0), "f"(acc[mf][nf][0]), "f"(acc[mf][nf][1]) : "memory");
            asm volatile("red.global.add.v2.f32 [%0], {%1,%2};"
                         :: "l"(p1), "f"(acc[mf][nf][2]), "f"(acc[mf][nf][3]) : "memory");
        }
    }
}

// ---------------- graph kernels ---------------------------------------------
__global__ void deg_k(const void* __restrict__ ei) {
    int e = blockIdx.x * blockDim.x + threadIdx.x;
    if (e < EE) atomicAdd(&g_deg[edge_at(ei, (long long)EE + e)], 1.0f);
}
__global__ void dinv_k() {
    int n = blockIdx.x * blockDim.x + threadIdx.x;
    if (n < NN) g_deg[n] = rsqrtf(g_deg[n] + 1.0f);
}
__global__ void norm_k(const void* __restrict__ ei) {
    int e = blockIdx.x * blockDim.x + threadIdx.x;
    if (e < EE) g_norm[e] = g_deg[edge_at(ei, e)] * g_deg[edge_at(ei, (long long)EE + e)];
}
__global__ void scatter_k(const void* __restrict__ ei) {
    long long idx = (long long)blockIdx.x * blockDim.x + threadIdx.x;
    int e = (int)(idx >> 7);
    int c = ((int)idx & 127) * 4;
    int src = edge_at(ei, e);
    int dst = edge_at(ei, (long long)EE + e);
    float nrm = g_norm[e];
    float4 v = *reinterpret_cast<const float4*>(&g_xwht[(size_t)src * 1024 + c]);
    float* o = &g_bufL[(size_t)dst * DD + c];
    asm volatile("red.global.add.v4.f32 [%0], {%1,%2,%3,%4};"
                 :: "l"(o), "f"(nrm * v.x), "f"(nrm * v.y),
                    "f"(nrm * v.z), "f"(nrm * v.w) : "memory");
}

__global__ void finish_gcn_k(const float* __restrict__ x, const float* __restrict__ gcn_b) {
    const int c = threadIdx.x;
    const int r0 = blockIdx.x * 128;
    const int rEnd = min(r0 + 128, NN);
    const float bc = gcn_b[c];
    float s = 0.f, s2 = 0.f;
    for (int r = r0; r < rEnd; r++) {
        size_t o = (size_t)r * DD + c;
        float dv = g_deg[r];
        float v = x[o] + g_bufL[o] + dv * dv * g_xwht[(size_t)r * 1024 + c] + bc;
        g_bufL[o] = v;
        s += v; s2 += v * v;
    }
    atomicAdd(&g_stats[0 * DD + c], s);
    atomicAdd(&g_stats[1 * DD + c], s2);
}

__global__ void addx_stats_k(const float* __restrict__ x, float* __restrict__ buf, int bn) {
    const int c = threadIdx.x;
    const int r0 = blockIdx.x * 128;
    const int rEnd = min(r0 + 128, NN);
    float s = 0.f, s2 = 0.f;
    for (int r = r0; r < rEnd; r++) {
        size_t o = (size_t)r * DD + c;
        float v = x[o] + buf[o];
        buf[o] = v;
        s += v; s2 += v * v;
    }
    atomicAdd(&g_stats[(bn * 2 + 0) * DD + c], s);
    atomicAdd(&g_stats[(bn * 2 + 1) * DD + c], s2);
}

__global__ void finalize_k(int bn, const float* __restrict__ gamma, const float* __restrict__ beta) {
    int c = threadIdx.x;
    float s  = g_stats[(bn * 2 + 0) * DD + c];
    float s2 = g_stats[(bn * 2 + 1) * DD + c];
    float m = s * (1.0f / NN);
    float var = s2 * (1.0f / NN) - m * m;
    float a = gamma[c] * rsqrtf(var + EPSC);
    g_coef[(bn * 2 + 0) * DD + c] = a;
    g_coef[(bn * 2 + 1) * DD + c] = beta[c] - m * a;
}

__global__ void apply_sum_k() {          // h exact + tf32 copy
    int idx = blockIdx.x * blockDim.x + threadIdx.x;
    if (idx >= NN * DD) return;
    int c = idx & (DD - 1);
    float v = g_bufL[idx] * g_coef[c] + g_coef[DD + c]
            + g_bufA[idx] * g_coef[2 * DD + c] + g_coef[3 * DD + c];
    g_h[idx] = v;
    g_h32[idx] = tf32r(v);
}
__global__ void bn2_apply_k(float* __restrict__ out) {
    int idx = blockIdx.x * blockDim.x + threadIdx.x;
    if (idx >= NN * DD) return;
    int c = idx & (DD - 1);
    out[idx] = g_ff[idx] * g_coef[4 * DD + c] + g_coef[5 * DD + c];
}

// ---------------- wave helpers ----------------------------------------------
__global__ void pack_w_k(const float* __restrict__ gcnW,
                         const float* __restrict__ linW,
                         const float* __restrict__ linB) {
    int idx = blockIdx.x * blockDim.x + threadIdx.x;
    if (idx >= DD * 1024) return;
    int d = idx >> 10, j = idx & 1023;
    float v;
    if (j < 512) v = gcnW[d * DD + j];
    else {
        int t = (j - 512) >> 7, s = (j - 512) & 127;
        v = linW[t * (DD * SSc) + d * SSc + s];
    }
    g_bigW[idx] = tf32r(v);
    if (idx < 1024) {
        float b = 0.f;
        if (idx >= 512) { int t = (idx - 512) >> 7, s = (idx - 512) & 127; b = linB[t * SSc + s]; }
        g_bigB[idx] = b;
    }
}
__global__ void scale_sig_k(float* __restrict__ u, const float* __restrict__ fs) {
    int idx = blockIdx.x * blockDim.x + threadIdx.x;
    if (idx >= TJc * KK * SSc) return;
    int t = idx >> 14;
    int k = (idx >> 7) & 127;
    u[idx] = tf32r(u[idx] * fs[k * TJc + t]);
}

// ---------------- launch -----------------------------------------------------
#define GSYM(p, s) do { void* _t; cudaGetSymbolAddress(&_t, s); (p) = (float*)_t; } while (0)

extern "C" void kernel_launch(void* const* d_in, const int* in_sizes, int n_in,
                              void* d_out, int out_size) {
    const float* x        = (const float*)d_in[0];
    const void*  ei       = d_in[1];
    const float* evc      = (const float*)d_in[2];
    const float* fs       = (const float*)d_in[3];
    const float* gcn_W    = (const float*)d_in[4];
    const float* gcn_b    = (const float*)d_in[5];
    const float* lin_W    = (const float*)d_in[6];
    const float* lin_b    = (const float*)d_in[7];
    const float* fusion_W = (const float*)d_in[8];
    const float* fusion_b = (const float*)d_in[9];
    const float* bn1l_g   = (const float*)d_in[10];
    const float* bn1l_b   = (const float*)d_in[11];
    const float* bn1a_g   = (const float*)d_in[12];
    const float* bn1a_b   = (const float*)d_in[13];
    const float* bn2_g    = (const float*)d_in[14];
    const float* bn2_b    = (const float*)d_in[15];
    const float* ff1_W    = (const float*)d_in[16];
    const float* ff1_b    = (const float*)d_in[17];
    const float* ff2_W    = (const float*)d_in[18];
    const float* ff2_b    = (const float*)d_in[19];
    float* out = (float*)d_out;

    float *p_xwht, *p_bufL, *p_v, *p_comb, *p_bufA, *p_h, *p_h32, *p_mid, *p_ff;
    float *p_u, *p_u2, *p_bigW, *p_bigB, *p_xt, *p_evct, *p_fWt, *p_f1Wt, *p_f2Wt;
    GSYM(p_xwht, g_xwht); GSYM(p_bufL, g_bufL); GSYM(p_v, g_v);
    GSYM(p_comb, g_comb); GSYM(p_bufA, g_bufA); GSYM(p_h, g_h);
    GSYM(p_h32, g_h32);   GSYM(p_mid, g_mid);   GSYM(p_ff, g_ff);
    GSYM(p_u, g_u);       GSYM(p_u2, g_u2);     GSYM(p_bigW, g_bigW);
    GSYM(p_bigB, g_bigB); GSYM(p_xt, g_xt);     GSYM(p_evct, g_evct);
    GSYM(p_fWt, g_fWt);   GSYM(p_f1Wt, g_f1Wt); GSYM(p_f2Wt, g_f2Wt);

    const int GEMM_SMEM = (2 * 128 * 36 + 2 * 32 * 136) * 4;   // 71680
    const int ATB_SMEM  = (2 * 32 * 136 * 2) * 4;              // 69632
    cudaFuncSetAttribute(tcgemm_k<true,  false, false>, cudaFuncAttributeMaxDynamicSharedMemorySize, GEMM_SMEM);
    cudaFuncSetAttribute(tcgemm_k<false, true,  false>, cudaFuncAttributeMaxDynamicSharedMemorySize, GEMM_SMEM);
    cudaFuncSetAttribute(tcgemm_k<false, false, true >, cudaFuncAttributeMaxDynamicSharedMemorySize, GEMM_SMEM);
    cudaFuncSetAttribute(tcgemm_k<true,  true,  false>, cudaFuncAttributeMaxDynamicSharedMemorySize, GEMM_SMEM);
    cudaFuncSetAttribute(tcgemm_k<true,  true,  true >, cudaFuncAttributeMaxDynamicSharedMemorySize, GEMM_SMEM);
    cudaFuncSetAttribute(atb_k, cudaFuncAttributeMaxDynamicSharedMemorySize, ATB_SMEM);

    const int MB = (NN + 127) / 128;           // 391
    dim3 gBig(1024 / 128, MB);
    dim3 gD(DD / 128, MB);
    dim3 gF(DD2 / 128, MB);
    dim3 gFwd(1, MB, TJc);
    dim3 gAtb(ATB_BLKS, 1, TJc);

    detect_k<<<1, 256>>>((const int*)ei);
    zero_scratch_k<<<2048, 256>>>();
    pack_w_k<<<(DD * 1024 + 255) / 256, 256>>>(gcn_W, lin_W, lin_b);
    round_k<<<1024, 256>>>(x, p_xt, (long long)NN * DD);
    round_k<<<256, 256>>>(evc, p_evct, (long long)NN * KK);
    round_k<<<128, 256>>>(fusion_W, p_fWt, DD * DD);
    round_k<<<256, 256>>>(ff1_W, p_f1Wt, DD * DD2);
    round_k<<<256, 256>>>(ff2_W, p_f2Wt, DD2 * DD);

    // ---- fused first GEMM: [xw | ht] = x_t @ [gcn_W | lin_W]_t ----
    tcgemm_k<true, false, false><<<gBig, 256, GEMM_SMEM>>>(
        p_xt, DD, p_bigW, 1024, 0, p_xwht, 1024, 0, p_bigB, NN, DD);

    // ---- GCN branch ----
    deg_k<<<(EE + 255) / 256, 256>>>(ei);
    dinv_k<<<(NN + 255) / 256, 256>>>();
    norm_k<<<(EE + 255) / 256, 256>>>(ei);
    scatter_k<<<(EE * 128) / 256, 256>>>(ei);
    finish_gcn_k<<<MB, DD>>>(x, gcn_b);

    // ---- Wave branch (z-batched over t) ----
    atb_k<<<gAtb, 256, ATB_SMEM>>>(p_evct, p_xwht + 512, 1024, 128, p_u);
    scale_sig_k<<<(TJc * KK * SSc + 255) / 256, 256>>>(p_u, fs);
    tcgemm_k<false, true, false><<<gFwd, 256, GEMM_SMEM>>>(
        p_evct, KK, p_u, SSc, KK * SSc, p_v, SSc, (long long)NN * SSc, nullptr, NN, KK);
    atb_k<<<gAtb, 256, ATB_SMEM>>>(p_evct, p_v, SSc, (long long)NN * SSc, p_u2);
    scale_sig_k<<<(TJc * KK * SSc + 255) / 256, 256>>>(p_u2, fs);
    tcgemm_k<false, false, true><<<gFwd, 256, GEMM_SMEM>>>(
        p_evct, KK, p_u2, SSc, KK * SSc, p_comb, DD, SSc, nullptr, NN, KK);
    tcgemm_k<true, true, false><<<gD, 256, GEMM_SMEM>>>(
        p_comb, DD, p_fWt, DD, 0, p_bufA, DD, 0, fusion_b, NN, DD);
    addx_stats_k<<<MB, DD>>>(x, p_bufA, 1);

    // ---- combine + BN ----
    finalize_k<<<1, DD>>>(0, bn1l_g, bn1l_b);
    finalize_k<<<1, DD>>>(1, bn1a_g, bn1a_b);
    apply_sum_k<<<(NN * DD + 255) / 256, 256>>>();

    // ---- feed-forward ----
    tcgemm_k<true, true, true><<<gF, 256, GEMM_SMEM>>>(
        p_h32, DD, p_f1Wt, DD2, 0, p_mid, DD2, 0, ff1_b, NN, DD);
    tcgemm_k<true, false, false><<<gD, 256, GEMM_SMEM>>>(
        p_mid, DD2, p_f2Wt, DD, 0, p_ff, DD, 0, ff2_b, NN, DD2);
    addx_stats_k<<<MB, DD>>>(p_h, p_ff, 2);
    finalize_k<<<1, DD>>>(2, bn2_g, bn2_b);
    bn2_apply_k<<<(NN * DD + 255) / 256, 256>>>(out);
}

// round 6
// speedup vs baseline: 3.3304x; 1.1324x over previous
#include <cuda_runtime.h>
#include <cstdint>

#define NN  50000
#define EE  800000
#define DD  512
#define KK  128
#define TJc 4
#define SSc 128
#define DD2 1024
#define EPSC 1e-5f

// ---------------- scratch (device globals) -----------------------------------
__device__ float g_xw  [(size_t)NN * DD];        // x @ gcn_W
__device__ float g_bufL[(size_t)NN * DD];
__device__ float g_v   [(size_t)TJc * NN * SSc]; // relu(evc@u), tf32-rounded
__device__ float g_bufA[(size_t)NN * DD];
__device__ float g_h   [(size_t)NN * DD];
__device__ float g_h32 [(size_t)NN * DD];        // tf32 copy of h
__device__ float g_mid [(size_t)NN * DD2];       // tf32-rounded
__device__ float g_ff  [(size_t)NN * DD];
__device__ float g_xt  [(size_t)NN * DD];        // tf32 x
__device__ float g_evct[(size_t)NN * KK];        // tf32 evc
__device__ float g_norm[EE];
__device__ float g_deg [NN];
__device__ float g_esum[KK];                     // colsum of evc
__device__ float g_xe  [KK * DD];                // evc^T @ x
__device__ float g_uraw[KK * DD];                // xe @ linW
__device__ float g_u   [KK * DD];                // sig*(...), [k][t*128+s], tf32
__device__ float g_u2  [KK * DD];                // evc^T@v, then sig*, tf32
__device__ float g_W2  [KK * DD];                // u2 @ fusion_W, tf32
__device__ float g_stats[6 * DD];
__device__ float g_coef [6 * DD];
__device__ float g_gWt  [DD * DD];               // tf32 gcn_W
__device__ float g_linWp[DD * DD];               // tf32 packed lin_W [d][t*128+s]
__device__ float g_fWt  [DD * DD];               // tf32 fusion_W
__device__ float g_f1Wt [DD * DD2];              // tf32 ff1_W
__device__ float g_f2Wt [DD2 * DD];              // tf32 ff2_W
__device__ int   g_is64;

// ---------------- helpers -----------------------------------------------------
__device__ __forceinline__ float tf32r(float f) {
    uint32_t u; asm("cvt.rna.tf32.f32 %0, %1;" : "=r"(u) : "f"(f));
    return __uint_as_float(u);
}
__device__ __forceinline__ void mma_tf32(float* c, const uint32_t* a, const uint32_t* b) {
    asm volatile("mma.sync.aligned.m16n8k8.row.col.f32.tf32.tf32.f32 "
        "{%0,%1,%2,%3}, {%4,%5,%6,%7}, {%8,%9}, {%0,%1,%2,%3};"
        : "+f"(c[0]), "+f"(c[1]), "+f"(c[2]), "+f"(c[3])
        : "r"(a[0]), "r"(a[1]), "r"(a[2]), "r"(a[3]), "r"(b[0]), "r"(b[1]));
}
__device__ __forceinline__ void cp16(void* sdst, const void* gsrc, bool pred) {
    uint32_t sa = (uint32_t)__cvta_generic_to_shared(sdst);
    int sz = pred ? 16 : 0;
    asm volatile("cp.async.cg.shared.global [%0], [%1], 16, %2;"
                 :: "r"(sa), "l"(gsrc), "r"(sz));
}
#define CP_COMMIT() asm volatile("cp.async.commit_group;")
#define CP_WAIT(n)  asm volatile("cp.async.wait_group %0;" :: "n"(n))

// ---------------- edge-index dtype detection --------------------------------
__global__ void detect_k(const int* __restrict__ ei32) {
    __shared__ int any;
    if (threadIdx.x == 0) any = 0;
    __syncthreads();
    int v = 0;
    for (int i = threadIdx.x; i < 1024; i += blockDim.x)
        v |= ei32[2 * i + 1];
    if (v) atomicOr(&any, 1);
    __syncthreads();
    if (threadIdx.x == 0) g_is64 = (any == 0) ? 1 : 0;
}
__device__ __forceinline__ int edge_at(const void* ei, long long pos) {
    return g_is64 ? (int)((const long long*)ei)[pos] : ((const int*)ei)[pos];
}

// ---------------- zero / round helpers ---------------------------------------
__global__ void zero_scratch_k() {
    int stride = gridDim.x * blockDim.x;
    int i0 = blockIdx.x * blockDim.x + threadIdx.x;
    for (size_t i = i0; i < (size_t)NN * DD; i += stride) g_bufL[i] = 0.f;
    for (int i = i0; i < NN; i += stride) g_deg[i] = 0.f;
    for (int i = i0; i < KK * DD; i += stride) { g_xe[i] = 0.f; g_u2[i] = 0.f; }
    for (int i = i0; i < 6 * DD; i += stride) g_stats[i] = 0.f;
    for (int i = i0; i < KK; i += stride) g_esum[i] = 0.f;
}
__global__ void round_k(const float* __restrict__ in, float* __restrict__ o, long long n) {
    long long i = (long long)blockIdx.x * blockDim.x + threadIdx.x;
    long long stride = (long long)gridDim.x * blockDim.x;
    for (; i < n / 4; i += stride) {
        float4 v = reinterpret_cast<const float4*>(in)[i];
        v.x = tf32r(v.x); v.y = tf32r(v.y); v.z = tf32r(v.z); v.w = tf32r(v.w);
        reinterpret_cast<float4*>(o)[i] = v;
    }
}
// colsum of evc: 128 threads/block, block handles a row chunk; coalesced rows.
__global__ void colsum_k(const float* __restrict__ evc) {
    int c = threadIdx.x;                     // 128
    int r0 = blockIdx.x * 500;
    int r1 = min(r0 + 500, NN);
    float s = 0.f;
    for (int r = r0; r < r1; r++) s += evc[(size_t)r * KK + c];
    atomicAdd(&g_esum[c], s);
}

// ---------------- pipelined TF32 GEMM (operands pre-rounded) -----------------
template <bool BIAS, bool RELU, bool RND>
__global__ void __launch_bounds__(256, 2) tcgemm_k(
    const float* __restrict__ A, int lda,
    const float* __restrict__ B, int ldb, long long bTs,
    float* __restrict__ C, int ldc, long long cTs,
    const float* __restrict__ bias,
    int M, int Kd)
{
    extern __shared__ uint32_t dyn[];
    uint32_t (*As)[128][36]  = reinterpret_cast<uint32_t(*)[128][36]>(dyn);
    uint32_t (*Bs)[32][136]  = reinterpret_cast<uint32_t(*)[32][136]>(dyn + 2 * 128 * 36);

    B += (long long)blockIdx.z * bTs;
    C += (long long)blockIdx.z * cTs;

    const int m0 = blockIdx.y * 128;
    const int n0 = blockIdx.x * 128;
    const int tid = threadIdx.x;
    const int lane = tid & 31;
    const int wid = tid >> 5;
    const int g = lane >> 2, t = lane & 3;
    const int wm0 = (wid & 1) * 64;
    const int wn0 = (wid >> 1) * 32;

    float acc[4][4][4] = {};
    const int T = Kd >> 5;

    auto load_tiles = [&](int it, int s) {
        int k0 = it * 32;
        #pragma unroll
        for (int l = 0; l < 4; l++) {
            int idx = tid + l * 256;
            int r = idx >> 3, c = (idx & 7) * 4;
            bool p = (m0 + r < M);
            int row = p ? (m0 + r) : 0;
            cp16(&As[s][r][c], &A[(size_t)row * lda + k0 + c], p);
        }
        #pragma unroll
        for (int l = 0; l < 4; l++) {
            int idx = tid + l * 256;
            int r = idx >> 5, c = (idx & 31) * 4;
            cp16(&Bs[s][r][c], &B[(size_t)(k0 + r) * ldb + n0 + c], true);
        }
    };

    load_tiles(0, 0);
    CP_COMMIT();

    for (int i = 0; i < T; i++) {
        int cur = i & 1;
        if (i + 1 < T) { load_tiles(i + 1, cur ^ 1); CP_COMMIT(); CP_WAIT(1); }
        else          { CP_WAIT(0); }
        __syncthreads();
        #pragma unroll
        for (int kk = 0; kk < 4; kk++) {
            uint32_t af[4][4], bf[4][2];
            #pragma unroll
            for (int mf = 0; mf < 4; mf++) {
                int mr = wm0 + mf * 16;
                af[mf][0] = As[cur][mr + g    ][kk * 8 + t];
                af[mf][1] = As[cur][mr + g + 8][kk * 8 + t];
                af[mf][2] = As[cur][mr + g    ][kk * 8 + t + 4];
                af[mf][3] = As[cur][mr + g + 8][kk * 8 + t + 4];
            }
            #pragma unroll
            for (int nf = 0; nf < 4; nf++) {
                bf[nf][0] = Bs[cur][kk * 8 + t    ][wn0 + nf * 8 + g];
                bf[nf][1] = Bs[cur][kk * 8 + t + 4][wn0 + nf * 8 + g];
            }
            #pragma unroll
            for (int mf = 0; mf < 4; mf++)
                #pragma unroll
                for (int nf = 0; nf < 4; nf++)
                    mma_tf32(acc[mf][nf], af[mf], bf[nf]);
        }
        __syncthreads();
    }

    #pragma unroll
    for (int mf = 0; mf < 4; mf++) {
        int row0 = m0 + wm0 + mf * 16 + g;
        int row1 = row0 + 8;
        #pragma unroll
        for (int nf = 0; nf < 4; nf++) {
            int n = n0 + wn0 + nf * 8 + 2 * t;
            float b0 = 0.f, b1 = 0.f;
            if (BIAS) { b0 = bias[n]; b1 = bias[n + 1]; }
            float2 v0 = make_float2(acc[mf][nf][0] + b0, acc[mf][nf][1] + b1);
            float2 v1 = make_float2(acc[mf][nf][2] + b0, acc[mf][nf][3] + b1);
            if (RELU) {
                v0.x = fmaxf(v0.x, 0.f); v0.y = fmaxf(v0.y, 0.f);
                v1.x = fmaxf(v1.x, 0.f); v1.y = fmaxf(v1.y, 0.f);
            }
            if (RND) {
                v0.x = tf32r(v0.x); v0.y = tf32r(v0.y);
                v1.x = tf32r(v1.x); v1.y = tf32r(v1.y);
            }
            if (row0 < M) *reinterpret_cast<float2*>(&C[(size_t)row0 * ldc + n]) = v0;
            if (row1 < M) *reinterpret_cast<float2*>(&C[(size_t)row1 * ldc + n]) = v1;
        }
    }
}

// ------- tensor-core tall reduction: C[128, cols] += evc^T[128,N]*B[N,cols] -
// All operands pre-rounded tf32. blockIdx.y = 128-col tile, blockIdx.z batch.
#define ATB_BLKS 64
__global__ void __launch_bounds__(256, 2) atb_k(
    const float* __restrict__ evc,
    const float* __restrict__ B, int ldb, long long bTs,
    float* __restrict__ C, int ldc, long long cTs)
{
    extern __shared__ uint32_t dyn[];
    uint32_t (*Es)[32][136] = reinterpret_cast<uint32_t(*)[32][136]>(dyn);
    uint32_t (*Hs)[32][136] = reinterpret_cast<uint32_t(*)[32][136]>(dyn + 2 * 32 * 136);

    B += (long long)blockIdx.z * bTs;
    C += (long long)blockIdx.z * cTs;
    const int noff = blockIdx.y * 128;

    const int chunk = (NN + ATB_BLKS - 1) / ATB_BLKS;
    const int nStart = blockIdx.x * chunk;
    const int nEnd = min(nStart + chunk, NN);
    const int iters = (chunk + 31) / 32;
    const int tid = threadIdx.x;
    const int lane = tid & 31;
    const int wid = tid >> 5;
    const int g = lane >> 2, t = lane & 3;
    const int wm0 = (wid & 1) * 64;
    const int wn0 = (wid >> 1) * 32;

    float acc[4][4][4] = {};

    auto load_tiles = [&](int it, int s) {
        int n0 = nStart + it * 32;
        #pragma unroll
        for (int l = 0; l < 4; l++) {
            int idx = tid + l * 256;
            int r = idx >> 5, c = (idx & 31) * 4;
            bool p = (n0 + r < nEnd);
            int row = p ? (n0 + r) : 0;
            cp16(&Es[s][r][c], &evc[(size_t)row * KK + c], p);
            cp16(&Hs[s][r][c], &B[(size_t)row * ldb + noff + c], p);
        }
    };

    load_tiles(0, 0);
    CP_COMMIT();

    for (int i = 0; i < iters; i++) {
        int cur = i & 1;
        if (i + 1 < iters) { load_tiles(i + 1, cur ^ 1); CP_COMMIT(); CP_WAIT(1); }
        else              { CP_WAIT(0); }
        __syncthreads();
        #pragma unroll
        for (int kk = 0; kk < 4; kk++) {
            uint32_t af[4][4], bf[4][2];
            #pragma unroll
            for (int mf = 0; mf < 4; mf++) {
                int mc = wm0 + mf * 16;
                af[mf][0] = Es[cur][kk * 8 + t    ][mc + g];
                af[mf][1] = Es[cur][kk * 8 + t    ][mc + g + 8];
                af[mf][2] = Es[cur][kk * 8 + t + 4][mc + g];
                af[mf][3] = Es[cur][kk * 8 + t + 4][mc + g + 8];
            }
            #pragma unroll
            for (int nf = 0; nf < 4; nf++) {
                bf[nf][0] = Hs[cur][kk * 8 + t    ][wn0 + nf * 8 + g];
                bf[nf][1] = Hs[cur][kk * 8 + t + 4][wn0 + nf * 8 + g];
            }
            #pragma unroll
            for (int mf = 0; mf < 4; mf++)
                #pragma unroll
                for (int nf = 0; nf < 4; nf++)
                    mma_tf32(acc[mf][nf], af[mf], bf[nf]);
        }
        __syncthreads();
    }

    #pragma unroll
    for (int mf = 0; mf < 4; mf++) {
        int row0 = wm0 + mf * 16 + g;
        #pragma unroll
        for (int nf = 0; nf < 4; nf++) {
            int n = noff + wn0 + nf * 8 + 2 * t;
            float* p0 = &C[(size_t)row0 * ldc + n];
            float* p1 = &C[(size_t)(row0 + 8) * ldc + n];
            asm volatile("red.global.add.v2.f32 [%0], {%1,%2};"
                         :: "l"(p0), "f"(acc[mf][nf][0]), "f"(acc[mf][nf][1]) : "memory");
            asm volatile("red.global.add.v2.f32 [%0], {%1,%2};"
                         :: "l"(p1), "f"(acc[mf][nf][2]), "f"(acc[mf][nf][3]) : "memory");
        }
    }
}

// ---------------- graph kernels ---------------------------------------------
__global__ void deg_k(const void* __restrict__ ei) {
    int e = blockIdx.x * blockDim.x + threadIdx.x;
    if (e < EE) atomicAdd(&g_deg[edge_at(ei, (long long)EE + e)], 1.0f);
}
__global__ void dinv_k() {
    int n = blockIdx.x * blockDim.x + threadIdx.x;
    if (n < NN) g_deg[n] = rsqrtf(g_deg[n] + 1.0f);
}
__global__ void norm_k(const void* __restrict__ ei) {
    int e = blockIdx.x * blockDim.x + threadIdx.x;
    if (e < EE) g_norm[e] = g_deg[edge_at(ei, e)] * g_deg[edge_at(ei, (long long)EE + e)];
}
__global__ void scatter_k(const void* __restrict__ ei) {
    long long idx = (long long)blockIdx.x * blockDim.x + threadIdx.x;
    int e = (int)(idx >> 7);
    int c = ((int)idx & 127) * 4;
    int src = edge_at(ei, e);
    int dst = edge_at(ei, (long long)EE + e);
    float nrm = g_norm[e];
    float4 v = *reinterpret_cast<const float4*>(&g_xw[(size_t)src * DD + c]);
    float* o = &g_bufL[(size_t)dst * DD + c];
    asm volatile("red.global.add.v4.f32 [%0], {%1,%2,%3,%4};"
                 :: "l"(o), "f"(nrm * v.x), "f"(nrm * v.y),
                    "f"(nrm * v.z), "f"(nrm * v.w) : "memory");
}

__global__ void finish_gcn_k(const float* __restrict__ x, const float* __restrict__ gcn_b) {
    const int c = threadIdx.x;
    const int r0 = blockIdx.x * 128;
    const int rEnd = min(r0 + 128, NN);
    const float bc = gcn_b[c];
    float s = 0.f, s2 = 0.f;
    for (int r = r0; r < rEnd; r++) {
        size_t o = (size_t)r * DD + c;
        float dv = g_deg[r];
        float v = x[o] + g_bufL[o] + dv * dv * g_xw[o] + bc;
        g_bufL[o] = v;
        s += v; s2 += v * v;
    }
    atomicAdd(&g_stats[0 * DD + c], s);
    atomicAdd(&g_stats[1 * DD + c], s2);
}

__global__ void addx_stats_k(const float* __restrict__ x, float* __restrict__ buf, int bn) {
    const int c = threadIdx.x;
    const int r0 = blockIdx.x * 128;
    const int rEnd = min(r0 + 128, NN);
    float s = 0.f, s2 = 0.f;
    for (int r = r0; r < rEnd; r++) {
        size_t o = (size_t)r * DD + c;
        float v = x[o] + buf[o];
        buf[o] = v;
        s += v; s2 += v * v;
    }
    atomicAdd(&g_stats[(bn * 2 + 0) * DD + c], s);
    atomicAdd(&g_stats[(bn * 2 + 1) * DD + c], s2);
}

__global__ void finalize_k(int bn, const float* __restrict__ gamma, const float* __restrict__ beta) {
    int c = threadIdx.x;
    float s  = g_stats[(bn * 2 + 0) * DD + c];
    float s2 = g_stats[(bn * 2 + 1) * DD + c];
    float m = s * (1.0f / NN);
    float var = s2 * (1.0f / NN) - m * m;
    float a = gamma[c] * rsqrtf(var + EPSC);
    g_coef[(bn * 2 + 0) * DD + c] = a;
    g_coef[(bn * 2 + 1) * DD + c] = beta[c] - m * a;
}

__global__ void apply_sum_k() {
    int idx = blockIdx.x * blockDim.x + threadIdx.x;
    if (idx >= NN * DD) return;
    int c = idx & (DD - 1);
    float v = g_bufL[idx] * g_coef[c] + g_coef[DD + c]
            + g_bufA[idx] * g_coef[2 * DD + c] + g_coef[3 * DD + c];
    g_h[idx] = v;
    g_h32[idx] = tf32r(v);
}
__global__ void bn2_apply_k(float* __restrict__ out) {
    int idx = blockIdx.x * blockDim.x + threadIdx.x;
    if (idx >= NN * DD) return;
    int c = idx & (DD - 1);
    out[idx] = g_ff[idx] * g_coef[4 * DD + c] + g_coef[5 * DD + c];
}

// ---------------- wave helpers ----------------------------------------------
__global__ void pack_w_k(const float* __restrict__ gcnW, const float* __restrict__ linW) {
    int idx = blockIdx.x * blockDim.x + threadIdx.x;   // DD*DD
    if (idx >= DD * DD) return;
    int d = idx >> 9, j = idx & 511;
    int t = j >> 7, s = j & 127;
    g_gWt[idx]   = tf32r(gcnW[idx]);
    g_linWp[idx] = tf32r(linW[t * (DD * SSc) + d * SSc + s]);
}
// u[k, t*128+s] = tf32( fs[k,t] * (uraw[k,j] + esum[k]*lin_b[t,s]) )
__global__ void post_u_k(const float* __restrict__ fs, const float* __restrict__ linB) {
    int idx = blockIdx.x * blockDim.x + threadIdx.x;   // KK*DD
    if (idx >= KK * DD) return;
    int k = idx >> 9, j = idx & 511;
    int t = j >> 7, s = j & 127;
    g_u[idx] = tf32r(fs[k * TJc + t] * (g_uraw[idx] + g_esum[k] * linB[t * SSc + s]));
}
// u2[k, t*128+s] *= fs[k,t]; round
__global__ void scale_u2_k(const float* __restrict__ fs) {
    int idx = blockIdx.x * blockDim.x + threadIdx.x;   // KK*DD
    if (idx >= KK * DD) return;
    int k = idx >> 9, t = (idx & 511) >> 7;
    g_u2[idx] = tf32r(g_u2[idx] * fs[k * TJc + t]);
}

// ---------------- launch -----------------------------------------------------
#define GSYM(p, s) do { void* _t; cudaGetSymbolAddress(&_t, s); (p) = (float*)_t; } while (0)

extern "C" void kernel_launch(void* const* d_in, const int* in_sizes, int n_in,
                              void* d_out, int out_size) {
    const float* x        = (const float*)d_in[0];
    const void*  ei       = d_in[1];
    const float* evc      = (const float*)d_in[2];
    const float* fs       = (const float*)d_in[3];
    const float* gcn_W    = (const float*)d_in[4];
    const float* gcn_b    = (const float*)d_in[5];
    const float* lin_W    = (const float*)d_in[6];
    const float* lin_b    = (const float*)d_in[7];
    const float* fusion_W = (const float*)d_in[8];
    const float* fusion_b = (const float*)d_in[9];
    const float* bn1l_g   = (const float*)d_in[10];
    const float* bn1l_b   = (const float*)d_in[11];
    const float* bn1a_g   = (const float*)d_in[12];
    const float* bn1a_b   = (const float*)d_in[13];
    const float* bn2_g    = (const float*)d_in[14];
    const float* bn2_b    = (const float*)d_in[15];
    const float* ff1_W    = (const float*)d_in[16];
    const float* ff1_b    = (const float*)d_in[17];
    const float* ff2_W    = (const float*)d_in[18];
    const float* ff2_b    = (const float*)d_in[19];
    float* out = (float*)d_out;

    float *p_xw, *p_bufL, *p_v, *p_bufA, *p_h, *p_h32, *p_mid, *p_ff;
    float *p_xt, *p_evct, *p_xe, *p_uraw, *p_u, *p_u2, *p_W2;
    float *p_gWt, *p_linWp, *p_fWt, *p_f1Wt, *p_f2Wt;
    GSYM(p_xw, g_xw);     GSYM(p_bufL, g_bufL); GSYM(p_v, g_v);
    GSYM(p_bufA, g_bufA); GSYM(p_h, g_h);       GSYM(p_h32, g_h32);
    GSYM(p_mid, g_mid);   GSYM(p_ff, g_ff);     GSYM(p_xt, g_xt);
    GSYM(p_evct, g_evct); GSYM(p_xe, g_xe);     GSYM(p_uraw, g_uraw);
    GSYM(p_u, g_u);       GSYM(p_u2, g_u2);     GSYM(p_W2, g_W2);
    GSYM(p_gWt, g_gWt);   GSYM(p_linWp, g_linWp); GSYM(p_fWt, g_fWt);
    GSYM(p_f1Wt, g_f1Wt); GSYM(p_f2Wt, g_f2Wt);

    const int GEMM_SMEM = (2 * 128 * 36 + 2 * 32 * 136) * 4;
    const int ATB_SMEM  = (2 * 32 * 136 * 2) * 4;
    cudaFuncSetAttribute(tcgemm_k<false, false, false>, cudaFuncAttributeMaxDynamicSharedMemorySize, GEMM_SMEM);
    cudaFuncSetAttribute(tcgemm_k<false, true,  true >, cudaFuncAttributeMaxDynamicSharedMemorySize, GEMM_SMEM);
    cudaFuncSetAttribute(tcgemm_k<false, false, true >, cudaFuncAttributeMaxDynamicSharedMemorySize, GEMM_SMEM);
    cudaFuncSetAttribute(tcgemm_k<true,  true,  false>, cudaFuncAttributeMaxDynamicSharedMemorySize, GEMM_SMEM);
    cudaFuncSetAttribute(tcgemm_k<true,  true,  true >, cudaFuncAttributeMaxDynamicSharedMemorySize, GEMM_SMEM);
    cudaFuncSetAttribute(tcgemm_k<true,  false, false>, cudaFuncAttributeMaxDynamicSharedMemorySize, GEMM_SMEM);
    cudaFuncSetAttribute(atb_k, cudaFuncAttributeMaxDynamicSharedMemorySize, ATB_SMEM);

    const int MB = (NN + 127) / 128;          // 391
    dim3 gD(4, MB);                            // N x 512
    dim3 gF(8, MB);                            // N x 1024
    dim3 gV(1, MB, TJc);                       // N x 128 per t
    dim3 gTiny(4, 1);                          // 128 x 512
    dim3 gAtbX(ATB_BLKS, 4, 1);                // xe: 512 cols
    dim3 gAtbU(ATB_BLKS, 1, TJc);              // u2: per t

    detect_k<<<1, 256>>>((const int*)ei);
    zero_scratch_k<<<2048, 256>>>();
    pack_w_k<<<(DD * DD + 255) / 256, 256>>>(gcn_W, lin_W);
    round_k<<<1024, 256>>>(x, p_xt, (long long)NN * DD);
    round_k<<<256, 256>>>(evc, p_evct, (long long)NN * KK);
    round_k<<<128, 256>>>(fusion_W, p_fWt, DD * DD);
    round_k<<<256, 256>>>(ff1_W, p_f1Wt, DD * DD2);
    round_k<<<256, 256>>>(ff2_W, p_f2Wt, DD2 * DD);

    // ---- GCN branch ----
    tcgemm_k<false, false, false><<<gD, 256, GEMM_SMEM>>>(
        p_xt, DD, p_gWt, DD, 0, p_xw, DD, 0, nullptr, NN, DD);
    deg_k<<<(EE + 255) / 256, 256>>>(ei);
    dinv_k<<<(NN + 255) / 256, 256>>>();
    norm_k<<<(EE + 255) / 256, 256>>>(ei);
    scatter_k<<<(EE * 128) / 256, 256>>>(ei);
    finish_gcn_k<<<MB, DD>>>(x, gcn_b);

    // ---- Wave branch (factored through K=128) ----
    colsum_k<<<(NN + 499) / 500, KK>>>(evc);
    atb_k<<<gAtbX, 256, ATB_SMEM>>>(p_evct, p_xt, DD, 0, p_xe, DD, 0);   // xe = evc^T x
    round_k<<<64, 256>>>(p_xe, p_xe, KK * DD);
    tcgemm_k<false, false, false><<<gTiny, 256, GEMM_SMEM>>>(            // uraw = xe @ linWp
        p_xe, DD, p_linWp, DD, 0, p_uraw, DD, 0, nullptr, KK, DD);
    post_u_k<<<(KK * DD + 255) / 256, 256>>>(fs, lin_b);                 // -> g_u (tf32)
    tcgemm_k<false, true, true><<<gV, 256, GEMM_SMEM>>>(                 // v = relu(evc@u)
        p_evct, KK, p_u, DD, 128, p_v, SSc, (long long)NN * SSc, nullptr, NN, KK);
    atb_k<<<gAtbU, 256, ATB_SMEM>>>(p_evct, p_v, SSc, (long long)NN * SSc,
                                    p_u2, DD, 128);                      // u2 = evc^T v
    scale_u2_k<<<(KK * DD + 255) / 256, 256>>>(fs);                      // tf32 rounded
    tcgemm_k<false, false, true><<<gTiny, 256, GEMM_SMEM>>>(             // W2 = u2 @ fusion_W
        p_u2, DD, p_fWt, DD, 0, p_W2, DD, 0, nullptr, KK, DD);
    tcgemm_k<true, true, false><<<gD, 256, GEMM_SMEM>>>(                 // bufA = relu(evc@W2+b)
        p_evct, KK, p_W2, DD, 0, p_bufA, DD, 0, fusion_b, NN, KK);
    addx_stats_k<<<MB, DD>>>(x, p_bufA, 1);

    // ---- combine + BN ----
    finalize_k<<<1, DD>>>(0, bn1l_g, bn1l_b);
    finalize_k<<<1, DD>>>(1, bn1a_g, bn1a_b);
    apply_sum_k<<<(NN * DD + 255) / 256, 256>>>();

    // ---- feed-forward ----
    tcgemm_k<true, true, true><<<gF, 256, GEMM_SMEM>>>(
        p_h32, DD, p_f1Wt, DD2, 0, p_mid, DD2, 0, ff1_b, NN, DD);
    tcgemm_k<true, false, false><<<gD, 256, GEMM_SMEM>>>(
        p_mid, DD2, p_f2Wt, DD, 0, p_ff, DD, 0, ff2_b, NN, DD2);
    addx_stats_k<<<MB, DD>>>(p_h, p_ff, 2);
    finalize_k<<<1, DD>>>(2, bn2_g, bn2_b);
    bn2_apply_k<<<(NN * DD + 255) / 256, 256>>>(out);
}

// round 7
// speedup vs baseline: 3.4533x; 1.0369x over previous
#include <cuda_runtime.h>
#include <cstdint>

#define NN  50000
#define EE  800000
#define DD  512
#define KK  128
#define TJc 4
#define SSc 128
#define DD2 1024
#define EPSC 1e-5f

// ---------------- scratch (device globals) -----------------------------------
__device__ float g_xw  [(size_t)NN * DD];        // x @ gcn_W
__device__ float g_bufL[(size_t)NN * DD];
__device__ float g_v   [(size_t)TJc * NN * SSc]; // relu(evc@u), tf32-rounded
__device__ float g_bufA[(size_t)NN * DD];
__device__ float g_h   [(size_t)NN * DD];
__device__ float g_mid [(size_t)NN * DD2];       // tf32-rounded
__device__ float g_ff  [(size_t)NN * DD];
__device__ float g_xt  [(size_t)NN * DD];        // tf32 x
__device__ float g_evct[(size_t)NN * KK];        // tf32 evc
__device__ float g_norm[EE];
__device__ float g_deg [NN];
__device__ float g_esum[KK];
__device__ float g_xe  [KK * DD];
__device__ float g_uraw[KK * DD];
__device__ float g_u   [KK * DD];
__device__ float g_u2  [KK * DD];
__device__ float g_W2  [KK * DD];
__device__ float g_stats[6 * DD];
__device__ float g_coef [6 * DD];
__device__ float g_gWt  [DD * DD];
__device__ float g_linWp[DD * DD];
__device__ float g_fWt  [DD * DD];
__device__ float g_f1Wt [DD * DD2];
__device__ float g_f2Wt [DD2 * DD];
__device__ int   g_is64;

// ---------------- helpers -----------------------------------------------------
__device__ __forceinline__ float tf32r(float f) {
    uint32_t u; asm("cvt.rna.tf32.f32 %0, %1;" : "=r"(u) : "f"(f));
    return __uint_as_float(u);
}
__device__ __forceinline__ uint32_t cvt_rna(uint32_t x) {
    uint32_t u; float f = __uint_as_float(x);
    asm("cvt.rna.tf32.f32 %0, %1;" : "=r"(u) : "f"(f)); return u;
}
__device__ __forceinline__ void mma_tf32(float* c, const uint32_t* a, const uint32_t* b) {
    asm volatile("mma.sync.aligned.m16n8k8.row.col.f32.tf32.tf32.f32 "
        "{%0,%1,%2,%3}, {%4,%5,%6,%7}, {%8,%9}, {%0,%1,%2,%3};"
        : "+f"(c[0]), "+f"(c[1]), "+f"(c[2]), "+f"(c[3])
        : "r"(a[0]), "r"(a[1]), "r"(a[2]), "r"(a[3]), "r"(b[0]), "r"(b[1]));
}
__device__ __forceinline__ void cp16(void* sdst, const void* gsrc, bool pred) {
    uint32_t sa = (uint32_t)__cvta_generic_to_shared(sdst);
    int sz = pred ? 16 : 0;
    asm volatile("cp.async.cg.shared.global [%0], [%1], 16, %2;"
                 :: "r"(sa), "l"(gsrc), "r"(sz));
}
#define CP_COMMIT() asm volatile("cp.async.commit_group;")
#define CP_WAIT(n)  asm volatile("cp.async.wait_group %0;" :: "n"(n))

// ---------------- edge-index dtype detection --------------------------------
__global__ void detect_k(const int* __restrict__ ei32) {
    __shared__ int any;
    if (threadIdx.x == 0) any = 0;
    __syncthreads();
    int v = 0;
    for (int i = threadIdx.x; i < 1024; i += blockDim.x)
        v |= ei32[2 * i + 1];
    if (v) atomicOr(&any, 1);
    __syncthreads();
    if (threadIdx.x == 0) g_is64 = (any == 0) ? 1 : 0;
}
__device__ __forceinline__ int edge_at(const void* ei, long long pos) {
    return g_is64 ? (int)((const long long*)ei)[pos] : ((const int*)ei)[pos];
}

// ---------------- zero / round helpers ---------------------------------------
__global__ void zero_scratch_k() {
    int stride = gridDim.x * blockDim.x;
    int i0 = blockIdx.x * blockDim.x + threadIdx.x;
    for (size_t i = i0; i < (size_t)NN * DD; i += stride) g_bufL[i] = 0.f;
    for (int i = i0; i < NN; i += stride) g_deg[i] = 0.f;
    for (int i = i0; i < KK * DD; i += stride) { g_xe[i] = 0.f; g_u2[i] = 0.f; }
    for (int i = i0; i < 6 * DD; i += stride) g_stats[i] = 0.f;
    for (int i = i0; i < KK; i += stride) g_esum[i] = 0.f;
}
__global__ void round_k(const float* __restrict__ in, float* __restrict__ o, long long n) {
    long long i = (long long)blockIdx.x * blockDim.x + threadIdx.x;
    long long stride = (long long)gridDim.x * blockDim.x;
    for (; i < n / 4; i += stride) {
        float4 v = reinterpret_cast<const float4*>(in)[i];
        v.x = tf32r(v.x); v.y = tf32r(v.y); v.z = tf32r(v.z); v.w = tf32r(v.w);
        reinterpret_cast<float4*>(o)[i] = v;
    }
}
__global__ void colsum_k(const float* __restrict__ evc) {
    int c = threadIdx.x;
    int r0 = blockIdx.x * 500;
    int r1 = min(r0 + 500, NN);
    float s = 0.f;
    for (int r = r0; r < r1; r++) s += evc[(size_t)r * KK + c];
    atomicAdd(&g_esum[c], s);
}

// ---------------- pipelined TF32 GEMM ----------------------------------------
// CVTA: cvt A fragments on read (A not pre-rounded).
// ADDST: C = Xadd + epilogue(acc); accumulate BN stats into g_stats[bn].
template <bool BIAS, bool RELU, bool RND, bool CVTA, bool ADDST>
__global__ void __launch_bounds__(256, 2) tcgemm_k(
    const float* __restrict__ A, int lda,
    const float* __restrict__ B, int ldb, long long bTs,
    float* __restrict__ C, int ldc, long long cTs,
    const float* __restrict__ bias,
    int M, int Kd,
    const float* __restrict__ Xadd, int bn)
{
    extern __shared__ uint32_t dyn[];
    uint32_t (*As)[128][36]  = reinterpret_cast<uint32_t(*)[128][36]>(dyn);
    uint32_t (*Bs)[32][136]  = reinterpret_cast<uint32_t(*)[32][136]>(dyn + 2 * 128 * 36);

    B += (long long)blockIdx.z * bTs;
    C += (long long)blockIdx.z * cTs;

    const int m0 = blockIdx.y * 128;
    const int n0 = blockIdx.x * 128;
    const int tid = threadIdx.x;
    const int lane = tid & 31;
    const int wid = tid >> 5;
    const int g = lane >> 2, t = lane & 3;
    const int wm0 = (wid & 1) * 64;
    const int wn0 = (wid >> 1) * 32;

    float acc[4][4][4] = {};
    const int T = Kd >> 5;

    auto load_tiles = [&](int it, int s) {
        int k0 = it * 32;
        #pragma unroll
        for (int l = 0; l < 4; l++) {
            int idx = tid + l * 256;
            int r = idx >> 3, c = (idx & 7) * 4;
            bool p = (m0 + r < M);
            int row = p ? (m0 + r) : 0;
            cp16(&As[s][r][c], &A[(size_t)row * lda + k0 + c], p);
        }
        #pragma unroll
        for (int l = 0; l < 4; l++) {
            int idx = tid + l * 256;
            int r = idx >> 5, c = (idx & 31) * 4;
            cp16(&Bs[s][r][c], &B[(size_t)(k0 + r) * ldb + n0 + c], true);
        }
    };

    load_tiles(0, 0);
    CP_COMMIT();

    for (int i = 0; i < T; i++) {
        int cur = i & 1;
        if (i + 1 < T) { load_tiles(i + 1, cur ^ 1); CP_COMMIT(); CP_WAIT(1); }
        else          { CP_WAIT(0); }
        __syncthreads();
        #pragma unroll
        for (int kk = 0; kk < 4; kk++) {
            uint32_t af[4][4], bf[4][2];
            #pragma unroll
            for (int mf = 0; mf < 4; mf++) {
                int mr = wm0 + mf * 16;
                uint32_t a0 = As[cur][mr + g    ][kk * 8 + t];
                uint32_t a1 = As[cur][mr + g + 8][kk * 8 + t];
                uint32_t a2 = As[cur][mr + g    ][kk * 8 + t + 4];
                uint32_t a3 = As[cur][mr + g + 8][kk * 8 + t + 4];
                if (CVTA) { a0 = cvt_rna(a0); a1 = cvt_rna(a1); a2 = cvt_rna(a2); a3 = cvt_rna(a3); }
                af[mf][0] = a0; af[mf][1] = a1; af[mf][2] = a2; af[mf][3] = a3;
            }
            #pragma unroll
            for (int nf = 0; nf < 4; nf++) {
                bf[nf][0] = Bs[cur][kk * 8 + t    ][wn0 + nf * 8 + g];
                bf[nf][1] = Bs[cur][kk * 8 + t + 4][wn0 + nf * 8 + g];
            }
            #pragma unroll
            for (int mf = 0; mf < 4; mf++)
                #pragma unroll
                for (int nf = 0; nf < 4; nf++)
                    mma_tf32(acc[mf][nf], af[mf], bf[nf]);
        }
        __syncthreads();
    }

    float cs[4][2] = {}, cq[4][2] = {};

    #pragma unroll
    for (int mf = 0; mf < 4; mf++) {
        int row0 = m0 + wm0 + mf * 16 + g;
        int row1 = row0 + 8;
        #pragma unroll
        for (int nf = 0; nf < 4; nf++) {
            int n = n0 + wn0 + nf * 8 + 2 * t;
            float b0 = 0.f, b1 = 0.f;
            if (BIAS) { b0 = bias[n]; b1 = bias[n + 1]; }
            float2 v0 = make_float2(acc[mf][nf][0] + b0, acc[mf][nf][1] + b1);
            float2 v1 = make_float2(acc[mf][nf][2] + b0, acc[mf][nf][3] + b1);
            if (RELU) {
                v0.x = fmaxf(v0.x, 0.f); v0.y = fmaxf(v0.y, 0.f);
                v1.x = fmaxf(v1.x, 0.f); v1.y = fmaxf(v1.y, 0.f);
            }
            if (RND) {
                v0.x = tf32r(v0.x); v0.y = tf32r(v0.y);
                v1.x = tf32r(v1.x); v1.y = tf32r(v1.y);
            }
            if (row0 < M) {
                if (ADDST) {
                    v0.x += Xadd[(size_t)row0 * ldc + n];
                    v0.y += Xadd[(size_t)row0 * ldc + n + 1];
                    cs[nf][0] += v0.x; cq[nf][0] += v0.x * v0.x;
                    cs[nf][1] += v0.y; cq[nf][1] += v0.y * v0.y;
                }
                *reinterpret_cast<float2*>(&C[(size_t)row0 * ldc + n]) = v0;
            }
            if (row1 < M) {
                if (ADDST) {
                    v1.x += Xadd[(size_t)row1 * ldc + n];
                    v1.y += Xadd[(size_t)row1 * ldc + n + 1];
                    cs[nf][0] += v1.x; cq[nf][0] += v1.x * v1.x;
                    cs[nf][1] += v1.y; cq[nf][1] += v1.y * v1.y;
                }
                *reinterpret_cast<float2*>(&C[(size_t)row1 * ldc + n]) = v1;
            }
        }
    }

    if (ADDST) {
        #pragma unroll
        for (int nf = 0; nf < 4; nf++)
            #pragma unroll
            for (int c2 = 0; c2 < 2; c2++) {
                float s = cs[nf][c2], q = cq[nf][c2];
                #pragma unroll
                for (int off = 4; off < 32; off <<= 1) {
                    s += __shfl_xor_sync(0xffffffffu, s, off);
                    q += __shfl_xor_sync(0xffffffffu, q, off);
                }
                if (g == 0) {
                    int n = n0 + wn0 + nf * 8 + 2 * t + c2;
                    atomicAdd(&g_stats[(bn * 2 + 0) * DD + n], s);
                    atomicAdd(&g_stats[(bn * 2 + 1) * DD + n], q);
                }
            }
    }
}

// ------- tensor-core tall reduction: C[128, cols] += evc^T[128,N]*B[N,cols] -
#define ATB_BLKS 64
__global__ void __launch_bounds__(256, 2) atb_k(
    const float* __restrict__ evc,
    const float* __restrict__ B, int ldb, long long bTs,
    float* __restrict__ C, int ldc, long long cTs)
{
    extern __shared__ uint32_t dyn[];
    uint32_t (*Es)[32][136] = reinterpret_cast<uint32_t(*)[32][136]>(dyn);
    uint32_t (*Hs)[32][136] = reinterpret_cast<uint32_t(*)[32][136]>(dyn + 2 * 32 * 136);

    B += (long long)blockIdx.z * bTs;
    C += (long long)blockIdx.z * cTs;
    const int noff = blockIdx.y * 128;

    const int chunk = (NN + ATB_BLKS - 1) / ATB_BLKS;
    const int nStart = blockIdx.x * chunk;
    const int nEnd = min(nStart + chunk, NN);
    const int iters = (chunk + 31) / 32;
    const int tid = threadIdx.x;
    const int lane = tid & 31;
    const int wid = tid >> 5;
    const int g = lane >> 2, t = lane & 3;
    const int wm0 = (wid & 1) * 64;
    const int wn0 = (wid >> 1) * 32;

    float acc[4][4][4] = {};

    auto load_tiles = [&](int it, int s) {
        int n0 = nStart + it * 32;
        #pragma unroll
        for (int l = 0; l < 4; l++) {
            int idx = tid + l * 256;
            int r = idx >> 5, c = (idx & 31) * 4;
            bool p = (n0 + r < nEnd);
            int row = p ? (n0 + r) : 0;
            cp16(&Es[s][r][c], &evc[(size_t)row * KK + c], p);
            cp16(&Hs[s][r][c], &B[(size_t)row * ldb + noff + c], p);
        }
    };

    load_tiles(0, 0);
    CP_COMMIT();

    for (int i = 0; i < iters; i++) {
        int cur = i & 1;
        if (i + 1 < iters) { load_tiles(i + 1, cur ^ 1); CP_COMMIT(); CP_WAIT(1); }
        else              { CP_WAIT(0); }
        __syncthreads();
        #pragma unroll
        for (int kk = 0; kk < 4; kk++) {
            uint32_t af[4][4], bf[4][2];
            #pragma unroll
            for (int mf = 0; mf < 4; mf++) {
                int mc = wm0 + mf * 16;
                af[mf][0] = Es[cur][kk * 8 + t    ][mc + g];
                af[mf][1] = Es[cur][kk * 8 + t    ][mc + g + 8];
                af[mf][2] = Es[cur][kk * 8 + t + 4][mc + g];
                af[mf][3] = Es[cur][kk * 8 + t + 4][mc + g + 8];
            }
            #pragma unroll
            for (int nf = 0; nf < 4; nf++) {
                bf[nf][0] = Hs[cur][kk * 8 + t    ][wn0 + nf * 8 + g];
                bf[nf][1] = Hs[cur][kk * 8 + t + 4][wn0 + nf * 8 + g];
            }
            #pragma unroll
            for (int mf = 0; mf < 4; mf++)
                #pragma unroll
                for (int nf = 0; nf < 4; nf++)
                    mma_tf32(acc[mf][nf], af[mf], bf[nf]);
        }
        __syncthreads();
    }

    #pragma unroll
    for (int mf = 0; mf < 4; mf++) {
        int row0 = wm0 + mf * 16 + g;
        #pragma unroll
        for (int nf = 0; nf < 4; nf++) {
            int n = noff + wn0 + nf * 8 + 2 * t;
            float* p0 = &C[(size_t)row0 * ldc + n];
            float* p1 = &C[(size_t)(row0 + 8) * ldc + n];
            asm volatile("red.global.add.v2.f32 [%0], {%1,%2};"
                         :: "l"(p0), "f"(acc[mf][nf][0]), "f"(acc[mf][nf][1]) : "memory");
            asm volatile("red.global.add.v2.f32 [%0], {%1,%2};"
                         :: "l"(p1), "f"(acc[mf][nf][2]), "f"(acc[mf][nf][3]) : "memory");
        }
    }
}

// ---------------- graph kernels ---------------------------------------------
__global__ void deg_k(const void* __restrict__ ei) {
    int e = blockIdx.x * blockDim.x + threadIdx.x;
    if (e < EE) atomicAdd(&g_deg[edge_at(ei, (long long)EE + e)], 1.0f);
}
__global__ void dinv_k() {
    int n = blockIdx.x * blockDim.x + threadIdx.x;
    if (n < NN) g_deg[n] = rsqrtf(g_deg[n] + 1.0f);
}
__global__ void norm_k(const void* __restrict__ ei) {
    int e = blockIdx.x * blockDim.x + threadIdx.x;
    if (e < EE) g_norm[e] = g_deg[edge_at(ei, e)] * g_deg[edge_at(ei, (long long)EE + e)];
}
__global__ void scatter_k(const void* __restrict__ ei) {
    long long idx = (long long)blockIdx.x * blockDim.x + threadIdx.x;
    int e = (int)(idx >> 7);
    int c = ((int)idx & 127) * 4;
    int src = edge_at(ei, e);
    int dst = edge_at(ei, (long long)EE + e);
    float nrm = g_norm[e];
    float4 v = *reinterpret_cast<const float4*>(&g_xw[(size_t)src * DD + c]);
    float* o = &g_bufL[(size_t)dst * DD + c];
    asm volatile("red.global.add.v4.f32 [%0], {%1,%2,%3,%4};"
                 :: "l"(o), "f"(nrm * v.x), "f"(nrm * v.y),
                    "f"(nrm * v.z), "f"(nrm * v.w) : "memory");
}

__global__ void finish_gcn_k(const float* __restrict__ x, const float* __restrict__ gcn_b) {
    const int c = threadIdx.x;
    const int r0 = blockIdx.x * 128;
    const int rEnd = min(r0 + 128, NN);
    const float bc = gcn_b[c];
    float s = 0.f, s2 = 0.f;
    for (int r = r0; r < rEnd; r++) {
        size_t o = (size_t)r * DD + c;
        float dv = g_deg[r];
        float v = x[o] + g_bufL[o] + dv * dv * g_xw[o] + bc;
        g_bufL[o] = v;
        s += v; s2 += v * v;
    }
    atomicAdd(&g_stats[0 * DD + c], s);
    atomicAdd(&g_stats[1 * DD + c], s2);
}

__global__ void finalize_k(int bn, const float* __restrict__ gamma, const float* __restrict__ beta) {
    int c = threadIdx.x;
    float s  = g_stats[(bn * 2 + 0) * DD + c];
    float s2 = g_stats[(bn * 2 + 1) * DD + c];
    float m = s * (1.0f / NN);
    float var = s2 * (1.0f / NN) - m * m;
    float a = gamma[c] * rsqrtf(var + EPSC);
    g_coef[(bn * 2 + 0) * DD + c] = a;
    g_coef[(bn * 2 + 1) * DD + c] = beta[c] - m * a;
}

__global__ void apply_sum_k() {
    int idx = blockIdx.x * blockDim.x + threadIdx.x;
    if (idx >= NN * DD) return;
    int c = idx & (DD - 1);
    g_h[idx] = g_bufL[idx] * g_coef[c] + g_coef[DD + c]
             + g_bufA[idx] * g_coef[2 * DD + c] + g_coef[3 * DD + c];
}
__global__ void bn2_apply_k(float* __restrict__ out) {
    int idx = blockIdx.x * blockDim.x + threadIdx.x;
    if (idx >= NN * DD) return;
    int c = idx & (DD - 1);
    out[idx] = g_ff[idx] * g_coef[4 * DD + c] + g_coef[5 * DD + c];
}

// ---------------- wave helpers ----------------------------------------------
__global__ void pack_w_k(const float* __restrict__ gcnW, const float* __restrict__ linW) {
    int idx = blockIdx.x * blockDim.x + threadIdx.x;
    if (idx >= DD * DD) return;
    int d = idx >> 9, j = idx & 511;
    int t = j >> 7, s = j & 127;
    g_gWt[idx]   = tf32r(gcnW[idx]);
    g_linWp[idx] = tf32r(linW[t * (DD * SSc) + d * SSc + s]);
}
__global__ void post_u_k(const float* __restrict__ fs, const float* __restrict__ linB) {
    int idx = blockIdx.x * blockDim.x + threadIdx.x;
    if (idx >= KK * DD) return;
    int k = idx >> 9, j = idx & 511;
    int t = j >> 7, s = j & 127;
    g_u[idx] = tf32r(fs[k * TJc + t] * (g_uraw[idx] + g_esum[k] * linB[t * SSc + s]));
}
__global__ void scale_u2_k(const float* __restrict__ fs) {
    int idx = blockIdx.x * blockDim.x + threadIdx.x;
    if (idx >= KK * DD) return;
    int k = idx >> 9, t = (idx & 511) >> 7;
    g_u2[idx] = tf32r(g_u2[idx] * fs[k * TJc + t]);
}

// ---------------- launch -----------------------------------------------------
#define GSYM(p, s) do { void* _t; cudaGetSymbolAddress(&_t, s); (p) = (float*)_t; } while (0)

extern "C" void kernel_launch(void* const* d_in, const int* in_sizes, int n_in,
                              void* d_out, int out_size) {
    const float* x        = (const float*)d_in[0];
    const void*  ei       = d_in[1];
    const float* evc      = (const float*)d_in[2];
    const float* fs       = (const float*)d_in[3];
    const float* gcn_W    = (const float*)d_in[4];
    const float* gcn_b    = (const float*)d_in[5];
    const float* lin_W    = (const float*)d_in[6];
    const float* lin_b    = (const float*)d_in[7];
    const float* fusion_W = (const float*)d_in[8];
    const float* fusion_b = (const float*)d_in[9];
    const float* bn1l_g   = (const float*)d_in[10];
    const float* bn1l_b   = (const float*)d_in[11];
    const float* bn1a_g   = (const float*)d_in[12];
    const float* bn1a_b   = (const float*)d_in[13];
    const float* bn2_g    = (const float*)d_in[14];
    const float* bn2_b    = (const float*)d_in[15];
    const float* ff1_W    = (const float*)d_in[16];
    const float* ff1_b    = (const float*)d_in[17];
    const float* ff2_W    = (const float*)d_in[18];
    const float* ff2_b    = (const float*)d_in[19];
    float* out = (float*)d_out;

    float *p_xw, *p_bufL, *p_v, *p_bufA, *p_h, *p_mid, *p_ff;
    float *p_xt, *p_evct, *p_xe, *p_uraw, *p_u, *p_u2, *p_W2;
    float *p_gWt, *p_linWp, *p_fWt, *p_f1Wt, *p_f2Wt;
    GSYM(p_xw, g_xw);     GSYM(p_bufL, g_bufL); GSYM(p_v, g_v);
    GSYM(p_bufA, g_bufA); GSYM(p_h, g_h);       GSYM(p_mid, g_mid);
    GSYM(p_ff, g_ff);     GSYM(p_xt, g_xt);     GSYM(p_evct, g_evct);
    GSYM(p_xe, g_xe);     GSYM(p_uraw, g_uraw); GSYM(p_u, g_u);
    GSYM(p_u2, g_u2);     GSYM(p_W2, g_W2);     GSYM(p_gWt, g_gWt);
    GSYM(p_linWp, g_linWp); GSYM(p_fWt, g_fWt); GSYM(p_f1Wt, g_f1Wt);
    GSYM(p_f2Wt, g_f2Wt);

    const int GEMM_SMEM = (2 * 128 * 36 + 2 * 32 * 136) * 4;
    const int ATB_SMEM  = (2 * 32 * 136 * 2) * 4;
    cudaFuncSetAttribute(tcgemm_k<false, false, false, false, false>, cudaFuncAttributeMaxDynamicSharedMemorySize, GEMM_SMEM);
    cudaFuncSetAttribute(tcgemm_k<false, false, true,  false, false>, cudaFuncAttributeMaxDynamicSharedMemorySize, GEMM_SMEM);
    cudaFuncSetAttribute(tcgemm_k<false, true,  true,  false, false>, cudaFuncAttributeMaxDynamicSharedMemorySize, GEMM_SMEM);
    cudaFuncSetAttribute(tcgemm_k<true,  true,  false, false, true >, cudaFuncAttributeMaxDynamicSharedMemorySize, GEMM_SMEM);
    cudaFuncSetAttribute(tcgemm_k<true,  true,  true,  true,  false>, cudaFuncAttributeMaxDynamicSharedMemorySize, GEMM_SMEM);
    cudaFuncSetAttribute(tcgemm_k<true,  false, false, false, true >, cudaFuncAttributeMaxDynamicSharedMemorySize, GEMM_SMEM);
    cudaFuncSetAttribute(atb_k, cudaFuncAttributeMaxDynamicSharedMemorySize, ATB_SMEM);

    const int MB = (NN + 127) / 128;
    dim3 gD(4, MB);
    dim3 gF(8, MB);
    dim3 gV(1, MB, TJc);
    dim3 gTiny(4, 1);
    dim3 gAtbX(ATB_BLKS, 4, 1);
    dim3 gAtbU(ATB_BLKS, 1, TJc);

    detect_k<<<1, 256>>>((const int*)ei);
    zero_scratch_k<<<2048, 256>>>();
    pack_w_k<<<(DD * DD + 255) / 256, 256>>>(gcn_W, lin_W);
    round_k<<<1024, 256>>>(x, p_xt, (long long)NN * DD);
    round_k<<<256, 256>>>(evc, p_evct, (long long)NN * KK);
    round_k<<<128, 256>>>(fusion_W, p_fWt, DD * DD);
    round_k<<<256, 256>>>(ff1_W, p_f1Wt, DD * DD2);
    round_k<<<256, 256>>>(ff2_W, p_f2Wt, DD2 * DD);

    // ---- GCN branch ----
    tcgemm_k<false, false, false, false, false><<<gD, 256, GEMM_SMEM>>>(
        p_xt, DD, p_gWt, DD, 0, p_xw, DD, 0, nullptr, NN, DD, nullptr, 0);
    deg_k<<<(EE + 255) / 256, 256>>>(ei);
    dinv_k<<<(NN + 255) / 256, 256>>>();
    norm_k<<<(EE + 255) / 256, 256>>>(ei);
    scatter_k<<<(EE * 128) / 256, 256>>>(ei);
    finish_gcn_k<<<MB, DD>>>(x, gcn_b);

    // ---- Wave branch (factored through K=128) ----
    colsum_k<<<(NN + 499) / 500, KK>>>(evc);
    atb_k<<<gAtbX, 256, ATB_SMEM>>>(p_evct, p_xt, DD, 0, p_xe, DD, 0);
    round_k<<<64, 256>>>(p_xe, p_xe, KK * DD);
    tcgemm_k<false, false, false, false, false><<<gTiny, 256, GEMM_SMEM>>>(
        p_xe, DD, p_linWp, DD, 0, p_uraw, DD, 0, nullptr, KK, DD, nullptr, 0);
    post_u_k<<<(KK * DD + 255) / 256, 256>>>(fs, lin_b);
    tcgemm_k<false, true, true, false, false><<<gV, 256, GEMM_SMEM>>>(
        p_evct, KK, p_u, DD, 128, p_v, SSc, (long long)NN * SSc, nullptr, NN, KK, nullptr, 0);
    atb_k<<<gAtbU, 256, ATB_SMEM>>>(p_evct, p_v, SSc, (long long)NN * SSc, p_u2, DD, 128);
    scale_u2_k<<<(KK * DD + 255) / 256, 256>>>(fs);
    tcgemm_k<false, false, true, false, false><<<gTiny, 256, GEMM_SMEM>>>(
        p_u2, DD, p_fWt, DD, 0, p_W2, DD, 0, nullptr, KK, DD, nullptr, 0);
    // bufA = x + relu(evc@W2 + fusion_b), fused BN1a stats
    tcgemm_k<true, true, false, false, true><<<gD, 256, GEMM_SMEM>>>(
        p_evct, KK, p_W2, DD, 0, p_bufA, DD, 0, fusion_b, NN, KK, x, 1);

    // ---- combine + BN ----
    finalize_k<<<1, DD>>>(0, bn1l_g, bn1l_b);
    finalize_k<<<1, DD>>>(1, bn1a_g, bn1a_b);
    apply_sum_k<<<(NN * DD + 255) / 256, 256>>>();

    // ---- feed-forward ----
    tcgemm_k<true, true, true, true, false><<<gF, 256, GEMM_SMEM>>>(
        p_h, DD, p_f1Wt, DD2, 0, p_mid, DD2, 0, ff1_b, NN, DD, nullptr, 0);
    // ff = h + (mid@ff2_W + ff2_b), fused BN2 stats
    tcgemm_k<true, false, false, false, true><<<gD, 256, GEMM_SMEM>>>(
        p_mid, DD2, p_f2Wt, DD, 0, p_ff, DD, 0, ff2_b, NN, DD2, p_h, 2);
    finalize_k<<<1, DD>>>(2, bn2_g, bn2_b);
    bn2_apply_k<<<(NN * DD + 255) / 256, 256>>>(out);
}

// round 8
// speedup vs baseline: 4.1582x; 1.2041x over previous
#include <cuda_runtime.h>
#include <cstdint>

#define NN  50000
#define EE  800000
#define DD  512
#define KK  128
#define TJc 4
#define SSc 128
#define DD2 1024
#define EPSC 1e-5f

// ---------------- scratch (device globals) -----------------------------------
__device__ float g_xw  [(size_t)NN * DD];        // x @ gcn_W
__device__ float g_bufL[(size_t)NN * DD];
__device__ float g_v   [(size_t)TJc * NN * SSc];
__device__ float g_bufA[(size_t)NN * DD];
__device__ float g_h   [(size_t)NN * DD];
__device__ float g_mid [(size_t)NN * DD2];
__device__ float g_ff  [(size_t)NN * DD];
__device__ float g_xt  [(size_t)NN * DD];        // tf32 x
__device__ float g_evct[(size_t)NN * KK];        // tf32 evc
__device__ float g_deg [NN];                     // dinv
__device__ int   g_degi[NN];
__device__ int   g_off [NN + 1];
__device__ int   g_cur [NN];
__device__ int   g_csrc[EE];
__device__ float g_esum[KK];
__device__ float g_xe  [KK * DD];
__device__ float g_uraw[KK * DD];
__device__ float g_u   [KK * DD];
__device__ float g_u2  [KK * DD];
__device__ float g_W2  [KK * DD];
__device__ float g_stats[6 * DD];
__device__ float g_coef [6 * DD];
__device__ float g_gWt  [DD * DD];
__device__ float g_linWp[DD * DD];
__device__ float g_fWt  [DD * DD];
__device__ float g_f1Wt [DD * DD2];
__device__ float g_f2Wt [DD2 * DD];
__device__ int   g_is64;

// ---------------- helpers -----------------------------------------------------
__device__ __forceinline__ float tf32r(float f) {
    uint32_t u; asm("cvt.rna.tf32.f32 %0, %1;" : "=r"(u) : "f"(f));
    return __uint_as_float(u);
}
__device__ __forceinline__ uint32_t cvt_rna(uint32_t x) {
    uint32_t u; float f = __uint_as_float(x);
    asm("cvt.rna.tf32.f32 %0, %1;" : "=r"(u) : "f"(f)); return u;
}
__device__ __forceinline__ void mma_tf32(float* c, const uint32_t* a, const uint32_t* b) {
    asm volatile("mma.sync.aligned.m16n8k8.row.col.f32.tf32.tf32.f32 "
        "{%0,%1,%2,%3}, {%4,%5,%6,%7}, {%8,%9}, {%0,%1,%2,%3};"
        : "+f"(c[0]), "+f"(c[1]), "+f"(c[2]), "+f"(c[3])
        : "r"(a[0]), "r"(a[1]), "r"(a[2]), "r"(a[3]), "r"(b[0]), "r"(b[1]));
}
__device__ __forceinline__ void cp16(void* sdst, const void* gsrc, bool pred) {
    uint32_t sa = (uint32_t)__cvta_generic_to_shared(sdst);
    int sz = pred ? 16 : 0;
    asm volatile("cp.async.cg.shared.global [%0], [%1], 16, %2;"
                 :: "r"(sa), "l"(gsrc), "r"(sz));
}
#define CP_COMMIT() asm volatile("cp.async.commit_group;")
#define CP_WAIT(n)  asm volatile("cp.async.wait_group %0;" :: "n"(n))

// ---------------- edge-index dtype detection --------------------------------
__global__ void detect_k(const int* __restrict__ ei32) {
    __shared__ int any;
    if (threadIdx.x == 0) any = 0;
    __syncthreads();
    int v = 0;
    for (int i = threadIdx.x; i < 1024; i += blockDim.x)
        v |= ei32[2 * i + 1];
    if (v) atomicOr(&any, 1);
    __syncthreads();
    if (threadIdx.x == 0) g_is64 = (any == 0) ? 1 : 0;
}
__device__ __forceinline__ int edge_at(const void* ei, long long pos) {
    return g_is64 ? (int)((const long long*)ei)[pos] : ((const int*)ei)[pos];
}

// ---------------- zero / round helpers ---------------------------------------
__global__ void zero_scratch_k() {
    int stride = gridDim.x * blockDim.x;
    int i0 = blockIdx.x * blockDim.x + threadIdx.x;
    for (int i = i0; i < NN; i += stride) g_degi[i] = 0;
    for (int i = i0; i < KK * DD; i += stride) { g_xe[i] = 0.f; g_u2[i] = 0.f; }
    for (int i = i0; i < 6 * DD; i += stride) g_stats[i] = 0.f;
    for (int i = i0; i < KK; i += stride) g_esum[i] = 0.f;
}
__global__ void round_k(const float* __restrict__ in, float* __restrict__ o, long long n) {
    long long i = (long long)blockIdx.x * blockDim.x + threadIdx.x;
    long long stride = (long long)gridDim.x * blockDim.x;
    for (; i < n / 4; i += stride) {
        float4 v = reinterpret_cast<const float4*>(in)[i];
        v.x = tf32r(v.x); v.y = tf32r(v.y); v.z = tf32r(v.z); v.w = tf32r(v.w);
        reinterpret_cast<float4*>(o)[i] = v;
    }
}
__global__ void colsum_k(const float* __restrict__ evc) {
    int c = threadIdx.x;
    int r0 = blockIdx.x * 500;
    int r1 = min(r0 + 500, NN);
    float s = 0.f;
    for (int r = r0; r < r1; r++) s += evc[(size_t)r * KK + c];
    atomicAdd(&g_esum[c], s);
}

// ---------------- pipelined TF32 GEMM ----------------------------------------
template <bool BIAS, bool RELU, bool RND, bool CVTA, bool ADDST>
__global__ void __launch_bounds__(256, 2) tcgemm_k(
    const float* __restrict__ A, int lda,
    const float* __restrict__ B, int ldb, long long bTs,
    float* __restrict__ C, int ldc, long long cTs,
    const float* __restrict__ bias,
    int M, int Kd,
    const float* __restrict__ Xadd, int bn)
{
    extern __shared__ uint32_t dyn[];
    uint32_t (*As)[128][36]  = reinterpret_cast<uint32_t(*)[128][36]>(dyn);
    uint32_t (*Bs)[32][136]  = reinterpret_cast<uint32_t(*)[32][136]>(dyn + 2 * 128 * 36);

    B += (long long)blockIdx.z * bTs;
    C += (long long)blockIdx.z * cTs;

    const int m0 = blockIdx.y * 128;
    const int n0 = blockIdx.x * 128;
    const int tid = threadIdx.x;
    const int lane = tid & 31;
    const int wid = tid >> 5;
    const int g = lane >> 2, t = lane & 3;
    const int wm0 = (wid & 1) * 64;
    const int wn0 = (wid >> 1) * 32;

    float acc[4][4][4] = {};
    const int T = Kd >> 5;

    auto load_tiles = [&](int it, int s) {
        int k0 = it * 32;
        #pragma unroll
        for (int l = 0; l < 4; l++) {
            int idx = tid + l * 256;
            int r = idx >> 3, c = (idx & 7) * 4;
            bool p = (m0 + r < M);
            int row = p ? (m0 + r) : 0;
            cp16(&As[s][r][c], &A[(size_t)row * lda + k0 + c], p);
        }
        #pragma unroll
        for (int l = 0; l < 4; l++) {
            int idx = tid + l * 256;
            int r = idx >> 5, c = (idx & 31) * 4;
            cp16(&Bs[s][r][c], &B[(size_t)(k0 + r) * ldb + n0 + c], true);
        }
    };

    load_tiles(0, 0);
    CP_COMMIT();

    for (int i = 0; i < T; i++) {
        int cur = i & 1;
        if (i + 1 < T) { load_tiles(i + 1, cur ^ 1); CP_COMMIT(); CP_WAIT(1); }
        else          { CP_WAIT(0); }
        __syncthreads();
        #pragma unroll
        for (int kk = 0; kk < 4; kk++) {
            uint32_t af[4][4], bf[4][2];
            #pragma unroll
            for (int mf = 0; mf < 4; mf++) {
                int mr = wm0 + mf * 16;
                uint32_t a0 = As[cur][mr + g    ][kk * 8 + t];
                uint32_t a1 = As[cur][mr + g + 8][kk * 8 + t];
                uint32_t a2 = As[cur][mr + g    ][kk * 8 + t + 4];
                uint32_t a3 = As[cur][mr + g + 8][kk * 8 + t + 4];
                if (CVTA) { a0 = cvt_rna(a0); a1 = cvt_rna(a1); a2 = cvt_rna(a2); a3 = cvt_rna(a3); }
                af[mf][0] = a0; af[mf][1] = a1; af[mf][2] = a2; af[mf][3] = a3;
            }
            #pragma unroll
            for (int nf = 0; nf < 4; nf++) {
                bf[nf][0] = Bs[cur][kk * 8 + t    ][wn0 + nf * 8 + g];
                bf[nf][1] = Bs[cur][kk * 8 + t + 4][wn0 + nf * 8 + g];
            }
            #pragma unroll
            for (int mf = 0; mf < 4; mf++)
                #pragma unroll
                for (int nf = 0; nf < 4; nf++)
                    mma_tf32(acc[mf][nf], af[mf], bf[nf]);
        }
        __syncthreads();
    }

    float cs[4][2] = {}, cq[4][2] = {};

    #pragma unroll
    for (int mf = 0; mf < 4; mf++) {
        int row0 = m0 + wm0 + mf * 16 + g;
        int row1 = row0 + 8;
        #pragma unroll
        for (int nf = 0; nf < 4; nf++) {
            int n = n0 + wn0 + nf * 8 + 2 * t;
            float b0 = 0.f, b1 = 0.f;
            if (BIAS) { b0 = bias[n]; b1 = bias[n + 1]; }
            float2 v0 = make_float2(acc[mf][nf][0] + b0, acc[mf][nf][1] + b1);
            float2 v1 = make_float2(acc[mf][nf][2] + b0, acc[mf][nf][3] + b1);
            if (RELU) {
                v0.x = fmaxf(v0.x, 0.f); v0.y = fmaxf(v0.y, 0.f);
                v1.x = fmaxf(v1.x, 0.f); v1.y = fmaxf(v1.y, 0.f);
            }
            if (RND) {
                v0.x = tf32r(v0.x); v0.y = tf32r(v0.y);
                v1.x = tf32r(v1.x); v1.y = tf32r(v1.y);
            }
            if (row0 < M) {
                if (ADDST) {
                    v0.x += Xadd[(size_t)row0 * ldc + n];
                    v0.y += Xadd[(size_t)row0 * ldc + n + 1];
                    cs[nf][0] += v0.x; cq[nf][0] += v0.x * v0.x;
                    cs[nf][1] += v0.y; cq[nf][1] += v0.y * v0.y;
                }
                *reinterpret_cast<float2*>(&C[(size_t)row0 * ldc + n]) = v0;
            }
            if (row1 < M) {
                if (ADDST) {
                    v1.x += Xadd[(size_t)row1 * ldc + n];
                    v1.y += Xadd[(size_t)row1 * ldc + n + 1];
                    cs[nf][0] += v1.x; cq[nf][0] += v1.x * v1.x;
                    cs[nf][1] += v1.y; cq[nf][1] += v1.y * v1.y;
                }
                *reinterpret_cast<float2*>(&C[(size_t)row1 * ldc + n]) = v1;
            }
        }
    }

    if (ADDST) {
        #pragma unroll
        for (int nf = 0; nf < 4; nf++)
            #pragma unroll
            for (int c2 = 0; c2 < 2; c2++) {
                float s = cs[nf][c2], q = cq[nf][c2];
                #pragma unroll
                for (int off = 4; off < 32; off <<= 1) {
                    s += __shfl_xor_sync(0xffffffffu, s, off);
                    q += __shfl_xor_sync(0xffffffffu, q, off);
                }
                if (g == 0) {
                    int n = n0 + wn0 + nf * 8 + 2 * t + c2;
                    atomicAdd(&g_stats[(bn * 2 + 0) * DD + n], s);
                    atomicAdd(&g_stats[(bn * 2 + 1) * DD + n], q);
                }
            }
    }
}

// ------- tensor-core tall reduction: C[128, cols] += evc^T[128,N]*B[N,cols] -
#define ATB_BLKS 64
__global__ void __launch_bounds__(256, 2) atb_k(
    const float* __restrict__ evc,
    const float* __restrict__ B, int ldb, long long bTs,
    float* __restrict__ C, int ldc, long long cTs)
{
    extern __shared__ uint32_t dyn[];
    uint32_t (*Es)[32][136] = reinterpret_cast<uint32_t(*)[32][136]>(dyn);
    uint32_t (*Hs)[32][136] = reinterpret_cast<uint32_t(*)[32][136]>(dyn + 2 * 32 * 136);

    B += (long long)blockIdx.z * bTs;
    C += (long long)blockIdx.z * cTs;
    const int noff = blockIdx.y * 128;

    const int chunk = (NN + ATB_BLKS - 1) / ATB_BLKS;
    const int nStart = blockIdx.x * chunk;
    const int nEnd = min(nStart + chunk, NN);
    const int iters = (chunk + 31) / 32;
    const int tid = threadIdx.x;
    const int lane = tid & 31;
    const int wid = tid >> 5;
    const int g = lane >> 2, t = lane & 3;
    const int wm0 = (wid & 1) * 64;
    const int wn0 = (wid >> 1) * 32;

    float acc[4][4][4] = {};

    auto load_tiles = [&](int it, int s) {
        int n0 = nStart + it * 32;
        #pragma unroll
        for (int l = 0; l < 4; l++) {
            int idx = tid + l * 256;
            int r = idx >> 5, c = (idx & 31) * 4;
            bool p = (n0 + r < nEnd);
            int row = p ? (n0 + r) : 0;
            cp16(&Es[s][r][c], &evc[(size_t)row * KK + c], p);
            cp16(&Hs[s][r][c], &B[(size_t)row * ldb + noff + c], p);
        }
    };

    load_tiles(0, 0);
    CP_COMMIT();

    for (int i = 0; i < iters; i++) {
        int cur = i & 1;
        if (i + 1 < iters) { load_tiles(i + 1, cur ^ 1); CP_COMMIT(); CP_WAIT(1); }
        else              { CP_WAIT(0); }
        __syncthreads();
        #pragma unroll
        for (int kk = 0; kk < 4; kk++) {
            uint32_t af[4][4], bf[4][2];
            #pragma unroll
            for (int mf = 0; mf < 4; mf++) {
                int mc = wm0 + mf * 16;
                af[mf][0] = Es[cur][kk * 8 + t    ][mc + g];
                af[mf][1] = Es[cur][kk * 8 + t    ][mc + g + 8];
                af[mf][2] = Es[cur][kk * 8 + t + 4][mc + g];
                af[mf][3] = Es[cur][kk * 8 + t + 4][mc + g + 8];
            }
            #pragma unroll
            for (int nf = 0; nf < 4; nf++) {
                bf[nf][0] = Hs[cur][kk * 8 + t    ][wn0 + nf * 8 + g];
                bf[nf][1] = Hs[cur][kk * 8 + t + 4][wn0 + nf * 8 + g];
            }
            #pragma unroll
            for (int mf = 0; mf < 4; mf++)
                #pragma unroll
                for (int nf = 0; nf < 4; nf++)
                    mma_tf32(acc[mf][nf], af[mf], bf[nf]);
        }
        __syncthreads();
    }

    #pragma unroll
    for (int mf = 0; mf < 4; mf++) {
        int row0 = wm0 + mf * 16 + g;
        #pragma unroll
        for (int nf = 0; nf < 4; nf++) {
            int n = noff + wn0 + nf * 8 + 2 * t;
            float* p0 = &C[(size_t)row0 * ldc + n];
            float* p1 = &C[(size_t)(row0 + 8) * ldc + n];
            asm volatile("red.global.add.v2.f32 [%0], {%1,%2};"
                         :: "l"(p0), "f"(acc[mf][nf][0]), "f"(acc[mf][nf][1]) : "memory");
            asm volatile("red.global.add.v2.f32 [%0], {%1,%2};"
                         :: "l"(p1), "f"(acc[mf][nf][2]), "f"(acc[mf][nf][3]) : "memory");
        }
    }
}

// ---------------- graph: CSR build + gather ----------------------------------
__global__ void degi_k(const void* __restrict__ ei) {
    int e = blockIdx.x * blockDim.x + threadIdx.x;
    if (e < EE) atomicAdd(&g_degi[edge_at(ei, (long long)EE + e)], 1);
}
__global__ void dinv_k() {
    int n = blockIdx.x * blockDim.x + threadIdx.x;
    if (n < NN) g_deg[n] = rsqrtf((float)g_degi[n] + 1.0f);
}
// exclusive scan of g_degi -> g_off / g_cur  (one block, 1024 threads)
__global__ void scan_k() {
    __shared__ int s[1024];
    int tid = threadIdx.x;
    const int per = (NN + 1023) / 1024;        // 49
    int start = tid * per, end = min(start + per, NN);
    int sum = 0;
    for (int i = start; i < end; i++) sum += g_degi[i];
    s[tid] = sum;
    __syncthreads();
    for (int off = 1; off < 1024; off <<= 1) {
        int v = 0;
        if (tid >= off) v = s[tid - off];
        __syncthreads();
        if (tid >= off) s[tid] += v;
        __syncthreads();
    }
    int base = s[tid] - sum;                   // exclusive
    for (int i = start; i < end; i++) {
        g_off[i] = base; g_cur[i] = base;
        base += g_degi[i];
    }
    if (tid == 1023) g_off[NN] = base;
}
__global__ void fill_k(const void* __restrict__ ei) {
    int e = blockIdx.x * blockDim.x + threadIdx.x;
    if (e >= EE) return;
    int src = edge_at(ei, e);
    int dst = edge_at(ei, (long long)EE + e);
    int pos = atomicAdd(&g_cur[dst], 1);
    g_csrc[pos] = src;
}
// bufL[n] = x[n] + sum_e nrm*xw[src] + dinv^2*xw[n] + gcn_b   (one block per node)
__global__ void __launch_bounds__(128) gather_k(const float* __restrict__ x,
                                                const float* __restrict__ gcn_b) {
    const int n = blockIdx.x;
    const int c = threadIdx.x * 4;
    const int s0 = g_off[n], s1 = g_off[n + 1];
    const float dv = g_deg[n];
    float4 acc = make_float4(0.f, 0.f, 0.f, 0.f);
    int e = s0;
    #pragma unroll 1
    for (; e + 2 <= s1; e += 2) {
        int srcA = g_csrc[e], srcB = g_csrc[e + 1];
        float nA = dv * g_deg[srcA], nB = dv * g_deg[srcB];
        float4 vA = *reinterpret_cast<const float4*>(&g_xw[(size_t)srcA * DD + c]);
        float4 vB = *reinterpret_cast<const float4*>(&g_xw[(size_t)srcB * DD + c]);
        acc.x += nA * vA.x + nB * vB.x;
        acc.y += nA * vA.y + nB * vB.y;
        acc.z += nA * vA.z + nB * vB.z;
        acc.w += nA * vA.w + nB * vB.w;
    }
    if (e < s1) {
        int src = g_csrc[e];
        float nrm = dv * g_deg[src];
        float4 v = *reinterpret_cast<const float4*>(&g_xw[(size_t)src * DD + c]);
        acc.x += nrm * v.x; acc.y += nrm * v.y; acc.z += nrm * v.z; acc.w += nrm * v.w;
    }
    float4 xw = *reinterpret_cast<const float4*>(&g_xw[(size_t)n * DD + c]);
    float4 xr = *reinterpret_cast<const float4*>(&x[(size_t)n * DD + c]);
    float4 bb = *reinterpret_cast<const float4*>(&gcn_b[c]);
    float d2 = dv * dv;
    float4 o;
    o.x = xr.x + acc.x + d2 * xw.x + bb.x;
    o.y = xr.y + acc.y + d2 * xw.y + bb.y;
    o.z = xr.z + acc.z + d2 * xw.z + bb.z;
    o.w = xr.w + acc.w + d2 * xw.w + bb.w;
    *reinterpret_cast<float4*>(&g_bufL[(size_t)n * DD + c]) = o;
}
// BN0 stats over bufL
__global__ void stats0_k() {
    const int c = threadIdx.x;
    const int r0 = blockIdx.x * 128;
    const int rEnd = min(r0 + 128, NN);
    float s = 0.f, s2 = 0.f;
    for (int r = r0; r < rEnd; r++) {
        float v = g_bufL[(size_t)r * DD + c];
        s += v; s2 += v * v;
    }
    atomicAdd(&g_stats[0 * DD + c], s);
    atomicAdd(&g_stats[1 * DD + c], s2);
}

__global__ void finalize_k(int bn, const float* __restrict__ gamma, const float* __restrict__ beta) {
    int c = threadIdx.x;
    float s  = g_stats[(bn * 2 + 0) * DD + c];
    float s2 = g_stats[(bn * 2 + 1) * DD + c];
    float m = s * (1.0f / NN);
    float var = s2 * (1.0f / NN) - m * m;
    float a = gamma[c] * rsqrtf(var + EPSC);
    g_coef[(bn * 2 + 0) * DD + c] = a;
    g_coef[(bn * 2 + 1) * DD + c] = beta[c] - m * a;
}

__global__ void apply_sum_k() {
    int idx = blockIdx.x * blockDim.x + threadIdx.x;
    if (idx >= NN * DD) return;
    int c = idx & (DD - 1);
    g_h[idx] = g_bufL[idx] * g_coef[c] + g_coef[DD + c]
             + g_bufA[idx] * g_coef[2 * DD + c] + g_coef[3 * DD + c];
}
__global__ void bn2_apply_k(float* __restrict__ out) {
    int idx = blockIdx.x * blockDim.x + threadIdx.x;
    if (idx >= NN * DD) return;
    int c = idx & (DD - 1);
    out[idx] = g_ff[idx] * g_coef[4 * DD + c] + g_coef[5 * DD + c];
}

// ---------------- wave helpers ----------------------------------------------
__global__ void pack_w_k(const float* __restrict__ gcnW, const float* __restrict__ linW) {
    int idx = blockIdx.x * blockDim.x + threadIdx.x;
    if (idx >= DD * DD) return;
    int d = idx >> 9, j = idx & 511;
    int t = j >> 7, s = j & 127;
    g_gWt[idx]   = tf32r(gcnW[idx]);
    g_linWp[idx] = tf32r(linW[t * (DD * SSc) + d * SSc + s]);
}
__global__ void post_u_k(const float* __restrict__ fs, const float* __restrict__ linB) {
    int idx = blockIdx.x * blockDim.x + threadIdx.x;
    if (idx >= KK * DD) return;
    int k = idx >> 9, j = idx & 511;
    int t = j >> 7, s = j & 127;
    g_u[idx] = tf32r(fs[k * TJc + t] * (g_uraw[idx] + g_esum[k] * linB[t * SSc + s]));
}
__global__ void scale_u2_k(const float* __restrict__ fs) {
    int idx = blockIdx.x * blockDim.x + threadIdx.x;
    if (idx >= KK * DD) return;
    int k = idx >> 9, t = (idx & 511) >> 7;
    g_u2[idx] = tf32r(g_u2[idx] * fs[k * TJc + t]);
}

// ---------------- launch -----------------------------------------------------
#define GSYM(p, s) do { void* _t; cudaGetSymbolAddress(&_t, s); (p) = (float*)_t; } while (0)

extern "C" void kernel_launch(void* const* d_in, const int* in_sizes, int n_in,
                              void* d_out, int out_size) {
    const float* x        = (const float*)d_in[0];
    const void*  ei       = d_in[1];
    const float* evc      = (const float*)d_in[2];
    const float* fs       = (const float*)d_in[3];
    const float* gcn_W    = (const float*)d_in[4];
    const float* gcn_b    = (const float*)d_in[5];
    const float* lin_W    = (const float*)d_in[6];
    const float* lin_b    = (const float*)d_in[7];
    const float* fusion_W = (const float*)d_in[8];
    const float* fusion_b = (const float*)d_in[9];
    const float* bn1l_g   = (const float*)d_in[10];
    const float* bn1l_b   = (const float*)d_in[11];
    const float* bn1a_g   = (const float*)d_in[12];
    const float* bn1a_b   = (const float*)d_in[13];
    const float* bn2_g    = (const float*)d_in[14];
    const float* bn2_b    = (const float*)d_in[15];
    const float* ff1_W    = (const float*)d_in[16];
    const float* ff1_b    = (const float*)d_in[17];
    const float* ff2_W    = (const float*)d_in[18];
    const float* ff2_b    = (const float*)d_in[19];
    float* out = (float*)d_out;

    float *p_xw, *p_bufL, *p_v, *p_bufA, *p_h, *p_mid, *p_ff;
    float *p_xt, *p_evct, *p_xe, *p_uraw, *p_u, *p_u2, *p_W2;
    float *p_gWt, *p_linWp, *p_fWt, *p_f1Wt, *p_f2Wt;
    GSYM(p_xw, g_xw);     GSYM(p_bufL, g_bufL); GSYM(p_v, g_v);
    GSYM(p_bufA, g_bufA); GSYM(p_h, g_h);       GSYM(p_mid, g_mid);
    GSYM(p_ff, g_ff);     GSYM(p_xt, g_xt);     GSYM(p_evct, g_evct);
    GSYM(p_xe, g_xe);     GSYM(p_uraw, g_uraw); GSYM(p_u, g_u);
    GSYM(p_u2, g_u2);     GSYM(p_W2, g_W2);     GSYM(p_gWt, g_gWt);
    GSYM(p_linWp, g_linWp); GSYM(p_fWt, g_fWt); GSYM(p_f1Wt, g_f1Wt);
    GSYM(p_f2Wt, g_f2Wt);

    const int GEMM_SMEM = (2 * 128 * 36 + 2 * 32 * 136) * 4;
    const int ATB_SMEM  = (2 * 32 * 136 * 2) * 4;
    cudaFuncSetAttribute(tcgemm_k<false, false, false, false, false>, cudaFuncAttributeMaxDynamicSharedMemorySize, GEMM_SMEM);
    cudaFuncSetAttribute(tcgemm_k<false, false, true,  false, false>, cudaFuncAttributeMaxDynamicSharedMemorySize, GEMM_SMEM);
    cudaFuncSetAttribute(tcgemm_k<false, true,  true,  false, false>, cudaFuncAttributeMaxDynamicSharedMemorySize, GEMM_SMEM);
    cudaFuncSetAttribute(tcgemm_k<true,  true,  false, false, true >, cudaFuncAttributeMaxDynamicSharedMemorySize, GEMM_SMEM);
    cudaFuncSetAttribute(tcgemm_k<true,  true,  true,  true,  false>, cudaFuncAttributeMaxDynamicSharedMemorySize, GEMM_SMEM);
    cudaFuncSetAttribute(tcgemm_k<true,  false, false, false, true >, cudaFuncAttributeMaxDynamicSharedMemorySize, GEMM_SMEM);
    cudaFuncSetAttribute(atb_k, cudaFuncAttributeMaxDynamicSharedMemorySize, ATB_SMEM);

    const int MB = (NN + 127) / 128;
    dim3 gD(4, MB);
    dim3 gF(8, MB);
    dim3 gV(1, MB, TJc);
    dim3 gTiny(4, 1);
    dim3 gAtbX(ATB_BLKS, 4, 1);
    dim3 gAtbU(ATB_BLKS, 1, TJc);

    detect_k<<<1, 256>>>((const int*)ei);
    zero_scratch_k<<<2048, 256>>>();
    pack_w_k<<<(DD * DD + 255) / 256, 256>>>(gcn_W, lin_W);
    round_k<<<1024, 256>>>(x, p_xt, (long long)NN * DD);
    round_k<<<256, 256>>>(evc, p_evct, (long long)NN * KK);
    round_k<<<128, 256>>>(fusion_W, p_fWt, DD * DD);
    round_k<<<256, 256>>>(ff1_W, p_f1Wt, DD * DD2);
    round_k<<<256, 256>>>(ff2_W, p_f2Wt, DD2 * DD);

    // ---- GCN branch: CSR build runs alongside the xw GEMM ----
    degi_k<<<(EE + 255) / 256, 256>>>(ei);
    dinv_k<<<(NN + 255) / 256, 256>>>();
    scan_k<<<1, 1024>>>();
    fill_k<<<(EE + 255) / 256, 256>>>(ei);
    tcgemm_k<false, false, false, false, false><<<gD, 256, GEMM_SMEM>>>(
        p_xt, DD, p_gWt, DD, 0, p_xw, DD, 0, nullptr, NN, DD, nullptr, 0);
    gather_k<<<NN, 128>>>(x, gcn_b);
    stats0_k<<<MB, DD>>>();

    // ---- Wave branch (factored through K=128) ----
    colsum_k<<<(NN + 499) / 500, KK>>>(evc);
    atb_k<<<gAtbX, 256, ATB_SMEM>>>(p_evct, p_xt, DD, 0, p_xe, DD, 0);
    round_k<<<64, 256>>>(p_xe, p_xe, KK * DD);
    tcgemm_k<false, false, false, false, false><<<gTiny, 256, GEMM_SMEM>>>(
        p_xe, DD, p_linWp, DD, 0, p_uraw, DD, 0, nullptr, KK, DD, nullptr, 0);
    post_u_k<<<(KK * DD + 255) / 256, 256>>>(fs, lin_b);
    tcgemm_k<false, true, true, false, false><<<gV, 256, GEMM_SMEM>>>(
        p_evct, KK, p_u, DD, 128, p_v, SSc, (long long)NN * SSc, nullptr, NN, KK, nullptr, 0);
    atb_k<<<gAtbU, 256, ATB_SMEM>>>(p_evct, p_v, SSc, (long long)NN * SSc, p_u2, DD, 128);
    scale_u2_k<<<(KK * DD + 255) / 256, 256>>>(fs);
    tcgemm_k<false, false, true, false, false><<<gTiny, 256, GEMM_SMEM>>>(
        p_u2, DD, p_fWt, DD, 0, p_W2, DD, 0, nullptr, KK, DD, nullptr, 0);
    tcgemm_k<true, true, false, false, true><<<gD, 256, GEMM_SMEM>>>(
        p_evct, KK, p_W2, DD, 0, p_bufA, DD, 0, fusion_b, NN, KK, x, 1);

    // ---- combine + BN ----
    finalize_k<<<1, DD>>>(0, bn1l_g, bn1l_b);
    finalize_k<<<1, DD>>>(1, bn1a_g, bn1a_b);
    apply_sum_k<<<(NN * DD + 255) / 256, 256>>>();

    // ---- feed-forward ----
    tcgemm_k<true, true, true, true, false><<<gF, 256, GEMM_SMEM>>>(
        p_h, DD, p_f1Wt, DD2, 0, p_mid, DD2, 0, ff1_b, NN, DD, nullptr, 0);
    tcgemm_k<true, false, false, false, true><<<gD, 256, GEMM_SMEM>>>(
        p_mid, DD2, p_f2Wt, DD, 0, p_ff, DD, 0, ff2_b, NN, DD2, p_h, 2);
    finalize_k<<<1, DD>>>(2, bn2_g, bn2_b);
    bn2_apply_k<<<(NN * DD + 255) / 256, 256>>>(out);
}

// round 9
// speedup vs baseline: 5.1647x; 1.2420x over previous
#include <cuda_runtime.h>
#include <cuda_bf16.h>
#include <cstdint>

#define NN  50000
#define EE  800000
#define DD  512
#define KK  128
#define TJc 4
#define SSc 128
#define DD2 1024
#define EPSC 1e-5f

// ---------------- scratch (device globals) -----------------------------------
__device__ float g_xw  [(size_t)NN * DD];
__device__ float g_bufL[(size_t)NN * DD];
__device__ float g_v   [(size_t)TJc * NN * SSc];   // fp32 tf32-rounded (atb input)
__device__ float g_bufA[(size_t)NN * DD];
__device__ float g_h   [(size_t)NN * DD];
__device__ float g_ff  [(size_t)NN * DD];
__device__ float g_xt  [(size_t)NN * DD];          // tf32 x (atbX)
__device__ float g_evct[(size_t)NN * KK];          // tf32 evc (atb)
__device__ __nv_bfloat16 g_xb  [(size_t)NN * DD];  // bf16 x
__device__ __nv_bfloat16 g_evcb[(size_t)NN * KK];  // bf16 evc
__device__ __nv_bfloat16 g_hb  [(size_t)NN * DD];  // bf16 h
__device__ __nv_bfloat16 g_midb[(size_t)NN * DD2]; // bf16 ff hidden
__device__ uint32_t g_gWbp [(DD / 2) * DD];        // bf16x2 packed weights
__device__ uint32_t g_f1Wbp[(DD / 2) * DD2];
__device__ uint32_t g_f2Wbp[(DD2 / 2) * DD];
__device__ uint32_t g_W2bp [(KK / 2) * DD];
__device__ uint32_t g_ubp  [(KK / 2) * DD];
__device__ float g_deg [NN];
__device__ int   g_degi[NN];
__device__ int   g_off [NN + 1];
__device__ int   g_cur [NN];
__device__ int   g_csrc[EE];
__device__ float g_esum[KK];
__device__ float g_xe  [KK * DD];
__device__ float g_uraw[KK * DD];
__device__ float g_u2  [KK * DD];
__device__ float g_W2  [KK * DD];
__device__ float g_stats[6 * DD];
__device__ float g_coef [6 * DD];
__device__ float g_linWp[DD * DD];                 // tf32 packed lin_W
__device__ float g_fWt  [DD * DD];                 // tf32 fusion_W
__device__ int   g_is64;

// ---------------- helpers -----------------------------------------------------
__device__ __forceinline__ float tf32r(float f) {
    uint32_t u; asm("cvt.rna.tf32.f32 %0, %1;" : "=r"(u) : "f"(f));
    return __uint_as_float(u);
}
__device__ __forceinline__ uint32_t packbf(float lo, float hi) {
    uint32_t r; asm("cvt.rn.bf16x2.f32 %0, %1, %2;" : "=r"(r) : "f"(hi), "f"(lo));
    return r;
}
__device__ __forceinline__ void mma_tf32(float* c, const uint32_t* a, const uint32_t* b) {
    asm volatile("mma.sync.aligned.m16n8k8.row.col.f32.tf32.tf32.f32 "
        "{%0,%1,%2,%3}, {%4,%5,%6,%7}, {%8,%9}, {%0,%1,%2,%3};"
        : "+f"(c[0]), "+f"(c[1]), "+f"(c[2]), "+f"(c[3])
        : "r"(a[0]), "r"(a[1]), "r"(a[2]), "r"(a[3]), "r"(b[0]), "r"(b[1]));
}
__device__ __forceinline__ void mma_bf16(float* c, const uint32_t* a, const uint32_t* b) {
    asm volatile("mma.sync.aligned.m16n8k16.row.col.f32.bf16.bf16.f32 "
        "{%0,%1,%2,%3}, {%4,%5,%6,%7}, {%8,%9}, {%0,%1,%2,%3};"
        : "+f"(c[0]), "+f"(c[1]), "+f"(c[2]), "+f"(c[3])
        : "r"(a[0]), "r"(a[1]), "r"(a[2]), "r"(a[3]), "r"(b[0]), "r"(b[1]));
}
__device__ __forceinline__ void cp16(void* sdst, const void* gsrc, bool pred) {
    uint32_t sa = (uint32_t)__cvta_generic_to_shared(sdst);
    int sz = pred ? 16 : 0;
    asm volatile("cp.async.cg.shared.global [%0], [%1], 16, %2;"
                 :: "r"(sa), "l"(gsrc), "r"(sz));
}
#define CP_COMMIT() asm volatile("cp.async.commit_group;")
#define CP_WAIT(n)  asm volatile("cp.async.wait_group %0;" :: "n"(n))

// ---------------- edge-index dtype detection --------------------------------
__global__ void detect_k(const int* __restrict__ ei32) {
    __shared__ int any;
    if (threadIdx.x == 0) any = 0;
    __syncthreads();
    int v = 0;
    for (int i = threadIdx.x; i < 1024; i += blockDim.x)
        v |= ei32[2 * i + 1];
    if (v) atomicOr(&any, 1);
    __syncthreads();
    if (threadIdx.x == 0) g_is64 = (any == 0) ? 1 : 0;
}
__device__ __forceinline__ int edge_at(const void* ei, long long pos) {
    return g_is64 ? (int)((const long long*)ei)[pos] : ((const int*)ei)[pos];
}

// ---------------- zero / round / pack helpers --------------------------------
__global__ void zero_scratch_k() {
    int stride = gridDim.x * blockDim.x;
    int i0 = blockIdx.x * blockDim.x + threadIdx.x;
    for (int i = i0; i < NN; i += stride) g_degi[i] = 0;
    for (int i = i0; i < KK * DD; i += stride) { g_xe[i] = 0.f; g_u2[i] = 0.f; }
    for (int i = i0; i < 6 * DD; i += stride) g_stats[i] = 0.f;
    for (int i = i0; i < KK; i += stride) g_esum[i] = 0.f;
}
__global__ void round_k(const float* __restrict__ in, float* __restrict__ o, long long n) {
    long long i = (long long)blockIdx.x * blockDim.x + threadIdx.x;
    long long stride = (long long)gridDim.x * blockDim.x;
    for (; i < n / 4; i += stride) {
        float4 v = reinterpret_cast<const float4*>(in)[i];
        v.x = tf32r(v.x); v.y = tf32r(v.y); v.z = tf32r(v.z); v.w = tf32r(v.w);
        reinterpret_cast<float4*>(o)[i] = v;
    }
}
__global__ void tobf_k(const float* __restrict__ in, __nv_bfloat16* __restrict__ o, long long n) {
    long long i = (long long)blockIdx.x * blockDim.x + threadIdx.x;
    long long stride = (long long)gridDim.x * blockDim.x;
    for (; i < n / 4; i += stride) {
        float4 v = reinterpret_cast<const float4*>(in)[i];
        uint2 p = make_uint2(packbf(v.x, v.y), packbf(v.z, v.w));
        reinterpret_cast<uint2*>(o)[i] = p;
    }
}
// pack W [Kd, N] fp32 -> [Kd/2, N] bf16x2 pairs
__global__ void packpairs_k(const float* __restrict__ W, uint32_t* __restrict__ Wp,
                            int Ncols, int total) {
    int idx = blockIdx.x * blockDim.x + threadIdx.x;
    if (idx >= total) return;
    int kp = idx / Ncols, n = idx - kp * Ncols;
    Wp[idx] = packbf(W[(size_t)(2 * kp) * Ncols + n], W[(size_t)(2 * kp + 1) * Ncols + n]);
}
__global__ void colsum_k(const float* __restrict__ evc) {
    int c = threadIdx.x;
    int r0 = blockIdx.x * 500;
    int r1 = min(r0 + 500, NN);
    float s = 0.f;
    for (int r = r0; r < r1; r++) s += evc[(size_t)r * KK + c];
    atomicAdd(&g_esum[c], s);
}

// ---------------- bf16 tensor-core GEMM --------------------------------------
// A bf16 [M, Kd] row-major; Bp bf16x2 pairs [Kd/2, ldb]; Kd % 32 == 0.
template <bool BIAS, bool RELU, bool RND, bool OUTBF, bool ADDST>
__global__ void __launch_bounds__(256, 2) bfgemm_k(
    const __nv_bfloat16* __restrict__ A, int lda,
    const uint32_t* __restrict__ Bp, int ldb, long long bTs,
    void* __restrict__ Cv, int ldc, long long cTs,
    const float* __restrict__ bias,
    int M, int Kd,
    const float* __restrict__ Xadd, int bn)
{
    __shared__ uint32_t AsB[2][128][20];
    __shared__ uint32_t BsB[2][16][136];

    Bp += (long long)blockIdx.z * bTs;

    const int m0 = blockIdx.y * 128;
    const int n0 = blockIdx.x * 128;
    const int tid = threadIdx.x;
    const int lane = tid & 31;
    const int wid = tid >> 5;
    const int g = lane >> 2, t = lane & 3;
    const int wm0 = (wid & 1) * 64;
    const int wn0 = (wid >> 1) * 32;

    float acc[4][4][4] = {};
    const int T = Kd >> 5;

    auto load_tiles = [&](int it, int s) {
        int k0 = it * 32;
        #pragma unroll
        for (int l = 0; l < 2; l++) {               // A: 128 x 32 bf16
            int idx = tid + l * 256;
            int r = idx >> 2, c8 = (idx & 3) * 8;
            bool p = (m0 + r < M);
            int row = p ? (m0 + r) : 0;
            cp16(&AsB[s][r][(idx & 3) * 4], &A[(size_t)row * lda + k0 + c8], p);
        }
        #pragma unroll
        for (int l = 0; l < 2; l++) {               // B: 16 pair-rows x 128 u32
            int idx = tid + l * 256;
            int r = idx >> 5, c = (idx & 31) * 4;
            cp16(&BsB[s][r][c], &Bp[(size_t)(k0 / 2 + r) * ldb + n0 + c], true);
        }
    };

    load_tiles(0, 0);
    CP_COMMIT();

    for (int i = 0; i < T; i++) {
        int cur = i & 1;
        if (i + 1 < T) { load_tiles(i + 1, cur ^ 1); CP_COMMIT(); CP_WAIT(1); }
        else          { CP_WAIT(0); }
        __syncthreads();
        #pragma unroll
        for (int kk = 0; kk < 2; kk++) {            // 2 x k16 per tile
            uint32_t af[4][4], bf[4][2];
            #pragma unroll
            for (int mf = 0; mf < 4; mf++) {
                int mr = wm0 + mf * 16;
                af[mf][0] = AsB[cur][mr + g    ][kk * 8 + t];
                af[mf][1] = AsB[cur][mr + g + 8][kk * 8 + t];
                af[mf][2] = AsB[cur][mr + g    ][kk * 8 + t + 4];
                af[mf][3] = AsB[cur][mr + g + 8][kk * 8 + t + 4];
            }
            #pragma unroll
            for (int nf = 0; nf < 4; nf++) {
                bf[nf][0] = BsB[cur][kk * 8 + t    ][wn0 + nf * 8 + g];
                bf[nf][1] = BsB[cur][kk * 8 + t + 4][wn0 + nf * 8 + g];
            }
            #pragma unroll
            for (int mf = 0; mf < 4; mf++)
                #pragma unroll
                for (int nf = 0; nf < 4; nf++)
                    mma_bf16(acc[mf][nf], af[mf], bf[nf]);
        }
        __syncthreads();
    }

    float* C = (float*)Cv + (long long)blockIdx.z * cTs;
    __nv_bfloat16* Cb = (__nv_bfloat16*)Cv + (long long)blockIdx.z * cTs;
    float cs[4][2] = {}, cq[4][2] = {};

    #pragma unroll
    for (int mf = 0; mf < 4; mf++) {
        int row0 = m0 + wm0 + mf * 16 + g;
        int row1 = row0 + 8;
        #pragma unroll
        for (int nf = 0; nf < 4; nf++) {
            int n = n0 + wn0 + nf * 8 + 2 * t;
            float b0 = 0.f, b1 = 0.f;
            if (BIAS) { b0 = bias[n]; b1 = bias[n + 1]; }
            float2 v0 = make_float2(acc[mf][nf][0] + b0, acc[mf][nf][1] + b1);
            float2 v1 = make_float2(acc[mf][nf][2] + b0, acc[mf][nf][3] + b1);
            if (RELU) {
                v0.x = fmaxf(v0.x, 0.f); v0.y = fmaxf(v0.y, 0.f);
                v1.x = fmaxf(v1.x, 0.f); v1.y = fmaxf(v1.y, 0.f);
            }
            if (RND) {
                v0.x = tf32r(v0.x); v0.y = tf32r(v0.y);
                v1.x = tf32r(v1.x); v1.y = tf32r(v1.y);
            }
            if (row0 < M) {
                if (ADDST) {
                    v0.x += Xadd[(size_t)row0 * ldc + n];
                    v0.y += Xadd[(size_t)row0 * ldc + n + 1];
                    cs[nf][0] += v0.x; cq[nf][0] += v0.x * v0.x;
                    cs[nf][1] += v0.y; cq[nf][1] += v0.y * v0.y;
                }
                if (OUTBF) *reinterpret_cast<uint32_t*>(&Cb[(size_t)row0 * ldc + n]) = packbf(v0.x, v0.y);
                else       *reinterpret_cast<float2*>(&C[(size_t)row0 * ldc + n]) = v0;
            }
            if (row1 < M) {
                if (ADDST) {
                    v1.x += Xadd[(size_t)row1 * ldc + n];
                    v1.y += Xadd[(size_t)row1 * ldc + n + 1];
                    cs[nf][0] += v1.x; cq[nf][0] += v1.x * v1.x;
                    cs[nf][1] += v1.y; cq[nf][1] += v1.y * v1.y;
                }
                if (OUTBF) *reinterpret_cast<uint32_t*>(&Cb[(size_t)row1 * ldc + n]) = packbf(v1.x, v1.y);
                else       *reinterpret_cast<float2*>(&C[(size_t)row1 * ldc + n]) = v1;
            }
        }
    }

    if (ADDST) {
        #pragma unroll
        for (int nf = 0; nf < 4; nf++)
            #pragma unroll
            for (int c2 = 0; c2 < 2; c2++) {
                float s = cs[nf][c2], q = cq[nf][c2];
                #pragma unroll
                for (int off = 4; off < 32; off <<= 1) {
                    s += __shfl_xor_sync(0xffffffffu, s, off);
                    q += __shfl_xor_sync(0xffffffffu, q, off);
                }
                if (g == 0) {
                    int n = n0 + wn0 + nf * 8 + 2 * t + c2;
                    atomicAdd(&g_stats[(bn * 2 + 0) * DD + n], s);
                    atomicAdd(&g_stats[(bn * 2 + 1) * DD + n], q);
                }
            }
    }
}

// ---------------- tf32 GEMM (tiny 128-row GEMMs only) ------------------------
__global__ void __launch_bounds__(256, 2) tcgemm_k(
    const float* __restrict__ A, int lda,
    const float* __restrict__ B, int ldb,
    float* __restrict__ C, int ldc,
    int M, int Kd)
{
    extern __shared__ uint32_t dyn[];
    uint32_t (*As)[128][36]  = reinterpret_cast<uint32_t(*)[128][36]>(dyn);
    uint32_t (*Bs)[32][136]  = reinterpret_cast<uint32_t(*)[32][136]>(dyn + 2 * 128 * 36);

    const int m0 = blockIdx.y * 128;
    const int n0 = blockIdx.x * 128;
    const int tid = threadIdx.x;
    const int lane = tid & 31;
    const int wid = tid >> 5;
    const int g = lane >> 2, t = lane & 3;
    const int wm0 = (wid & 1) * 64;
    const int wn0 = (wid >> 1) * 32;

    float acc[4][4][4] = {};
    const int T = Kd >> 5;

    auto load_tiles = [&](int it, int s) {
        int k0 = it * 32;
        #pragma unroll
        for (int l = 0; l < 4; l++) {
            int idx = tid + l * 256;
            int r = idx >> 3, c = (idx & 7) * 4;
            bool p = (m0 + r < M);
            int row = p ? (m0 + r) : 0;
            cp16(&As[s][r][c], &A[(size_t)row * lda + k0 + c], p);
        }
        #pragma unroll
        for (int l = 0; l < 4; l++) {
            int idx = tid + l * 256;
            int r = idx >> 5, c = (idx & 31) * 4;
            cp16(&Bs[s][r][c], &B[(size_t)(k0 + r) * ldb + n0 + c], true);
        }
    };

    load_tiles(0, 0);
    CP_COMMIT();

    for (int i = 0; i < T; i++) {
        int cur = i & 1;
        if (i + 1 < T) { load_tiles(i + 1, cur ^ 1); CP_COMMIT(); CP_WAIT(1); }
        else          { CP_WAIT(0); }
        __syncthreads();
        #pragma unroll
        for (int kk = 0; kk < 4; kk++) {
            uint32_t af[4][4], bf[4][2];
            #pragma unroll
            for (int mf = 0; mf < 4; mf++) {
                int mr = wm0 + mf * 16;
                af[mf][0] = As[cur][mr + g    ][kk * 8 + t];
                af[mf][1] = As[cur][mr + g + 8][kk * 8 + t];
                af[mf][2] = As[cur][mr + g    ][kk * 8 + t + 4];
                af[mf][3] = As[cur][mr + g + 8][kk * 8 + t + 4];
            }
            #pragma unroll
            for (int nf = 0; nf < 4; nf++) {
                bf[nf][0] = Bs[cur][kk * 8 + t    ][wn0 + nf * 8 + g];
                bf[nf][1] = Bs[cur][kk * 8 + t + 4][wn0 + nf * 8 + g];
            }
            #pragma unroll
            for (int mf = 0; mf < 4; mf++)
                #pragma unroll
                for (int nf = 0; nf < 4; nf++)
                    mma_tf32(acc[mf][nf], af[mf], bf[nf]);
        }
        __syncthreads();
    }

    #pragma unroll
    for (int mf = 0; mf < 4; mf++) {
        int row0 = m0 + wm0 + mf * 16 + g;
        int row1 = row0 + 8;
        #pragma unroll
        for (int nf = 0; nf < 4; nf++) {
            int n = n0 + wn0 + nf * 8 + 2 * t;
            float2 v0 = make_float2(acc[mf][nf][0], acc[mf][nf][1]);
            float2 v1 = make_float2(acc[mf][nf][2], acc[mf][nf][3]);
            if (row0 < M) *reinterpret_cast<float2*>(&C[(size_t)row0 * ldc + n]) = v0;
            if (row1 < M) *reinterpret_cast<float2*>(&C[(size_t)row1 * ldc + n]) = v1;
        }
    }
}

// ------- tf32 tall reduction: C[128, cols] += evc^T[128,N]*B[N,cols] --------
#define ATB_BLKS 64
__global__ void __launch_bounds__(256, 2) atb_k(
    const float* __restrict__ evc,
    const float* __restrict__ B, int ldb, long long bTs,
    float* __restrict__ C, int ldc, long long cTs)
{
    extern __shared__ uint32_t dyn[];
    uint32_t (*Es)[32][136] = reinterpret_cast<uint32_t(*)[32][136]>(dyn);
    uint32_t (*Hs)[32][136] = reinterpret_cast<uint32_t(*)[32][136]>(dyn + 2 * 32 * 136);

    B += (long long)blockIdx.z * bTs;
    C += (long long)blockIdx.z * cTs;
    const int noff = blockIdx.y * 128;

    const int chunk = (NN + ATB_BLKS - 1) / ATB_BLKS;
    const int nStart = blockIdx.x * chunk;
    const int nEnd = min(nStart + chunk, NN);
    const int iters = (chunk + 31) / 32;
    const int tid = threadIdx.x;
    const int lane = tid & 31;
    const int wid = tid >> 5;
    const int g = lane >> 2, t = lane & 3;
    const int wm0 = (wid & 1) * 64;
    const int wn0 = (wid >> 1) * 32;

    float acc[4][4][4] = {};

    auto load_tiles = [&](int it, int s) {
        int n0 = nStart + it * 32;
        #pragma unroll
        for (int l = 0; l < 4; l++) {
            int idx = tid + l * 256;
            int r = idx >> 5, c = (idx & 31) * 4;
            bool p = (n0 + r < nEnd);
            int row = p ? (n0 + r) : 0;
            cp16(&Es[s][r][c], &evc[(size_t)row * KK + c], p);
            cp16(&Hs[s][r][c], &B[(size_t)row * ldb + noff + c], p);
        }
    };

    load_tiles(0, 0);
    CP_COMMIT();

    for (int i = 0; i < iters; i++) {
        int cur = i & 1;
        if (i + 1 < iters) { load_tiles(i + 1, cur ^ 1); CP_COMMIT(); CP_WAIT(1); }
        else              { CP_WAIT(0); }
        __syncthreads();
        #pragma unroll
        for (int kk = 0; kk < 4; kk++) {
            uint32_t af[4][4], bf[4][2];
            #pragma unroll
            for (int mf = 0; mf < 4; mf++) {
                int mc = wm0 + mf * 16;
                af[mf][0] = Es[cur][kk * 8 + t    ][mc + g];
                af[mf][1] = Es[cur][kk * 8 + t    ][mc + g + 8];
                af[mf][2] = Es[cur][kk * 8 + t + 4][mc + g];
                af[mf][3] = Es[cur][kk * 8 + t + 4][mc + g + 8];
            }
            #pragma unroll
            for (int nf = 0; nf < 4; nf++) {
                bf[nf][0] = Hs[cur][kk * 8 + t    ][wn0 + nf * 8 + g];
                bf[nf][1] = Hs[cur][kk * 8 + t + 4][wn0 + nf * 8 + g];
            }
            #pragma unroll
            for (int mf = 0; mf < 4; mf++)
                #pragma unroll
                for (int nf = 0; nf < 4; nf++)
                    mma_tf32(acc[mf][nf], af[mf], bf[nf]);
        }
        __syncthreads();
    }

    #pragma unroll
    for (int mf = 0; mf < 4; mf++) {
        int row0 = wm0 + mf * 16 + g;
        #pragma unroll
        for (int nf = 0; nf < 4; nf++) {
            int n = noff + wn0 + nf * 8 + 2 * t;
            float* p0 = &C[(size_t)row0 * ldc + n];
            float* p1 = &C[(size_t)(row0 + 8) * ldc + n];
            asm volatile("red.global.add.v2.f32 [%0], {%1,%2};"
                         :: "l"(p0), "f"(acc[mf][nf][0]), "f"(acc[mf][nf][1]) : "memory");
            asm volatile("red.global.add.v2.f32 [%0], {%1,%2};"
                         :: "l"(p1), "f"(acc[mf][nf][2]), "f"(acc[mf][nf][3]) : "memory");
        }
    }
}

// ---------------- graph: CSR build + gather ----------------------------------
__global__ void degi_k(const void* __restrict__ ei) {
    int e = blockIdx.x * blockDim.x + threadIdx.x;
    if (e < EE) atomicAdd(&g_degi[edge_at(ei, (long long)EE + e)], 1);
}
__global__ void dinv_k() {
    int n = blockIdx.x * blockDim.x + threadIdx.x;
    if (n < NN) g_deg[n] = rsqrtf((float)g_degi[n] + 1.0f);
}
__global__ void scan_k() {
    __shared__ int s[1024];
    int tid = threadIdx.x;
    const int per = (NN + 1023) / 1024;
    int start = tid * per, end = min(start + per, NN);
    int sum = 0;
    for (int i = start; i < end; i++) sum += g_degi[i];
    s[tid] = sum;
    __syncthreads();
    for (int off = 1; off < 1024; off <<= 1) {
        int v = 0;
        if (tid >= off) v = s[tid - off];
        __syncthreads();
        if (tid >= off) s[tid] += v;
        __syncthreads();
    }
    int base = s[tid] - sum;
    for (int i = start; i < end; i++) {
        g_off[i] = base; g_cur[i] = base;
        base += g_degi[i];
    }
    if (tid == 1023) g_off[NN] = base;
}
__global__ void fill_k(const void* __restrict__ ei) {
    int e = blockIdx.x * blockDim.x + threadIdx.x;
    if (e >= EE) return;
    int src = edge_at(ei, e);
    int dst = edge_at(ei, (long long)EE + e);
    int pos = atomicAdd(&g_cur[dst], 1);
    g_csrc[pos] = src;
}
__global__ void __launch_bounds__(128) gather_k(const float* __restrict__ x,
                                                const float* __restrict__ gcn_b) {
    const int n = blockIdx.x;
    const int c = threadIdx.x * 4;
    const int s0 = g_off[n], s1 = g_off[n + 1];
    const float dv = g_deg[n];
    float4 acc = make_float4(0.f, 0.f, 0.f, 0.f);
    int e = s0;
    #pragma unroll 1
    for (; e + 2 <= s1; e += 2) {
        int srcA = g_csrc[e], srcB = g_csrc[e + 1];
        float nA = dv * g_deg[srcA], nB = dv * g_deg[srcB];
        float4 vA = *reinterpret_cast<const float4*>(&g_xw[(size_t)srcA * DD + c]);
        float4 vB = *reinterpret_cast<const float4*>(&g_xw[(size_t)srcB * DD + c]);
        acc.x += nA * vA.x + nB * vB.x;
        acc.y += nA * vA.y + nB * vB.y;
        acc.z += nA * vA.z + nB * vB.z;
        acc.w += nA * vA.w + nB * vB.w;
    }
    if (e < s1) {
        int src = g_csrc[e];
        float nrm = dv * g_deg[src];
        float4 v = *reinterpret_cast<const float4*>(&g_xw[(size_t)src * DD + c]);
        acc.x += nrm * v.x; acc.y += nrm * v.y; acc.z += nrm * v.z; acc.w += nrm * v.w;
    }
    float4 xw = *reinterpret_cast<const float4*>(&g_xw[(size_t)n * DD + c]);
    float4 xr = *reinterpret_cast<const float4*>(&x[(size_t)n * DD + c]);
    float4 bb = *reinterpret_cast<const float4*>(&gcn_b[c]);
    float d2 = dv * dv;
    float4 o;
    o.x = xr.x + acc.x + d2 * xw.x + bb.x;
    o.y = xr.y + acc.y + d2 * xw.y + bb.y;
    o.z = xr.z + acc.z + d2 * xw.z + bb.z;
    o.w = xr.w + acc.w + d2 * xw.w + bb.w;
    *reinterpret_cast<float4*>(&g_bufL[(size_t)n * DD + c]) = o;
}
__global__ void stats0_k() {
    const int c = threadIdx.x;
    const int r0 = blockIdx.x * 128;
    const int rEnd = min(r0 + 128, NN);
    float s = 0.f, s2 = 0.f;
    for (int r = r0; r < rEnd; r++) {
        float v = g_bufL[(size_t)r * DD + c];
        s += v; s2 += v * v;
    }
    atomicAdd(&g_stats[0 * DD + c], s);
    atomicAdd(&g_stats[1 * DD + c], s2);
}

__global__ void finalize_k(int bn, const float* __restrict__ gamma, const float* __restrict__ beta) {
    int c = threadIdx.x;
    float s  = g_stats[(bn * 2 + 0) * DD + c];
    float s2 = g_stats[(bn * 2 + 1) * DD + c];
    float m = s * (1.0f / NN);
    float var = s2 * (1.0f / NN) - m * m;
    float a = gamma[c] * rsqrtf(var + EPSC);
    g_coef[(bn * 2 + 0) * DD + c] = a;
    g_coef[(bn * 2 + 1) * DD + c] = beta[c] - m * a;
}

__global__ void apply_sum_k() {      // h fp32 + hb bf16
    int i = blockIdx.x * blockDim.x + threadIdx.x;
    if (i >= NN * DD / 2) return;
    int base = i * 2;
    int c = base & (DD - 1);
    float v0 = g_bufL[base] * g_coef[c] + g_coef[DD + c]
             + g_bufA[base] * g_coef[2 * DD + c] + g_coef[3 * DD + c];
    float v1 = g_bufL[base + 1] * g_coef[c + 1] + g_coef[DD + c + 1]
             + g_bufA[base + 1] * g_coef[2 * DD + c + 1] + g_coef[3 * DD + c + 1];
    g_h[base] = v0; g_h[base + 1] = v1;
    *reinterpret_cast<uint32_t*>(&g_hb[base]) = packbf(v0, v1);
}
__global__ void bn2_apply_k(float* __restrict__ out) {
    int idx = blockIdx.x * blockDim.x + threadIdx.x;
    if (idx >= NN * DD) return;
    int c = idx & (DD - 1);
    out[idx] = g_ff[idx] * g_coef[4 * DD + c] + g_coef[5 * DD + c];
}

// ---------------- wave helpers ----------------------------------------------
__global__ void pack_w_k(const float* __restrict__ linW, const float* __restrict__ fW) {
    int idx = blockIdx.x * blockDim.x + threadIdx.x;
    if (idx >= DD * DD) return;
    int d = idx >> 9, j = idx & 511;
    int t = j >> 7, s = j & 127;
    g_linWp[idx] = tf32r(linW[t * (DD * SSc) + d * SSc + s]);
    g_fWt[idx]   = tf32r(fW[idx]);
}
// u packed bf16 pairs: ubp[kp][j]
__global__ void post_u_k(const float* __restrict__ fs, const float* __restrict__ linB) {
    int idx = blockIdx.x * blockDim.x + threadIdx.x;   // (KK/2)*DD
    if (idx >= (KK / 2) * DD) return;
    int kp = idx >> 9, j = idx & 511;
    int t = j >> 7, s = j & 127;
    float bl = linB[t * SSc + s];
    int k0 = 2 * kp, k1 = 2 * kp + 1;
    float v0 = fs[k0 * TJc + t] * (g_uraw[k0 * DD + j] + g_esum[k0] * bl);
    float v1 = fs[k1 * TJc + t] * (g_uraw[k1 * DD + j] + g_esum[k1] * bl);
    g_ubp[idx] = packbf(v0, v1);
}
__global__ void scale_u2_k(const float* __restrict__ fs) {
    int idx = blockIdx.x * blockDim.x + threadIdx.x;
    if (idx >= KK * DD) return;
    int k = idx >> 9, t = (idx & 511) >> 7;
    g_u2[idx] = tf32r(g_u2[idx] * fs[k * TJc + t]);
}

// ---------------- launch -----------------------------------------------------
#define GSYM(p, ty, s) do { void* _t; cudaGetSymbolAddress(&_t, s); (p) = (ty)_t; } while (0)

extern "C" void kernel_launch(void* const* d_in, const int* in_sizes, int n_in,
                              void* d_out, int out_size) {
    const float* x        = (const float*)d_in[0];
    const void*  ei       = d_in[1];
    const float* evc      = (const float*)d_in[2];
    const float* fs       = (const float*)d_in[3];
    const float* gcn_W    = (const float*)d_in[4];
    const float* gcn_b    = (const float*)d_in[5];
    const float* lin_W    = (const float*)d_in[6];
    const float* lin_b    = (const float*)d_in[7];
    const float* fusion_W = (const float*)d_in[8];
    const float* fusion_b = (const float*)d_in[9];
    const float* bn1l_g   = (const float*)d_in[10];
    const float* bn1l_b   = (const float*)d_in[11];
    const float* bn1a_g   = (const float*)d_in[12];
    const float* bn1a_b   = (const float*)d_in[13];
    const float* bn2_g    = (const float*)d_in[14];
    const float* bn2_b    = (const float*)d_in[15];
    const float* ff1_W    = (const float*)d_in[16];
    const float* ff1_b    = (const float*)d_in[17];
    const float* ff2_W    = (const float*)d_in[18];
    const float* ff2_b    = (const float*)d_in[19];
    float* out = (float*)d_out;

    float *p_xw, *p_bufL, *p_v, *p_bufA, *p_h, *p_ff, *p_xt, *p_evct;
    float *p_xe, *p_uraw, *p_u2, *p_W2, *p_linWp, *p_fWt;
    __nv_bfloat16 *p_xb, *p_evcb, *p_hb, *p_midb;
    uint32_t *p_gWbp, *p_f1Wbp, *p_f2Wbp, *p_W2bp, *p_ubp;
    GSYM(p_xw, float*, g_xw);     GSYM(p_bufL, float*, g_bufL); GSYM(p_v, float*, g_v);
    GSYM(p_bufA, float*, g_bufA); GSYM(p_h, float*, g_h);       GSYM(p_ff, float*, g_ff);
    GSYM(p_xt, float*, g_xt);     GSYM(p_evct, float*, g_evct);
    GSYM(p_xe, float*, g_xe);     GSYM(p_uraw, float*, g_uraw);
    GSYM(p_u2, float*, g_u2);     GSYM(p_W2, float*, g_W2);
    GSYM(p_linWp, float*, g_linWp); GSYM(p_fWt, float*, g_fWt);
    GSYM(p_xb, __nv_bfloat16*, g_xb);   GSYM(p_evcb, __nv_bfloat16*, g_evcb);
    GSYM(p_hb, __nv_bfloat16*, g_hb);   GSYM(p_midb, __nv_bfloat16*, g_midb);
    GSYM(p_gWbp, uint32_t*, g_gWbp);    GSYM(p_f1Wbp, uint32_t*, g_f1Wbp);
    GSYM(p_f2Wbp, uint32_t*, g_f2Wbp);  GSYM(p_W2bp, uint32_t*, g_W2bp);
    GSYM(p_ubp, uint32_t*, g_ubp);

    const int GEMM_SMEM = (2 * 128 * 36 + 2 * 32 * 136) * 4;
    const int ATB_SMEM  = (2 * 32 * 136 * 2) * 4;
    cudaFuncSetAttribute(tcgemm_k, cudaFuncAttributeMaxDynamicSharedMemorySize, GEMM_SMEM);
    cudaFuncSetAttribute(atb_k, cudaFuncAttributeMaxDynamicSharedMemorySize, ATB_SMEM);

    const int MB = (NN + 127) / 128;
    dim3 gD(4, MB);
    dim3 gF(8, MB);
    dim3 gV(1, MB, TJc);
    dim3 gTiny(4, 1);
    dim3 gAtbX(ATB_BLKS, 4, 1);
    dim3 gAtbU(ATB_BLKS, 1, TJc);

    detect_k<<<1, 256>>>((const int*)ei);
    zero_scratch_k<<<2048, 256>>>();
    pack_w_k<<<(DD * DD + 255) / 256, 256>>>(lin_W, fusion_W);
    packpairs_k<<<((DD / 2) * DD + 255) / 256, 256>>>(gcn_W, p_gWbp, DD, (DD / 2) * DD);
    packpairs_k<<<((DD / 2) * DD2 + 255) / 256, 256>>>(ff1_W, p_f1Wbp, DD2, (DD / 2) * DD2);
    packpairs_k<<<((DD2 / 2) * DD + 255) / 256, 256>>>(ff2_W, p_f2Wbp, DD, (DD2 / 2) * DD);
    round_k<<<1024, 256>>>(x, p_xt, (long long)NN * DD);
    round_k<<<256, 256>>>(evc, p_evct, (long long)NN * KK);
    tobf_k<<<1024, 256>>>(x, p_xb, (long long)NN * DD);
    tobf_k<<<256, 256>>>(evc, p_evcb, (long long)NN * KK);

    // ---- GCN branch ----
    degi_k<<<(EE + 255) / 256, 256>>>(ei);
    dinv_k<<<(NN + 255) / 256, 256>>>();
    scan_k<<<1, 1024>>>();
    fill_k<<<(EE + 255) / 256, 256>>>(ei);
    bfgemm_k<false, false, false, false, false><<<gD, 256>>>(
        p_xb, DD, p_gWbp, DD, 0, p_xw, DD, 0, nullptr, NN, DD, nullptr, 0);
    gather_k<<<NN, 128>>>(x, gcn_b);
    stats0_k<<<MB, DD>>>();

    // ---- Wave branch ----
    colsum_k<<<(NN + 499) / 500, KK>>>(evc);
    atb_k<<<gAtbX, 256, ATB_SMEM>>>(p_evct, p_xt, DD, 0, p_xe, DD, 0);
    round_k<<<64, 256>>>(p_xe, p_xe, KK * DD);
    tcgemm_k<<<gTiny, 256, GEMM_SMEM>>>(p_xe, DD, p_linWp, DD, p_uraw, DD, KK, DD);
    post_u_k<<<((KK / 2) * DD + 255) / 256, 256>>>(fs, lin_b);
    // v = relu(evc @ u), tf32-rounded fp32 output (atb consumes it)
    bfgemm_k<false, true, true, false, false><<<gV, 256>>>(
        p_evcb, KK, p_ubp, DD, 128, p_v, SSc, (long long)NN * SSc, nullptr, NN, KK, nullptr, 0);
    atb_k<<<gAtbU, 256, ATB_SMEM>>>(p_evct, p_v, SSc, (long long)NN * SSc, p_u2, DD, 128);
    scale_u2_k<<<(KK * DD + 255) / 256, 256>>>(fs);
    tcgemm_k<<<gTiny, 256, GEMM_SMEM>>>(p_u2, DD, p_fWt, DD, p_W2, DD, KK, DD);
    packpairs_k<<<((KK / 2) * DD + 255) / 256, 256>>>(p_W2, p_W2bp, DD, (KK / 2) * DD);
    // bufA = x + relu(evc@W2 + fusion_b), fused BN1a stats
    bfgemm_k<true, true, false, false, true><<<gD, 256>>>(
        p_evcb, KK, p_W2bp, DD, 0, p_bufA, DD, 0, fusion_b, NN, KK, x, 1);

    // ---- combine + BN ----
    finalize_k<<<1, DD>>>(0, bn1l_g, bn1l_b);
    finalize_k<<<1, DD>>>(1, bn1a_g, bn1a_b);
    apply_sum_k<<<(NN * DD / 2 + 255) / 256, 256>>>();

    // ---- feed-forward ----
    bfgemm_k<true, true, false, true, false><<<gF, 256>>>(
        p_hb, DD, p_f1Wbp, DD2, 0, p_midb, DD2, 0, ff1_b, NN, DD, nullptr, 0);
    bfgemm_k<true, false, false, false, true><<<gD, 256>>>(
        p_midb, DD2, p_f2Wbp, DD, 0, p_ff, DD, 0, ff2_b, NN, DD2, p_h, 2);
    finalize_k<<<1, DD>>>(2, bn2_g, bn2_b);
    bn2_apply_k<<<(NN * DD + 255) / 256, 256>>>(out);
}

// round 10
// speedup vs baseline: 5.5381x; 1.0723x over previous
#include <cuda_runtime.h>
#include <cuda_bf16.h>
#include <cstdint>

#define NN  50000
#define EE  800000
#define DD  512
#define KK  128
#define TJc 4
#define SSc 128
#define DD2 1024
#define EPSC 1e-5f

// ---------------- scratch (device globals) -----------------------------------
__device__ float g_xw  [(size_t)NN * DD];
__device__ float g_bufL[(size_t)NN * DD];
__device__ float g_v   [(size_t)TJc * NN * SSc];
__device__ float g_bufA[(size_t)NN * DD];
__device__ float g_h   [(size_t)NN * DD];
__device__ float g_ff  [(size_t)NN * DD];
__device__ float g_evct[(size_t)NN * KK];          // tf32 evc (atb A)
__device__ __nv_bfloat16 g_xb  [(size_t)NN * DD];
__device__ __nv_bfloat16 g_evcb[(size_t)NN * KK];
__device__ __nv_bfloat16 g_hb  [(size_t)NN * DD];
__device__ __nv_bfloat16 g_midb[(size_t)NN * DD2];
__device__ uint32_t g_gWbp [(DD / 2) * DD];
__device__ uint32_t g_f1Wbp[(DD / 2) * DD2];
__device__ uint32_t g_f2Wbp[(DD2 / 2) * DD];
__device__ uint32_t g_W2bp [(KK / 2) * DD];
__device__ uint32_t g_ubp  [(KK / 2) * DD];
__device__ float g_deg [NN];
__device__ int   g_degi[NN];
__device__ int   g_off [NN + 1];
__device__ int   g_cur [NN];
__device__ int   g_csrc[EE];
__device__ float g_esum[KK];
__device__ float g_xe  [KK * DD];
__device__ float g_uraw[KK * DD];
__device__ float g_u2  [KK * DD];
__device__ float g_W2  [KK * DD];
__device__ float g_stats[6 * DD];
__device__ float g_coef [6 * DD];
__device__ float g_linWp[DD * DD];
__device__ float g_fWt  [DD * DD];
__device__ int   g_is64;

// ---------------- helpers -----------------------------------------------------
__device__ __forceinline__ float tf32r(float f) {
    uint32_t u; asm("cvt.rna.tf32.f32 %0, %1;" : "=r"(u) : "f"(f));
    return __uint_as_float(u);
}
__device__ __forceinline__ uint32_t cvt_rna(uint32_t x) {
    uint32_t u; float f = __uint_as_float(x);
    asm("cvt.rna.tf32.f32 %0, %1;" : "=r"(u) : "f"(f)); return u;
}
__device__ __forceinline__ uint32_t packbf(float lo, float hi) {
    uint32_t r; asm("cvt.rn.bf16x2.f32 %0, %1, %2;" : "=r"(r) : "f"(hi), "f"(lo));
    return r;
}
__device__ __forceinline__ void mma_tf32(float* c, const uint32_t* a, const uint32_t* b) {
    asm volatile("mma.sync.aligned.m16n8k8.row.col.f32.tf32.tf32.f32 "
        "{%0,%1,%2,%3}, {%4,%5,%6,%7}, {%8,%9}, {%0,%1,%2,%3};"
        : "+f"(c[0]), "+f"(c[1]), "+f"(c[2]), "+f"(c[3])
        : "r"(a[0]), "r"(a[1]), "r"(a[2]), "r"(a[3]), "r"(b[0]), "r"(b[1]));
}
__device__ __forceinline__ void mma_bf16(float* c, const uint32_t* a, const uint32_t* b) {
    asm volatile("mma.sync.aligned.m16n8k16.row.col.f32.bf16.bf16.f32 "
        "{%0,%1,%2,%3}, {%4,%5,%6,%7}, {%8,%9}, {%0,%1,%2,%3};"
        : "+f"(c[0]), "+f"(c[1]), "+f"(c[2]), "+f"(c[3])
        : "r"(a[0]), "r"(a[1]), "r"(a[2]), "r"(a[3]), "r"(b[0]), "r"(b[1]));
}
__device__ __forceinline__ void cp16(void* sdst, const void* gsrc, bool pred) {
    uint32_t sa = (uint32_t)__cvta_generic_to_shared(sdst);
    int sz = pred ? 16 : 0;
    asm volatile("cp.async.cg.shared.global [%0], [%1], 16, %2;"
                 :: "r"(sa), "l"(gsrc), "r"(sz));
}
#define CP_COMMIT() asm volatile("cp.async.commit_group;")
#define CP_WAIT(n)  asm volatile("cp.async.wait_group %0;" :: "n"(n))

// ---------------- edge-index dtype detection --------------------------------
__global__ void detect_k(const int* __restrict__ ei32) {
    __shared__ int any;
    if (threadIdx.x == 0) any = 0;
    __syncthreads();
    int v = 0;
    for (int i = threadIdx.x; i < 1024; i += blockDim.x)
        v |= ei32[2 * i + 1];
    if (v) atomicOr(&any, 1);
    __syncthreads();
    if (threadIdx.x == 0) g_is64 = (any == 0) ? 1 : 0;
}
__device__ __forceinline__ int edge_at(const void* ei, long long pos) {
    return g_is64 ? (int)((const long long*)ei)[pos] : ((const int*)ei)[pos];
}

// ---------------- zero / round / pack helpers --------------------------------
__global__ void zero_scratch_k() {
    int stride = gridDim.x * blockDim.x;
    int i0 = blockIdx.x * blockDim.x + threadIdx.x;
    for (int i = i0; i < NN; i += stride) g_degi[i] = 0;
    for (int i = i0; i < KK * DD; i += stride) { g_xe[i] = 0.f; g_u2[i] = 0.f; }
    for (int i = i0; i < 6 * DD; i += stride) g_stats[i] = 0.f;
    for (int i = i0; i < KK; i += stride) g_esum[i] = 0.f;
}
__global__ void round_k(const float* __restrict__ in, float* __restrict__ o, long long n) {
    long long i = (long long)blockIdx.x * blockDim.x + threadIdx.x;
    long long stride = (long long)gridDim.x * blockDim.x;
    for (; i < n / 4; i += stride) {
        float4 v = reinterpret_cast<const float4*>(in)[i];
        v.x = tf32r(v.x); v.y = tf32r(v.y); v.z = tf32r(v.z); v.w = tf32r(v.w);
        reinterpret_cast<float4*>(o)[i] = v;
    }
}
__global__ void tobf_k(const float* __restrict__ in, __nv_bfloat16* __restrict__ o, long long n) {
    long long i = (long long)blockIdx.x * blockDim.x + threadIdx.x;
    long long stride = (long long)gridDim.x * blockDim.x;
    for (; i < n / 4; i += stride) {
        float4 v = reinterpret_cast<const float4*>(in)[i];
        uint2 p = make_uint2(packbf(v.x, v.y), packbf(v.z, v.w));
        reinterpret_cast<uint2*>(o)[i] = p;
    }
}
__global__ void packpairs_k(const float* __restrict__ W, uint32_t* __restrict__ Wp,
                            int Ncols, int total) {
    int idx = blockIdx.x * blockDim.x + threadIdx.x;
    if (idx >= total) return;
    int kp = idx / Ncols, n = idx - kp * Ncols;
    Wp[idx] = packbf(W[(size_t)(2 * kp) * Ncols + n], W[(size_t)(2 * kp + 1) * Ncols + n]);
}
__global__ void colsum_k(const float* __restrict__ evc) {
    int c = threadIdx.x;
    int r0 = blockIdx.x * 500;
    int r1 = min(r0 + 500, NN);
    float s = 0.f;
    for (int r = r0; r < r1; r++) s += evc[(size_t)r * KK + c];
    atomicAdd(&g_esum[c], s);
}

// ---------------- bf16 tensor-core GEMM --------------------------------------
template <bool BIAS, bool RELU, bool RND, bool OUTBF, bool ADDST>
__global__ void __launch_bounds__(256, 2) bfgemm_k(
    const __nv_bfloat16* __restrict__ A, int lda,
    const uint32_t* __restrict__ Bp, int ldb, long long bTs,
    void* __restrict__ Cv, int ldc, long long cTs,
    const float* __restrict__ bias,
    int M, int Kd,
    const float* __restrict__ Xadd, int bn)
{
    __shared__ uint32_t AsB[2][128][20];
    __shared__ uint32_t BsB[2][16][136];

    Bp += (long long)blockIdx.z * bTs;

    const int m0 = blockIdx.y * 128;
    const int n0 = blockIdx.x * 128;
    const int tid = threadIdx.x;
    const int lane = tid & 31;
    const int wid = tid >> 5;
    const int g = lane >> 2, t = lane & 3;
    const int wm0 = (wid & 1) * 64;
    const int wn0 = (wid >> 1) * 32;

    float acc[4][4][4] = {};
    const int T = Kd >> 5;

    auto load_tiles = [&](int it, int s) {
        int k0 = it * 32;
        #pragma unroll
        for (int l = 0; l < 2; l++) {
            int idx = tid + l * 256;
            int r = idx >> 2, c8 = (idx & 3) * 8;
            bool p = (m0 + r < M);
            int row = p ? (m0 + r) : 0;
            cp16(&AsB[s][r][(idx & 3) * 4], &A[(size_t)row * lda + k0 + c8], p);
        }
        #pragma unroll
        for (int l = 0; l < 2; l++) {
            int idx = tid + l * 256;
            int r = idx >> 5, c = (idx & 31) * 4;
            cp16(&BsB[s][r][c], &Bp[(size_t)(k0 / 2 + r) * ldb + n0 + c], true);
        }
    };

    load_tiles(0, 0);
    CP_COMMIT();

    for (int i = 0; i < T; i++) {
        int cur = i & 1;
        if (i + 1 < T) { load_tiles(i + 1, cur ^ 1); CP_COMMIT(); CP_WAIT(1); }
        else          { CP_WAIT(0); }
        __syncthreads();
        #pragma unroll
        for (int kk = 0; kk < 2; kk++) {
            uint32_t af[4][4], bf[4][2];
            #pragma unroll
            for (int mf = 0; mf < 4; mf++) {
                int mr = wm0 + mf * 16;
                af[mf][0] = AsB[cur][mr + g    ][kk * 8 + t];
                af[mf][1] = AsB[cur][mr + g + 8][kk * 8 + t];
                af[mf][2] = AsB[cur][mr + g    ][kk * 8 + t + 4];
                af[mf][3] = AsB[cur][mr + g + 8][kk * 8 + t + 4];
            }
            #pragma unroll
            for (int nf = 0; nf < 4; nf++) {
                bf[nf][0] = BsB[cur][kk * 8 + t    ][wn0 + nf * 8 + g];
                bf[nf][1] = BsB[cur][kk * 8 + t + 4][wn0 + nf * 8 + g];
            }
            #pragma unroll
            for (int mf = 0; mf < 4; mf++)
                #pragma unroll
                for (int nf = 0; nf < 4; nf++)
                    mma_bf16(acc[mf][nf], af[mf], bf[nf]);
        }
        __syncthreads();
    }

    float* C = (float*)Cv + (long long)blockIdx.z * cTs;
    __nv_bfloat16* Cb = (__nv_bfloat16*)Cv + (long long)blockIdx.z * cTs;
    float cs[4][2] = {}, cq[4][2] = {};

    #pragma unroll
    for (int mf = 0; mf < 4; mf++) {
        int row0 = m0 + wm0 + mf * 16 + g;
        int row1 = row0 + 8;
        #pragma unroll
        for (int nf = 0; nf < 4; nf++) {
            int n = n0 + wn0 + nf * 8 + 2 * t;
            float b0 = 0.f, b1 = 0.f;
            if (BIAS) { b0 = bias[n]; b1 = bias[n + 1]; }
            float2 v0 = make_float2(acc[mf][nf][0] + b0, acc[mf][nf][1] + b1);
            float2 v1 = make_float2(acc[mf][nf][2] + b0, acc[mf][nf][3] + b1);
            if (RELU) {
                v0.x = fmaxf(v0.x, 0.f); v0.y = fmaxf(v0.y, 0.f);
                v1.x = fmaxf(v1.x, 0.f); v1.y = fmaxf(v1.y, 0.f);
            }
            if (RND) {
                v0.x = tf32r(v0.x); v0.y = tf32r(v0.y);
                v1.x = tf32r(v1.x); v1.y = tf32r(v1.y);
            }
            if (row0 < M) {
                if (ADDST) {
                    v0.x += Xadd[(size_t)row0 * ldc + n];
                    v0.y += Xadd[(size_t)row0 * ldc + n + 1];
                    cs[nf][0] += v0.x; cq[nf][0] += v0.x * v0.x;
                    cs[nf][1] += v0.y; cq[nf][1] += v0.y * v0.y;
                }
                if (OUTBF) *reinterpret_cast<uint32_t*>(&Cb[(size_t)row0 * ldc + n]) = packbf(v0.x, v0.y);
                else       *reinterpret_cast<float2*>(&C[(size_t)row0 * ldc + n]) = v0;
            }
            if (row1 < M) {
                if (ADDST) {
                    v1.x += Xadd[(size_t)row1 * ldc + n];
                    v1.y += Xadd[(size_t)row1 * ldc + n + 1];
                    cs[nf][0] += v1.x; cq[nf][0] += v1.x * v1.x;
                    cs[nf][1] += v1.y; cq[nf][1] += v1.y * v1.y;
                }
                if (OUTBF) *reinterpret_cast<uint32_t*>(&Cb[(size_t)row1 * ldc + n]) = packbf(v1.x, v1.y);
                else       *reinterpret_cast<float2*>(&C[(size_t)row1 * ldc + n]) = v1;
            }
        }
    }

    if (ADDST) {
        #pragma unroll
        for (int nf = 0; nf < 4; nf++)
            #pragma unroll
            for (int c2 = 0; c2 < 2; c2++) {
                float s = cs[nf][c2], q = cq[nf][c2];
                #pragma unroll
                for (int off = 4; off < 32; off <<= 1) {
                    s += __shfl_xor_sync(0xffffffffu, s, off);
                    q += __shfl_xor_sync(0xffffffffu, q, off);
                }
                if (g == 0) {
                    int n = n0 + wn0 + nf * 8 + 2 * t + c2;
                    atomicAdd(&g_stats[(bn * 2 + 0) * DD + n], s);
                    atomicAdd(&g_stats[(bn * 2 + 1) * DD + n], q);
                }
            }
    }
}

// ---------------- tf32 GEMM (tiny 128-row GEMMs) -----------------------------
__global__ void __launch_bounds__(256, 2) tcgemm_k(
    const float* __restrict__ A, int lda,
    const float* __restrict__ B, int ldb,
    float* __restrict__ C, int ldc,
    int M, int Kd)
{
    extern __shared__ uint32_t dyn[];
    uint32_t (*As)[128][36]  = reinterpret_cast<uint32_t(*)[128][36]>(dyn);
    uint32_t (*Bs)[32][136]  = reinterpret_cast<uint32_t(*)[32][136]>(dyn + 2 * 128 * 36);

    const int m0 = blockIdx.y * 128;
    const int n0 = blockIdx.x * 128;
    const int tid = threadIdx.x;
    const int lane = tid & 31;
    const int wid = tid >> 5;
    const int g = lane >> 2, t = lane & 3;
    const int wm0 = (wid & 1) * 64;
    const int wn0 = (wid >> 1) * 32;

    float acc[4][4][4] = {};
    const int T = Kd >> 5;

    auto load_tiles = [&](int it, int s) {
        int k0 = it * 32;
        #pragma unroll
        for (int l = 0; l < 4; l++) {
            int idx = tid + l * 256;
            int r = idx >> 3, c = (idx & 7) * 4;
            bool p = (m0 + r < M);
            int row = p ? (m0 + r) : 0;
            cp16(&As[s][r][c], &A[(size_t)row * lda + k0 + c], p);
        }
        #pragma unroll
        for (int l = 0; l < 4; l++) {
            int idx = tid + l * 256;
            int r = idx >> 5, c = (idx & 31) * 4;
            cp16(&Bs[s][r][c], &B[(size_t)(k0 + r) * ldb + n0 + c], true);
        }
    };

    load_tiles(0, 0);
    CP_COMMIT();

    for (int i = 0; i < T; i++) {
        int cur = i & 1;
        if (i + 1 < T) { load_tiles(i + 1, cur ^ 1); CP_COMMIT(); CP_WAIT(1); }
        else          { CP_WAIT(0); }
        __syncthreads();
        #pragma unroll
        for (int kk = 0; kk < 4; kk++) {
            uint32_t af[4][4], bf[4][2];
            #pragma unroll
            for (int mf = 0; mf < 4; mf++) {
                int mr = wm0 + mf * 16;
                af[mf][0] = As[cur][mr + g    ][kk * 8 + t];
                af[mf][1] = As[cur][mr + g + 8][kk * 8 + t];
                af[mf][2] = As[cur][mr + g    ][kk * 8 + t + 4];
                af[mf][3] = As[cur][mr + g + 8][kk * 8 + t + 4];
            }
            #pragma unroll
            for (int nf = 0; nf < 4; nf++) {
                bf[nf][0] = Bs[cur][kk * 8 + t    ][wn0 + nf * 8 + g];
                bf[nf][1] = Bs[cur][kk * 8 + t + 4][wn0 + nf * 8 + g];
            }
            #pragma unroll
            for (int mf = 0; mf < 4; mf++)
                #pragma unroll
                for (int nf = 0; nf < 4; nf++)
                    mma_tf32(acc[mf][nf], af[mf], bf[nf]);
        }
        __syncthreads();
    }

    #pragma unroll
    for (int mf = 0; mf < 4; mf++) {
        int row0 = m0 + wm0 + mf * 16 + g;
        int row1 = row0 + 8;
        #pragma unroll
        for (int nf = 0; nf < 4; nf++) {
            int n = n0 + wn0 + nf * 8 + 2 * t;
            float2 v0 = make_float2(acc[mf][nf][0], acc[mf][nf][1]);
            float2 v1 = make_float2(acc[mf][nf][2], acc[mf][nf][3]);
            if (row0 < M) *reinterpret_cast<float2*>(&C[(size_t)row0 * ldc + n]) = v0;
            if (row1 < M) *reinterpret_cast<float2*>(&C[(size_t)row1 * ldc + n]) = v1;
        }
    }
}

// ------- tf32 tall reduction: C[128, cols] += evc^T[128,N]*B[N,cols] --------
// CVTB: B is raw fp32; convert fragments on read (bit-identical to pre-round).
#define ATB_BLKS 64
template <bool CVTB>
__global__ void __launch_bounds__(256, 2) atb_k(
    const float* __restrict__ evc,
    const float* __restrict__ B, int ldb, long long bTs,
    float* __restrict__ C, int ldc, long long cTs)
{
    extern __shared__ uint32_t dyn[];
    uint32_t (*Es)[32][136] = reinterpret_cast<uint32_t(*)[32][136]>(dyn);
    uint32_t (*Hs)[32][136] = reinterpret_cast<uint32_t(*)[32][136]>(dyn + 2 * 32 * 136);

    B += (long long)blockIdx.z * bTs;
    C += (long long)blockIdx.z * cTs;
    const int noff = blockIdx.y * 128;

    const int chunk = (NN + ATB_BLKS - 1) / ATB_BLKS;
    const int nStart = blockIdx.x * chunk;
    const int nEnd = min(nStart + chunk, NN);
    const int iters = (chunk + 31) / 32;
    const int tid = threadIdx.x;
    const int lane = tid & 31;
    const int wid = tid >> 5;
    const int g = lane >> 2, t = lane & 3;
    const int wm0 = (wid & 1) * 64;
    const int wn0 = (wid >> 1) * 32;

    float acc[4][4][4] = {};

    auto load_tiles = [&](int it, int s) {
        int n0 = nStart + it * 32;
        #pragma unroll
        for (int l = 0; l < 4; l++) {
            int idx = tid + l * 256;
            int r = idx >> 5, c = (idx & 31) * 4;
            bool p = (n0 + r < nEnd);
            int row = p ? (n0 + r) : 0;
            cp16(&Es[s][r][c], &evc[(size_t)row * KK + c], p);
            cp16(&Hs[s][r][c], &B[(size_t)row * ldb + noff + c], p);
        }
    };

    load_tiles(0, 0);
    CP_COMMIT();

    for (int i = 0; i < iters; i++) {
        int cur = i & 1;
        if (i + 1 < iters) { load_tiles(i + 1, cur ^ 1); CP_COMMIT(); CP_WAIT(1); }
        else              { CP_WAIT(0); }
        __syncthreads();
        #pragma unroll
        for (int kk = 0; kk < 4; kk++) {
            uint32_t af[4][4], bf[4][2];
            #pragma unroll
            for (int mf = 0; mf < 4; mf++) {
                int mc = wm0 + mf * 16;
                af[mf][0] = Es[cur][kk * 8 + t    ][mc + g];
                af[mf][1] = Es[cur][kk * 8 + t    ][mc + g + 8];
                af[mf][2] = Es[cur][kk * 8 + t + 4][mc + g];
                af[mf][3] = Es[cur][kk * 8 + t + 4][mc + g + 8];
            }
            #pragma unroll
            for (int nf = 0; nf < 4; nf++) {
                uint32_t b0 = Hs[cur][kk * 8 + t    ][wn0 + nf * 8 + g];
                uint32_t b1 = Hs[cur][kk * 8 + t + 4][wn0 + nf * 8 + g];
                if (CVTB) { b0 = cvt_rna(b0); b1 = cvt_rna(b1); }
                bf[nf][0] = b0; bf[nf][1] = b1;
            }
            #pragma unroll
            for (int mf = 0; mf < 4; mf++)
                #pragma unroll
                for (int nf = 0; nf < 4; nf++)
                    mma_tf32(acc[mf][nf], af[mf], bf[nf]);
        }
        __syncthreads();
    }

    #pragma unroll
    for (int mf = 0; mf < 4; mf++) {
        int row0 = wm0 + mf * 16 + g;
        #pragma unroll
        for (int nf = 0; nf < 4; nf++) {
            int n = noff + wn0 + nf * 8 + 2 * t;
            float* p0 = &C[(size_t)row0 * ldc + n];
            float* p1 = &C[(size_t)(row0 + 8) * ldc + n];
            asm volatile("red.global.add.v2.f32 [%0], {%1,%2};"
                         :: "l"(p0), "f"(acc[mf][nf][0]), "f"(acc[mf][nf][1]) : "memory");
            asm volatile("red.global.add.v2.f32 [%0], {%1,%2};"
                         :: "l"(p1), "f"(acc[mf][nf][2]), "f"(acc[mf][nf][3]) : "memory");
        }
    }
}

// ---------------- graph: CSR build + gather ----------------------------------
__global__ void degi_k(const void* __restrict__ ei) {
    int e = blockIdx.x * blockDim.x + threadIdx.x;
    if (e < EE) atomicAdd(&g_degi[edge_at(ei, (long long)EE + e)], 1);
}
__global__ void dinv_k() {
    int n = blockIdx.x * blockDim.x + threadIdx.x;
    if (n < NN) g_deg[n] = rsqrtf((float)g_degi[n] + 1.0f);
}
__global__ void scan_k() {
    __shared__ int s[1024];
    int tid = threadIdx.x;
    const int per = (NN + 1023) / 1024;
    int start = tid * per, end = min(start + per, NN);
    int sum = 0;
    for (int i = start; i < end; i++) sum += g_degi[i];
    s[tid] = sum;
    __syncthreads();
    for (int off = 1; off < 1024; off <<= 1) {
        int v = 0;
        if (tid >= off) v = s[tid - off];
        __syncthreads();
        if (tid >= off) s[tid] += v;
        __syncthreads();
    }
    int base = s[tid] - sum;
    for (int i = start; i < end; i++) {
        g_off[i] = base; g_cur[i] = base;
        base += g_degi[i];
    }
    if (tid == 1023) g_off[NN] = base;
}
__global__ void fill_k(const void* __restrict__ ei) {
    int e = blockIdx.x * blockDim.x + threadIdx.x;
    if (e >= EE) return;
    int src = edge_at(ei, e);
    int dst = edge_at(ei, (long long)EE + e);
    int pos = atomicAdd(&g_cur[dst], 1);
    g_csrc[pos] = src;
}
__global__ void __launch_bounds__(128) gather_k(const float* __restrict__ x,
                                                const float* __restrict__ gcn_b) {
    const int n = blockIdx.x;
    const int c = threadIdx.x * 4;
    const int s0 = g_off[n], s1 = g_off[n + 1];
    const float dv = g_deg[n];
    float4 acc = make_float4(0.f, 0.f, 0.f, 0.f);
    int e = s0;
    #pragma unroll 1
    for (; e + 2 <= s1; e += 2) {
        int srcA = g_csrc[e], srcB = g_csrc[e + 1];
        float nA = dv * g_deg[srcA], nB = dv * g_deg[srcB];
        float4 vA = *reinterpret_cast<const float4*>(&g_xw[(size_t)srcA * DD + c]);
        float4 vB = *reinterpret_cast<const float4*>(&g_xw[(size_t)srcB * DD + c]);
        acc.x += nA * vA.x + nB * vB.x;
        acc.y += nA * vA.y + nB * vB.y;
        acc.z += nA * vA.z + nB * vB.z;
        acc.w += nA * vA.w + nB * vB.w;
    }
    if (e < s1) {
        int src = g_csrc[e];
        float nrm = dv * g_deg[src];
        float4 v = *reinterpret_cast<const float4*>(&g_xw[(size_t)src * DD + c]);
        acc.x += nrm * v.x; acc.y += nrm * v.y; acc.z += nrm * v.z; acc.w += nrm * v.w;
    }
    float4 xw = *reinterpret_cast<const float4*>(&g_xw[(size_t)n * DD + c]);
    float4 xr = *reinterpret_cast<const float4*>(&x[(size_t)n * DD + c]);
    float4 bb = *reinterpret_cast<const float4*>(&gcn_b[c]);
    float d2 = dv * dv;
    float4 o;
    o.x = xr.x + acc.x + d2 * xw.x + bb.x;
    o.y = xr.y + acc.y + d2 * xw.y + bb.y;
    o.z = xr.z + acc.z + d2 * xw.z + bb.z;
    o.w = xr.w + acc.w + d2 * xw.w + bb.w;
    *reinterpret_cast<float4*>(&g_bufL[(size_t)n * DD + c]) = o;
}
__global__ void stats0_k() {
    const int c = threadIdx.x;
    const int r0 = blockIdx.x * 128;
    const int rEnd = min(r0 + 128, NN);
    float s = 0.f, s2 = 0.f;
    for (int r = r0; r < rEnd; r++) {
        float v = g_bufL[(size_t)r * DD + c];
        s += v; s2 += v * v;
    }
    atomicAdd(&g_stats[0 * DD + c], s);
    atomicAdd(&g_stats[1 * DD + c], s2);
}

__global__ void finalize_k(int bn, const float* __restrict__ gamma, const float* __restrict__ beta) {
    int c = threadIdx.x;
    float s  = g_stats[(bn * 2 + 0) * DD + c];
    float s2 = g_stats[(bn * 2 + 1) * DD + c];
    float m = s * (1.0f / NN);
    float var = s2 * (1.0f / NN) - m * m;
    float a = gamma[c] * rsqrtf(var + EPSC);
    g_coef[(bn * 2 + 0) * DD + c] = a;
    g_coef[(bn * 2 + 1) * DD + c] = beta[c] - m * a;
}

__global__ void apply_sum_k() {
    int i = blockIdx.x * blockDim.x + threadIdx.x;
    if (i >= NN * DD / 2) return;
    int base = i * 2;
    int c = base & (DD - 1);
    float v0 = g_bufL[base] * g_coef[c] + g_coef[DD + c]
             + g_bufA[base] * g_coef[2 * DD + c] + g_coef[3 * DD + c];
    float v1 = g_bufL[base + 1] * g_coef[c + 1] + g_coef[DD + c + 1]
             + g_bufA[base + 1] * g_coef[2 * DD + c + 1] + g_coef[3 * DD + c + 1];
    g_h[base] = v0; g_h[base + 1] = v1;
    *reinterpret_cast<uint32_t*>(&g_hb[base]) = packbf(v0, v1);
}
__global__ void bn2_apply_k(float* __restrict__ out) {
    int idx = blockIdx.x * blockDim.x + threadIdx.x;
    if (idx >= NN * DD) return;
    int c = idx & (DD - 1);
    out[idx] = g_ff[idx] * g_coef[4 * DD + c] + g_coef[5 * DD + c];
}

// ---------------- wave helpers ----------------------------------------------
__global__ void pack_w_k(const float* __restrict__ linW, const float* __restrict__ fW) {
    int idx = blockIdx.x * blockDim.x + threadIdx.x;
    if (idx >= DD * DD) return;
    int d = idx >> 9, j = idx & 511;
    int t = j >> 7, s = j & 127;
    g_linWp[idx] = tf32r(linW[t * (DD * SSc) + d * SSc + s]);
    g_fWt[idx]   = tf32r(fW[idx]);
}
__global__ void post_u_k(const float* __restrict__ fs, const float* __restrict__ linB) {
    int idx = blockIdx.x * blockDim.x + threadIdx.x;
    if (idx >= (KK / 2) * DD) return;
    int kp = idx >> 9, j = idx & 511;
    int t = j >> 7, s = j & 127;
    float bl = linB[t * SSc + s];
    int k0 = 2 * kp, k1 = 2 * kp + 1;
    float v0 = fs[k0 * TJc + t] * (g_uraw[k0 * DD + j] + g_esum[k0] * bl);
    float v1 = fs[k1 * TJc + t] * (g_uraw[k1 * DD + j] + g_esum[k1] * bl);
    g_ubp[idx] = packbf(v0, v1);
}
__global__ void scale_u2_k(const float* __restrict__ fs) {
    int idx = blockIdx.x * blockDim.x + threadIdx.x;
    if (idx >= KK * DD) return;
    int k = idx >> 9, t = (idx & 511) >> 7;
    g_u2[idx] = tf32r(g_u2[idx] * fs[k * TJc + t]);
}

// ---------------- streams/events (created before harness checkpoints) --------
static cudaStream_t s_gcn = nullptr;
static cudaEvent_t ev_fork = nullptr, ev_xw = nullptr, ev_join = nullptr;
namespace { struct StreamInit {
    StreamInit() {
        cudaStreamCreateWithFlags(&s_gcn, cudaStreamNonBlocking);
        cudaEventCreateWithFlags(&ev_fork, cudaEventDisableTiming);
        cudaEventCreateWithFlags(&ev_xw,   cudaEventDisableTiming);
        cudaEventCreateWithFlags(&ev_join, cudaEventDisableTiming);
    }
} s_init; }

// ---------------- launch -----------------------------------------------------
#define GSYM(p, ty, s) do { void* _t; cudaGetSymbolAddress(&_t, s); (p) = (ty)_t; } while (0)

extern "C" void kernel_launch(void* const* d_in, const int* in_sizes, int n_in,
                              void* d_out, int out_size) {
    const float* x        = (const float*)d_in[0];
    const void*  ei       = d_in[1];
    const float* evc      = (const float*)d_in[2];
    const float* fs       = (const float*)d_in[3];
    const float* gcn_W    = (const float*)d_in[4];
    const float* gcn_b    = (const float*)d_in[5];
    const float* lin_W    = (const float*)d_in[6];
    const float* lin_b    = (const float*)d_in[7];
    const float* fusion_W = (const float*)d_in[8];
    const float* fusion_b = (const float*)d_in[9];
    const float* bn1l_g   = (const float*)d_in[10];
    const float* bn1l_b   = (const float*)d_in[11];
    const float* bn1a_g   = (const float*)d_in[12];
    const float* bn1a_b   = (const float*)d_in[13];
    const float* bn2_g    = (const float*)d_in[14];
    const float* bn2_b    = (const float*)d_in[15];
    const float* ff1_W    = (const float*)d_in[16];
    const float* ff1_b    = (const float*)d_in[17];
    const float* ff2_W    = (const float*)d_in[18];
    const float* ff2_b    = (const float*)d_in[19];
    float* out = (float*)d_out;

    float *p_xw, *p_bufL, *p_v, *p_bufA, *p_h, *p_ff, *p_evct;
    float *p_xe, *p_uraw, *p_u2, *p_W2, *p_linWp, *p_fWt;
    __nv_bfloat16 *p_xb, *p_evcb, *p_hb, *p_midb;
    uint32_t *p_gWbp, *p_f1Wbp, *p_f2Wbp, *p_W2bp, *p_ubp;
    GSYM(p_xw, float*, g_xw);     GSYM(p_bufL, float*, g_bufL); GSYM(p_v, float*, g_v);
    GSYM(p_bufA, float*, g_bufA); GSYM(p_h, float*, g_h);       GSYM(p_ff, float*, g_ff);
    GSYM(p_evct, float*, g_evct);
    GSYM(p_xe, float*, g_xe);     GSYM(p_uraw, float*, g_uraw);
    GSYM(p_u2, float*, g_u2);     GSYM(p_W2, float*, g_W2);
    GSYM(p_linWp, float*, g_linWp); GSYM(p_fWt, float*, g_fWt);
    GSYM(p_xb, __nv_bfloat16*, g_xb);   GSYM(p_evcb, __nv_bfloat16*, g_evcb);
    GSYM(p_hb, __nv_bfloat16*, g_hb);   GSYM(p_midb, __nv_bfloat16*, g_midb);
    GSYM(p_gWbp, uint32_t*, g_gWbp);    GSYM(p_f1Wbp, uint32_t*, g_f1Wbp);
    GSYM(p_f2Wbp, uint32_t*, g_f2Wbp);  GSYM(p_W2bp, uint32_t*, g_W2bp);
    GSYM(p_ubp, uint32_t*, g_ubp);

    const int GEMM_SMEM = (2 * 128 * 36 + 2 * 32 * 136) * 4;
    const int ATB_SMEM  = (2 * 32 * 136 * 2) * 4;
    cudaFuncSetAttribute(tcgemm_k, cudaFuncAttributeMaxDynamicSharedMemorySize, GEMM_SMEM);
    cudaFuncSetAttribute(atb_k<false>, cudaFuncAttributeMaxDynamicSharedMemorySize, ATB_SMEM);
    cudaFuncSetAttribute(atb_k<true>,  cudaFuncAttributeMaxDynamicSharedMemorySize, ATB_SMEM);

    const int MB = (NN + 127) / 128;
    dim3 gD(4, MB);
    dim3 gF(8, MB);
    dim3 gV(1, MB, TJc);
    dim3 gTiny(4, 1);
    dim3 gAtbX(ATB_BLKS, 4, 1);
    dim3 gAtbU(ATB_BLKS, 1, TJc);

    detect_k<<<1, 256>>>((const int*)ei);
    zero_scratch_k<<<1024, 256>>>();

    // ---- fork: GCN CSR build on s_gcn ----
    cudaEventRecord(ev_fork, 0);
    cudaStreamWaitEvent(s_gcn, ev_fork, 0);
    degi_k<<<(EE + 255) / 256, 256, 0, s_gcn>>>(ei);
    dinv_k<<<(NN + 255) / 256, 256, 0, s_gcn>>>();
    scan_k<<<1, 1024, 0, s_gcn>>>();
    fill_k<<<(EE + 255) / 256, 256, 0, s_gcn>>>(ei);

    // ---- main stream: packs/rounds + xw GEMM ----
    pack_w_k<<<(DD * DD + 255) / 256, 256>>>(lin_W, fusion_W);
    packpairs_k<<<((DD / 2) * DD + 255) / 256, 256>>>(gcn_W, p_gWbp, DD, (DD / 2) * DD);
    packpairs_k<<<((DD / 2) * DD2 + 255) / 256, 256>>>(ff1_W, p_f1Wbp, DD2, (DD / 2) * DD2);
    packpairs_k<<<((DD2 / 2) * DD + 255) / 256, 256>>>(ff2_W, p_f2Wbp, DD, (DD2 / 2) * DD);
    round_k<<<256, 256>>>(evc, p_evct, (long long)NN * KK);
    tobf_k<<<1024, 256>>>(x, p_xb, (long long)NN * DD);
    tobf_k<<<256, 256>>>(evc, p_evcb, (long long)NN * KK);
    bfgemm_k<false, false, false, false, false><<<gD, 256>>>(
        p_xb, DD, p_gWbp, DD, 0, p_xw, DD, 0, nullptr, NN, DD, nullptr, 0);
    cudaEventRecord(ev_xw, 0);

    // ---- s_gcn: gather + BN0 stats (needs xw) ----
    cudaStreamWaitEvent(s_gcn, ev_xw, 0);
    gather_k<<<NN, 128, 0, s_gcn>>>(x, gcn_b);
    stats0_k<<<MB, DD, 0, s_gcn>>>();
    cudaEventRecord(ev_join, s_gcn);

    // ---- main stream: wave branch (overlaps with s_gcn) ----
    colsum_k<<<(NN + 499) / 500, KK>>>(evc);
    atb_k<true><<<gAtbX, 256, ATB_SMEM>>>(p_evct, x, DD, 0, p_xe, DD, 0);
    round_k<<<64, 256>>>(p_xe, p_xe, KK * DD);
    tcgemm_k<<<gTiny, 256, GEMM_SMEM>>>(p_xe, DD, p_linWp, DD, p_uraw, DD, KK, DD);
    post_u_k<<<((KK / 2) * DD + 255) / 256, 256>>>(fs, lin_b);
    bfgemm_k<false, true, true, false, false><<<gV, 256>>>(
        p_evcb, KK, p_ubp, DD, 128, p_v, SSc, (long long)NN * SSc, nullptr, NN, KK, nullptr, 0);
    atb_k<false><<<gAtbU, 256, ATB_SMEM>>>(p_evct, p_v, SSc, (long long)NN * SSc, p_u2, DD, 128);
    scale_u2_k<<<(KK * DD + 255) / 256, 256>>>(fs);
    tcgemm_k<<<gTiny, 256, GEMM_SMEM>>>(p_u2, DD, p_fWt, DD, p_W2, DD, KK, DD);
    packpairs_k<<<((KK / 2) * DD + 255) / 256, 256>>>(p_W2, p_W2bp, DD, (KK / 2) * DD);
    bfgemm_k<true, true, false, false, true><<<gD, 256>>>(
        p_evcb, KK, p_W2bp, DD, 0, p_bufA, DD, 0, fusion_b, NN, KK, x, 1);

    // ---- join + BN ----
    cudaStreamWaitEvent(0, ev_join, 0);
    finalize_k<<<1, DD>>>(0, bn1l_g, bn1l_b);
    finalize_k<<<1, DD>>>(1, bn1a_g, bn1a_b);
    apply_sum_k<<<(NN * DD / 2 + 255) / 256, 256>>>();

    // ---- feed-forward ----
    bfgemm_k<true, true, false, true, false><<<gF, 256>>>(
        p_hb, DD, p_f1Wbp, DD2, 0, p_midb, DD2, 0, ff1_b, NN, DD, nullptr, 0);
    bfgemm_k<true, false, false, false, true><<<gD, 256>>>(
        p_midb, DD2, p_f2Wbp, DD, 0, p_ff, DD, 0, ff2_b, NN, DD2, p_h, 2);
    finalize_k<<<1, DD>>>(2, bn2_g, bn2_b);
    bn2_apply_k<<<(NN * DD + 255) / 256, 256>>>(out);
}

// round 11
// speedup vs baseline: 6.0717x; 1.0964x over previous
#include <cuda_runtime.h>
#include <cuda_bf16.h>
#include <cstdint>

#define NN  50000
#define EE  800000
#define DD  512
#define KK  128
#define TJc 4
#define SSc 128
#define DD2 1024
#define EPSC 1e-5f

// ---------------- scratch (device globals) -----------------------------------
__device__ float g_xw  [(size_t)NN * DD];
__device__ float g_bufL[(size_t)NN * DD];
__device__ float g_v   [(size_t)NN * DD];          // v [N, 512] (t*128+s)
__device__ float g_bufA[(size_t)NN * DD];
__device__ float g_h   [(size_t)NN * DD];
__device__ float g_ff  [(size_t)NN * DD];
__device__ float g_evct[(size_t)NN * KK];
__device__ __nv_bfloat16 g_xb  [(size_t)NN * DD];
__device__ __nv_bfloat16 g_evcb[(size_t)NN * KK];
__device__ __nv_bfloat16 g_hb  [(size_t)NN * DD];
__device__ __nv_bfloat16 g_midb[(size_t)NN * DD2];
__device__ uint32_t g_gWbp [(DD / 2) * DD];
__device__ uint32_t g_f1Wbp[(DD / 2) * DD2];
__device__ uint32_t g_f2Wbp[(DD2 / 2) * DD];
__device__ uint32_t g_W2bp [(KK / 2) * DD];
__device__ uint32_t g_ubp  [(KK / 2) * DD];
__device__ float g_deg [NN];
__device__ int   g_degi[NN];
__device__ int   g_off [NN + 1];
__device__ int   g_cur [NN];
__device__ int   g_csrc[EE];
__device__ float g_esum[KK];
__device__ float g_xe  [KK * DD];
__device__ float g_uraw[KK * DD];
__device__ float g_u2  [KK * DD];
__device__ float g_W2  [KK * DD];
__device__ float g_stats[6 * DD];
__device__ float g_coef [6 * DD];
__device__ float g_linWp[DD * DD];
__device__ float g_fWt  [DD * DD];
__device__ int   g_is64;

// ---------------- helpers -----------------------------------------------------
__device__ __forceinline__ float tf32r(float f) {
    uint32_t u; asm("cvt.rna.tf32.f32 %0, %1;" : "=r"(u) : "f"(f));
    return __uint_as_float(u);
}
__device__ __forceinline__ uint32_t cvt_rna(uint32_t x) {
    uint32_t u; float f = __uint_as_float(x);
    asm("cvt.rna.tf32.f32 %0, %1;" : "=r"(u) : "f"(f)); return u;
}
__device__ __forceinline__ uint32_t packbf(float lo, float hi) {
    uint32_t r; asm("cvt.rn.bf16x2.f32 %0, %1, %2;" : "=r"(r) : "f"(hi), "f"(lo));
    return r;
}
__device__ __forceinline__ void mma_tf32(float* c, const uint32_t* a, const uint32_t* b) {
    asm volatile("mma.sync.aligned.m16n8k8.row.col.f32.tf32.tf32.f32 "
        "{%0,%1,%2,%3}, {%4,%5,%6,%7}, {%8,%9}, {%0,%1,%2,%3};"
        : "+f"(c[0]), "+f"(c[1]), "+f"(c[2]), "+f"(c[3])
        : "r"(a[0]), "r"(a[1]), "r"(a[2]), "r"(a[3]), "r"(b[0]), "r"(b[1]));
}
__device__ __forceinline__ void mma_bf16(float* c, const uint32_t* a, const uint32_t* b) {
    asm volatile("mma.sync.aligned.m16n8k16.row.col.f32.bf16.bf16.f32 "
        "{%0,%1,%2,%3}, {%4,%5,%6,%7}, {%8,%9}, {%0,%1,%2,%3};"
        : "+f"(c[0]), "+f"(c[1]), "+f"(c[2]), "+f"(c[3])
        : "r"(a[0]), "r"(a[1]), "r"(a[2]), "r"(a[3]), "r"(b[0]), "r"(b[1]));
}
__device__ __forceinline__ void cp16(void* sdst, const void* gsrc, bool pred) {
    uint32_t sa = (uint32_t)__cvta_generic_to_shared(sdst);
    int sz = pred ? 16 : 0;
    asm volatile("cp.async.cg.shared.global [%0], [%1], 16, %2;"
                 :: "r"(sa), "l"(gsrc), "r"(sz));
}
#define CP_COMMIT() asm volatile("cp.async.commit_group;")
#define CP_WAIT(n)  asm volatile("cp.async.wait_group %0;" :: "n"(n))

// ---------------- edge-index dtype detection --------------------------------
__global__ void detect_k(const int* __restrict__ ei32) {
    __shared__ int any;
    if (threadIdx.x == 0) any = 0;
    __syncthreads();
    int v = 0;
    for (int i = threadIdx.x; i < 1024; i += blockDim.x)
        v |= ei32[2 * i + 1];
    if (v) atomicOr(&any, 1);
    __syncthreads();
    if (threadIdx.x == 0) g_is64 = (any == 0) ? 1 : 0;
}
__device__ __forceinline__ int edge_at(const void* ei, long long pos) {
    return g_is64 ? (int)((const long long*)ei)[pos] : ((const int*)ei)[pos];
}

// ---------------- zero / round / pack helpers --------------------------------
__global__ void zero_scratch_k() {
    int stride = gridDim.x * blockDim.x;
    int i0 = blockIdx.x * blockDim.x + threadIdx.x;
    for (int i = i0; i < NN; i += stride) g_degi[i] = 0;
    for (int i = i0; i < KK * DD; i += stride) { g_xe[i] = 0.f; g_u2[i] = 0.f; }
    for (int i = i0; i < 6 * DD; i += stride) g_stats[i] = 0.f;
    for (int i = i0; i < KK; i += stride) g_esum[i] = 0.f;
}
__global__ void round_k(const float* __restrict__ in, float* __restrict__ o, long long n) {
    long long i = (long long)blockIdx.x * blockDim.x + threadIdx.x;
    long long stride = (long long)gridDim.x * blockDim.x;
    for (; i < n / 4; i += stride) {
        float4 v = reinterpret_cast<const float4*>(in)[i];
        v.x = tf32r(v.x); v.y = tf32r(v.y); v.z = tf32r(v.z); v.w = tf32r(v.w);
        reinterpret_cast<float4*>(o)[i] = v;
    }
}
__global__ void tobf_k(const float* __restrict__ in, __nv_bfloat16* __restrict__ o, long long n) {
    long long i = (long long)blockIdx.x * blockDim.x + threadIdx.x;
    long long stride = (long long)gridDim.x * blockDim.x;
    for (; i < n / 4; i += stride) {
        float4 v = reinterpret_cast<const float4*>(in)[i];
        uint2 p = make_uint2(packbf(v.x, v.y), packbf(v.z, v.w));
        reinterpret_cast<uint2*>(o)[i] = p;
    }
}
__global__ void packpairs_k(const float* __restrict__ W, uint32_t* __restrict__ Wp,
                            int Ncols, int total) {
    int idx = blockIdx.x * blockDim.x + threadIdx.x;
    if (idx >= total) return;
    int kp = idx / Ncols, n = idx - kp * Ncols;
    Wp[idx] = packbf(W[(size_t)(2 * kp) * Ncols + n], W[(size_t)(2 * kp + 1) * Ncols + n]);
}
__global__ void colsum_k(const float* __restrict__ evc) {
    int c = threadIdx.x;
    int r0 = blockIdx.x * 500;
    int r1 = min(r0 + 500, NN);
    float s = 0.f;
    for (int r = r0; r < r1; r++) s += evc[(size_t)r * KK + c];
    atomicAdd(&g_esum[c], s);
}

// ---------------- bf16 tensor-core GEMM (k64 tiles, dyn smem) ----------------
template <bool BIAS, bool RELU, bool RND, bool OUTBF, bool ADDST>
__global__ void __launch_bounds__(256, 2) bfgemm_k(
    const __nv_bfloat16* __restrict__ A, int lda,
    const uint32_t* __restrict__ Bp, int ldb, long long bTs,
    void* __restrict__ Cv, int ldc, long long cTs,
    const float* __restrict__ bias,
    int M, int Kd,
    const float* __restrict__ Xadd, int bn)
{
    extern __shared__ uint32_t dynb[];
    uint32_t (*AsB)[128][36] = reinterpret_cast<uint32_t(*)[128][36]>(dynb);
    uint32_t (*BsB)[32][136] = reinterpret_cast<uint32_t(*)[32][136]>(dynb + 2 * 128 * 36);

    Bp += (long long)blockIdx.z * bTs;

    const int m0 = blockIdx.y * 128;
    const int n0 = blockIdx.x * 128;
    const int tid = threadIdx.x;
    const int lane = tid & 31;
    const int wid = tid >> 5;
    const int g = lane >> 2, t = lane & 3;
    const int wm0 = (wid & 1) * 64;
    const int wn0 = (wid >> 1) * 32;

    float acc[4][4][4] = {};
    const int T = Kd >> 6;

    auto load_tiles = [&](int it, int s) {
        int k0 = it * 64;
        #pragma unroll
        for (int l = 0; l < 4; l++) {               // A: 128 x 64 bf16
            int idx = tid + l * 256;
            int r = idx >> 3, ch = idx & 7;
            bool p = (m0 + r < M);
            int row = p ? (m0 + r) : 0;
            cp16(&AsB[s][r][ch * 4], &A[(size_t)row * lda + k0 + ch * 8], p);
        }
        #pragma unroll
        for (int l = 0; l < 4; l++) {               // B: 32 pair-rows x 128 u32
            int idx = tid + l * 256;
            int r = idx >> 5, c = (idx & 31) * 4;
            cp16(&BsB[s][r][c], &Bp[(size_t)(k0 / 2 + r) * ldb + n0 + c], true);
        }
    };

    load_tiles(0, 0);
    CP_COMMIT();

    for (int i = 0; i < T; i++) {
        int cur = i & 1;
        if (i + 1 < T) { load_tiles(i + 1, cur ^ 1); CP_COMMIT(); CP_WAIT(1); }
        else          { CP_WAIT(0); }
        __syncthreads();
        #pragma unroll
        for (int kk = 0; kk < 4; kk++) {            // 4 x k16 per k64 tile
            uint32_t af[4][4], bf[4][2];
            #pragma unroll
            for (int mf = 0; mf < 4; mf++) {
                int mr = wm0 + mf * 16;
                af[mf][0] = AsB[cur][mr + g    ][kk * 8 + t];
                af[mf][1] = AsB[cur][mr + g + 8][kk * 8 + t];
                af[mf][2] = AsB[cur][mr + g    ][kk * 8 + t + 4];
                af[mf][3] = AsB[cur][mr + g + 8][kk * 8 + t + 4];
            }
            #pragma unroll
            for (int nf = 0; nf < 4; nf++) {
                bf[nf][0] = BsB[cur][kk * 8 + t    ][wn0 + nf * 8 + g];
                bf[nf][1] = BsB[cur][kk * 8 + t + 4][wn0 + nf * 8 + g];
            }
            #pragma unroll
            for (int mf = 0; mf < 4; mf++)
                #pragma unroll
                for (int nf = 0; nf < 4; nf++)
                    mma_bf16(acc[mf][nf], af[mf], bf[nf]);
        }
        __syncthreads();
    }

    float* C = (float*)Cv + (long long)blockIdx.z * cTs;
    __nv_bfloat16* Cb = (__nv_bfloat16*)Cv + (long long)blockIdx.z * cTs;
    float cs[4][2] = {}, cq[4][2] = {};

    #pragma unroll
    for (int mf = 0; mf < 4; mf++) {
        int row0 = m0 + wm0 + mf * 16 + g;
        int row1 = row0 + 8;
        #pragma unroll
        for (int nf = 0; nf < 4; nf++) {
            int n = n0 + wn0 + nf * 8 + 2 * t;
            float b0 = 0.f, b1 = 0.f;
            if (BIAS) { b0 = bias[n]; b1 = bias[n + 1]; }
            float2 v0 = make_float2(acc[mf][nf][0] + b0, acc[mf][nf][1] + b1);
            float2 v1 = make_float2(acc[mf][nf][2] + b0, acc[mf][nf][3] + b1);
            if (RELU) {
                v0.x = fmaxf(v0.x, 0.f); v0.y = fmaxf(v0.y, 0.f);
                v1.x = fmaxf(v1.x, 0.f); v1.y = fmaxf(v1.y, 0.f);
            }
            if (RND) {
                v0.x = tf32r(v0.x); v0.y = tf32r(v0.y);
                v1.x = tf32r(v1.x); v1.y = tf32r(v1.y);
            }
            if (row0 < M) {
                if (ADDST) {
                    v0.x += Xadd[(size_t)row0 * ldc + n];
                    v0.y += Xadd[(size_t)row0 * ldc + n + 1];
                    cs[nf][0] += v0.x; cq[nf][0] += v0.x * v0.x;
                    cs[nf][1] += v0.y; cq[nf][1] += v0.y * v0.y;
                }
                if (OUTBF) *reinterpret_cast<uint32_t*>(&Cb[(size_t)row0 * ldc + n]) = packbf(v0.x, v0.y);
                else       *reinterpret_cast<float2*>(&C[(size_t)row0 * ldc + n]) = v0;
            }
            if (row1 < M) {
                if (ADDST) {
                    v1.x += Xadd[(size_t)row1 * ldc + n];
                    v1.y += Xadd[(size_t)row1 * ldc + n + 1];
                    cs[nf][0] += v1.x; cq[nf][0] += v1.x * v1.x;
                    cs[nf][1] += v1.y; cq[nf][1] += v1.y * v1.y;
                }
                if (OUTBF) *reinterpret_cast<uint32_t*>(&Cb[(size_t)row1 * ldc + n]) = packbf(v1.x, v1.y);
                else       *reinterpret_cast<float2*>(&C[(size_t)row1 * ldc + n]) = v1;
            }
        }
    }

    if (ADDST) {
        #pragma unroll
        for (int nf = 0; nf < 4; nf++)
            #pragma unroll
            for (int c2 = 0; c2 < 2; c2++) {
                float s = cs[nf][c2], q = cq[nf][c2];
                #pragma unroll
                for (int off = 4; off < 32; off <<= 1) {
                    s += __shfl_xor_sync(0xffffffffu, s, off);
                    q += __shfl_xor_sync(0xffffffffu, q, off);
                }
                if (g == 0) {
                    int n = n0 + wn0 + nf * 8 + 2 * t + c2;
                    atomicAdd(&g_stats[(bn * 2 + 0) * DD + n], s);
                    atomicAdd(&g_stats[(bn * 2 + 1) * DD + n], q);
                }
            }
    }
}

// ---------------- tf32 GEMM (tiny 128-row GEMMs) -----------------------------
__global__ void __launch_bounds__(256, 2) tcgemm_k(
    const float* __restrict__ A, int lda,
    const float* __restrict__ B, int ldb,
    float* __restrict__ C, int ldc,
    int M, int Kd)
{
    extern __shared__ uint32_t dyn[];
    uint32_t (*As)[128][36]  = reinterpret_cast<uint32_t(*)[128][36]>(dyn);
    uint32_t (*Bs)[32][136]  = reinterpret_cast<uint32_t(*)[32][136]>(dyn + 2 * 128 * 36);

    const int m0 = blockIdx.y * 128;
    const int n0 = blockIdx.x * 128;
    const int tid = threadIdx.x;
    const int lane = tid & 31;
    const int wid = tid >> 5;
    const int g = lane >> 2, t = lane & 3;
    const int wm0 = (wid & 1) * 64;
    const int wn0 = (wid >> 1) * 32;

    float acc[4][4][4] = {};
    const int T = Kd >> 5;

    auto load_tiles = [&](int it, int s) {
        int k0 = it * 32;
        #pragma unroll
        for (int l = 0; l < 4; l++) {
            int idx = tid + l * 256;
            int r = idx >> 3, c = (idx & 7) * 4;
            bool p = (m0 + r < M);
            int row = p ? (m0 + r) : 0;
            cp16(&As[s][r][c], &A[(size_t)row * lda + k0 + c], p);
        }
        #pragma unroll
        for (int l = 0; l < 4; l++) {
            int idx = tid + l * 256;
            int r = idx >> 5, c = (idx & 31) * 4;
            cp16(&Bs[s][r][c], &B[(size_t)(k0 + r) * ldb + n0 + c], true);
        }
    };

    load_tiles(0, 0);
    CP_COMMIT();

    for (int i = 0; i < T; i++) {
        int cur = i & 1;
        if (i + 1 < T) { load_tiles(i + 1, cur ^ 1); CP_COMMIT(); CP_WAIT(1); }
        else          { CP_WAIT(0); }
        __syncthreads();
        #pragma unroll
        for (int kk = 0; kk < 4; kk++) {
            uint32_t af[4][4], bf[4][2];
            #pragma unroll
            for (int mf = 0; mf < 4; mf++) {
                int mr = wm0 + mf * 16;
                af[mf][0] = As[cur][mr + g    ][kk * 8 + t];
                af[mf][1] = As[cur][mr + g + 8][kk * 8 + t];
                af[mf][2] = As[cur][mr + g    ][kk * 8 + t + 4];
                af[mf][3] = As[cur][mr + g + 8][kk * 8 + t + 4];
            }
            #pragma unroll
            for (int nf = 0; nf < 4; nf++) {
                bf[nf][0] = Bs[cur][kk * 8 + t    ][wn0 + nf * 8 + g];
                bf[nf][1] = Bs[cur][kk * 8 + t + 4][wn0 + nf * 8 + g];
            }
            #pragma unroll
            for (int mf = 0; mf < 4; mf++)
                #pragma unroll
                for (int nf = 0; nf < 4; nf++)
                    mma_tf32(acc[mf][nf], af[mf], bf[nf]);
        }
        __syncthreads();
    }

    #pragma unroll
    for (int mf = 0; mf < 4; mf++) {
        int row0 = m0 + wm0 + mf * 16 + g;
        int row1 = row0 + 8;
        #pragma unroll
        for (int nf = 0; nf < 4; nf++) {
            int n = n0 + wn0 + nf * 8 + 2 * t;
            float2 v0 = make_float2(acc[mf][nf][0], acc[mf][nf][1]);
            float2 v1 = make_float2(acc[mf][nf][2], acc[mf][nf][3]);
            if (row0 < M) *reinterpret_cast<float2*>(&C[(size_t)row0 * ldc + n]) = v0;
            if (row1 < M) *reinterpret_cast<float2*>(&C[(size_t)row1 * ldc + n]) = v1;
        }
    }
}

// ------- tf32 tall reduction: C[128, cols] += evc^T[128,N]*B[N,cols] --------
#define ATB_BLKS 64
template <bool CVTB>
__global__ void __launch_bounds__(256, 2) atb_k(
    const float* __restrict__ evc,
    const float* __restrict__ B, int ldb,
    float* __restrict__ C, int ldc)
{
    extern __shared__ uint32_t dyn[];
    uint32_t (*Es)[32][136] = reinterpret_cast<uint32_t(*)[32][136]>(dyn);
    uint32_t (*Hs)[32][136] = reinterpret_cast<uint32_t(*)[32][136]>(dyn + 2 * 32 * 136);

    const int noff = blockIdx.y * 128;

    const int chunk = (NN + ATB_BLKS - 1) / ATB_BLKS;
    const int nStart = blockIdx.x * chunk;
    const int nEnd = min(nStart + chunk, NN);
    const int iters = (chunk + 31) / 32;
    const int tid = threadIdx.x;
    const int lane = tid & 31;
    const int wid = tid >> 5;
    const int g = lane >> 2, t = lane & 3;
    const int wm0 = (wid & 1) * 64;
    const int wn0 = (wid >> 1) * 32;

    float acc[4][4][4] = {};

    auto load_tiles = [&](int it, int s) {
        int n0 = nStart + it * 32;
        #pragma unroll
        for (int l = 0; l < 4; l++) {
            int idx = tid + l * 256;
            int r = idx >> 5, c = (idx & 31) * 4;
            bool p = (n0 + r < nEnd);
            int row = p ? (n0 + r) : 0;
            cp16(&Es[s][r][c], &evc[(size_t)row * KK + c], p);
            cp16(&Hs[s][r][c], &B[(size_t)row * ldb + noff + c], p);
        }
    };

    load_tiles(0, 0);
    CP_COMMIT();

    for (int i = 0; i < iters; i++) {
        int cur = i & 1;
        if (i + 1 < iters) { load_tiles(i + 1, cur ^ 1); CP_COMMIT(); CP_WAIT(1); }
        else              { CP_WAIT(0); }
        __syncthreads();
        #pragma unroll
        for (int kk = 0; kk < 4; kk++) {
            uint32_t af[4][4], bf[4][2];
            #pragma unroll
            for (int mf = 0; mf < 4; mf++) {
                int mc = wm0 + mf * 16;
                af[mf][0] = Es[cur][kk * 8 + t    ][mc + g];
                af[mf][1] = Es[cur][kk * 8 + t    ][mc + g + 8];
                af[mf][2] = Es[cur][kk * 8 + t + 4][mc + g];
                af[mf][3] = Es[cur][kk * 8 + t + 4][mc + g + 8];
            }
            #pragma unroll
            for (int nf = 0; nf < 4; nf++) {
                uint32_t b0 = Hs[cur][kk * 8 + t    ][wn0 + nf * 8 + g];
                uint32_t b1 = Hs[cur][kk * 8 + t + 4][wn0 + nf * 8 + g];
                if (CVTB) { b0 = cvt_rna(b0); b1 = cvt_rna(b1); }
                bf[nf][0] = b0; bf[nf][1] = b1;
            }
            #pragma unroll
            for (int mf = 0; mf < 4; mf++)
                #pragma unroll
                for (int nf = 0; nf < 4; nf++)
                    mma_tf32(acc[mf][nf], af[mf], bf[nf]);
        }
        __syncthreads();
    }

    #pragma unroll
    for (int mf = 0; mf < 4; mf++) {
        int row0 = wm0 + mf * 16 + g;
        #pragma unroll
        for (int nf = 0; nf < 4; nf++) {
            int n = noff + wn0 + nf * 8 + 2 * t;
            float* p0 = &C[(size_t)row0 * ldc + n];
            float* p1 = &C[(size_t)(row0 + 8) * ldc + n];
            asm volatile("red.global.add.v2.f32 [%0], {%1,%2};"
                         :: "l"(p0), "f"(acc[mf][nf][0]), "f"(acc[mf][nf][1]) : "memory");
            asm volatile("red.global.add.v2.f32 [%0], {%1,%2};"
                         :: "l"(p1), "f"(acc[mf][nf][2]), "f"(acc[mf][nf][3]) : "memory");
        }
    }
}

// ---------------- graph: CSR build + gather ----------------------------------
__global__ void degi_k(const void* __restrict__ ei) {
    int e = blockIdx.x * blockDim.x + threadIdx.x;
    if (e < EE) atomicAdd(&g_degi[edge_at(ei, (long long)EE + e)], 1);
}
__global__ void dinv_k() {
    int n = blockIdx.x * blockDim.x + threadIdx.x;
    if (n < NN) g_deg[n] = rsqrtf((float)g_degi[n] + 1.0f);
}
__global__ void scan_k() {
    __shared__ int s[1024];
    int tid = threadIdx.x;
    const int per = (NN + 1023) / 1024;
    int start = tid * per, end = min(start + per, NN);
    int sum = 0;
    for (int i = start; i < end; i++) sum += g_degi[i];
    s[tid] = sum;
    __syncthreads();
    for (int off = 1; off < 1024; off <<= 1) {
        int v = 0;
        if (tid >= off) v = s[tid - off];
        __syncthreads();
        if (tid >= off) s[tid] += v;
        __syncthreads();
    }
    int base = s[tid] - sum;
    for (int i = start; i < end; i++) {
        g_off[i] = base; g_cur[i] = base;
        base += g_degi[i];
    }
    if (tid == 1023) g_off[NN] = base;
}
__global__ void fill_k(const void* __restrict__ ei) {
    int e = blockIdx.x * blockDim.x + threadIdx.x;
    if (e >= EE) return;
    int src = edge_at(ei, e);
    int dst = edge_at(ei, (long long)EE + e);
    int pos = atomicAdd(&g_cur[dst], 1);
    g_csrc[pos] = src;
}
__global__ void __launch_bounds__(128) gather_k(const float* __restrict__ x,
                                                const float* __restrict__ gcn_b) {
    const int n = blockIdx.x;
    const int c = threadIdx.x * 4;
    const int s0 = g_off[n], s1 = g_off[n + 1];
    const float dv = g_deg[n];
    float4 acc = make_float4(0.f, 0.f, 0.f, 0.f);
    int e = s0;
    #pragma unroll 1
    for (; e + 2 <= s1; e += 2) {
        int srcA = g_csrc[e], srcB = g_csrc[e + 1];
        float nA = dv * g_deg[srcA], nB = dv * g_deg[srcB];
        float4 vA = *reinterpret_cast<const float4*>(&g_xw[(size_t)srcA * DD + c]);
        float4 vB = *reinterpret_cast<const float4*>(&g_xw[(size_t)srcB * DD + c]);
        acc.x += nA * vA.x + nB * vB.x;
        acc.y += nA * vA.y + nB * vB.y;
        acc.z += nA * vA.z + nB * vB.z;
        acc.w += nA * vA.w + nB * vB.w;
    }
    if (e < s1) {
        int src = g_csrc[e];
        float nrm = dv * g_deg[src];
        float4 v = *reinterpret_cast<const float4*>(&g_xw[(size_t)src * DD + c]);
        acc.x += nrm * v.x; acc.y += nrm * v.y; acc.z += nrm * v.z; acc.w += nrm * v.w;
    }
    float4 xw = *reinterpret_cast<const float4*>(&g_xw[(size_t)n * DD + c]);
    float4 xr = *reinterpret_cast<const float4*>(&x[(size_t)n * DD + c]);
    float4 bb = *reinterpret_cast<const float4*>(&gcn_b[c]);
    float d2 = dv * dv;
    float4 o;
    o.x = xr.x + acc.x + d2 * xw.x + bb.x;
    o.y = xr.y + acc.y + d2 * xw.y + bb.y;
    o.z = xr.z + acc.z + d2 * xw.z + bb.z;
    o.w = xr.w + acc.w + d2 * xw.w + bb.w;
    *reinterpret_cast<float4*>(&g_bufL[(size_t)n * DD + c]) = o;
}
__global__ void stats0_k() {
    const int c = threadIdx.x;
    const int r0 = blockIdx.x * 128;
    const int rEnd = min(r0 + 128, NN);
    float s = 0.f, s2 = 0.f;
    for (int r = r0; r < rEnd; r++) {
        float v = g_bufL[(size_t)r * DD + c];
        s += v; s2 += v * v;
    }
    atomicAdd(&g_stats[0 * DD + c], s);
    atomicAdd(&g_stats[1 * DD + c], s2);
}

__global__ void finalize_k(int bn, const float* __restrict__ gamma, const float* __restrict__ beta) {
    int c = threadIdx.x;
    float s  = g_stats[(bn * 2 + 0) * DD + c];
    float s2 = g_stats[(bn * 2 + 1) * DD + c];
    float m = s * (1.0f / NN);
    float var = s2 * (1.0f / NN) - m * m;
    float a = gamma[c] * rsqrtf(var + EPSC);
    g_coef[(bn * 2 + 0) * DD + c] = a;
    g_coef[(bn * 2 + 1) * DD + c] = beta[c] - m * a;
}

__global__ void apply_sum_k() {
    int i = blockIdx.x * blockDim.x + threadIdx.x;
    if (i >= NN * DD / 2) return;
    int base = i * 2;
    int c = base & (DD - 1);
    float v0 = g_bufL[base] * g_coef[c] + g_coef[DD + c]
             + g_bufA[base] * g_coef[2 * DD + c] + g_coef[3 * DD + c];
    float v1 = g_bufL[base + 1] * g_coef[c + 1] + g_coef[DD + c + 1]
             + g_bufA[base + 1] * g_coef[2 * DD + c + 1] + g_coef[3 * DD + c + 1];
    g_h[base] = v0; g_h[base + 1] = v1;
    *reinterpret_cast<uint32_t*>(&g_hb[base]) = packbf(v0, v1);
}
__global__ void bn2_apply_k(float* __restrict__ out) {
    int idx = blockIdx.x * blockDim.x + threadIdx.x;
    if (idx >= NN * DD) return;
    int c = idx & (DD - 1);
    out[idx] = g_ff[idx] * g_coef[4 * DD + c] + g_coef[5 * DD + c];
}

// ---------------- wave helpers ----------------------------------------------
__global__ void pack_w_k(const float* __restrict__ linW, const float* __restrict__ fW) {
    int idx = blockIdx.x * blockDim.x + threadIdx.x;
    if (idx >= DD * DD) return;
    int d = idx >> 9, j = idx & 511;
    int t = j >> 7, s = j & 127;
    g_linWp[idx] = tf32r(linW[t * (DD * SSc) + d * SSc + s]);
    g_fWt[idx]   = tf32r(fW[idx]);
}
__global__ void post_u_k(const float* __restrict__ fs, const float* __restrict__ linB) {
    int idx = blockIdx.x * blockDim.x + threadIdx.x;
    if (idx >= (KK / 2) * DD) return;
    int kp = idx >> 9, j = idx & 511;
    int t = j >> 7, s = j & 127;
    float bl = linB[t * SSc + s];
    int k0 = 2 * kp, k1 = 2 * kp + 1;
    float v0 = fs[k0 * TJc + t] * (g_uraw[k0 * DD + j] + g_esum[k0] * bl);
    float v1 = fs[k1 * TJc + t] * (g_uraw[k1 * DD + j] + g_esum[k1] * bl);
    g_ubp[idx] = packbf(v0, v1);
}
__global__ void scale_u2_k(const float* __restrict__ fs) {
    int idx = blockIdx.x * blockDim.x + threadIdx.x;
    if (idx >= KK * DD) return;
    int k = idx >> 9, t = (idx & 511) >> 7;
    g_u2[idx] = tf32r(g_u2[idx] * fs[k * TJc + t]);
}

// ---------------- streams/events ----------------------------------------------
static cudaStream_t s_gcn = nullptr, s_aux = nullptr;
static cudaEvent_t ev_fork = nullptr, ev_xw = nullptr, ev_join = nullptr, ev_aux = nullptr;
namespace { struct StreamInit {
    StreamInit() {
        cudaStreamCreateWithFlags(&s_gcn, cudaStreamNonBlocking);
        cudaStreamCreateWithFlags(&s_aux, cudaStreamNonBlocking);
        cudaEventCreateWithFlags(&ev_fork, cudaEventDisableTiming);
        cudaEventCreateWithFlags(&ev_xw,   cudaEventDisableTiming);
        cudaEventCreateWithFlags(&ev_join, cudaEventDisableTiming);
        cudaEventCreateWithFlags(&ev_aux,  cudaEventDisableTiming);
    }
} s_init; }

// ---------------- launch -----------------------------------------------------
#define GSYM(p, ty, s) do { void* _t; cudaGetSymbolAddress(&_t, s); (p) = (ty)_t; } while (0)

extern "C" void kernel_launch(void* const* d_in, const int* in_sizes, int n_in,
                              void* d_out, int out_size) {
    const float* x        = (const float*)d_in[0];
    const void*  ei       = d_in[1];
    const float* evc      = (const float*)d_in[2];
    const float* fs       = (const float*)d_in[3];
    const float* gcn_W    = (const float*)d_in[4];
    const float* gcn_b    = (const float*)d_in[5];
    const float* lin_W    = (const float*)d_in[6];
    const float* lin_b    = (const float*)d_in[7];
    const float* fusion_W = (const float*)d_in[8];
    const float* fusion_b = (const float*)d_in[9];
    const float* bn1l_g   = (const float*)d_in[10];
    const float* bn1l_b   = (const float*)d_in[11];
    const float* bn1a_g   = (const float*)d_in[12];
    const float* bn1a_b   = (const float*)d_in[13];
    const float* bn2_g    = (const float*)d_in[14];
    const float* bn2_b    = (const float*)d_in[15];
    const float* ff1_W    = (const float*)d_in[16];
    const float* ff1_b    = (const float*)d_in[17];
    const float* ff2_W    = (const float*)d_in[18];
    const float* ff2_b    = (const float*)d_in[19];
    float* out = (float*)d_out;

    float *p_xw, *p_bufL, *p_v, *p_bufA, *p_h, *p_ff, *p_evct;
    float *p_xe, *p_uraw, *p_u2, *p_W2, *p_linWp, *p_fWt;
    __nv_bfloat16 *p_xb, *p_evcb, *p_hb, *p_midb;
    uint32_t *p_gWbp, *p_f1Wbp, *p_f2Wbp, *p_W2bp, *p_ubp;
    GSYM(p_xw, float*, g_xw);     GSYM(p_bufL, float*, g_bufL); GSYM(p_v, float*, g_v);
    GSYM(p_bufA, float*, g_bufA); GSYM(p_h, float*, g_h);       GSYM(p_ff, float*, g_ff);
    GSYM(p_evct, float*, g_evct);
    GSYM(p_xe, float*, g_xe);     GSYM(p_uraw, float*, g_uraw);
    GSYM(p_u2, float*, g_u2);     GSYM(p_W2, float*, g_W2);
    GSYM(p_linWp, float*, g_linWp); GSYM(p_fWt, float*, g_fWt);
    GSYM(p_xb, __nv_bfloat16*, g_xb);   GSYM(p_evcb, __nv_bfloat16*, g_evcb);
    GSYM(p_hb, __nv_bfloat16*, g_hb);   GSYM(p_midb, __nv_bfloat16*, g_midb);
    GSYM(p_gWbp, uint32_t*, g_gWbp);    GSYM(p_f1Wbp, uint32_t*, g_f1Wbp);
    GSYM(p_f2Wbp, uint32_t*, g_f2Wbp);  GSYM(p_W2bp, uint32_t*, g_W2bp);
    GSYM(p_ubp, uint32_t*, g_ubp);

    const int GEMM_SMEM = (2 * 128 * 36 + 2 * 32 * 136) * 4;   // 71680
    const int BF_SMEM   = GEMM_SMEM;
    const int ATB_SMEM  = (2 * 32 * 136 * 2) * 4;
    cudaFuncSetAttribute(tcgemm_k, cudaFuncAttributeMaxDynamicSharedMemorySize, GEMM_SMEM);
    cudaFuncSetAttribute(atb_k<false>, cudaFuncAttributeMaxDynamicSharedMemorySize, ATB_SMEM);
    cudaFuncSetAttribute(atb_k<true>,  cudaFuncAttributeMaxDynamicSharedMemorySize, ATB_SMEM);
    cudaFuncSetAttribute(bfgemm_k<false, false, false, false, false>, cudaFuncAttributeMaxDynamicSharedMemorySize, BF_SMEM);
    cudaFuncSetAttribute(bfgemm_k<false, true,  true,  false, false>, cudaFuncAttributeMaxDynamicSharedMemorySize, BF_SMEM);
    cudaFuncSetAttribute(bfgemm_k<true,  true,  false, false, true >, cudaFuncAttributeMaxDynamicSharedMemorySize, BF_SMEM);
    cudaFuncSetAttribute(bfgemm_k<true,  true,  false, true,  false>, cudaFuncAttributeMaxDynamicSharedMemorySize, BF_SMEM);
    cudaFuncSetAttribute(bfgemm_k<true,  false, false, false, true >, cudaFuncAttributeMaxDynamicSharedMemorySize, BF_SMEM);

    const int MB = (NN + 127) / 128;
    dim3 gD(4, MB);
    dim3 gF(8, MB);
    dim3 gTiny(4, 1);
    dim3 gAtbX(ATB_BLKS, 4, 1);
    dim3 gAtbU(ATB_BLKS, 4, 1);

    detect_k<<<1, 256>>>((const int*)ei);
    zero_scratch_k<<<1024, 256>>>();

    // ---- fork ----
    cudaEventRecord(ev_fork, 0);
    cudaStreamWaitEvent(s_gcn, ev_fork, 0);
    cudaStreamWaitEvent(s_aux, ev_fork, 0);

    // s_gcn: CSR build
    degi_k<<<(EE + 255) / 256, 256, 0, s_gcn>>>(ei);
    dinv_k<<<(NN + 255) / 256, 256, 0, s_gcn>>>();
    scan_k<<<1, 1024, 0, s_gcn>>>();
    fill_k<<<(EE + 255) / 256, 256, 0, s_gcn>>>(ei);

    // s_aux: weight packs needed later
    pack_w_k<<<(DD * DD + 255) / 256, 256, 0, s_aux>>>(lin_W, fusion_W);
    packpairs_k<<<((DD / 2) * DD2 + 255) / 256, 256, 0, s_aux>>>(ff1_W, p_f1Wbp, DD2, (DD / 2) * DD2);
    packpairs_k<<<((DD2 / 2) * DD + 255) / 256, 256, 0, s_aux>>>(ff2_W, p_f2Wbp, DD, (DD2 / 2) * DD);
    cudaEventRecord(ev_aux, s_aux);

    // main: prep + xw GEMM
    packpairs_k<<<((DD / 2) * DD + 255) / 256, 256>>>(gcn_W, p_gWbp, DD, (DD / 2) * DD);
    round_k<<<256, 256>>>(evc, p_evct, (long long)NN * KK);
    tobf_k<<<1024, 256>>>(x, p_xb, (long long)NN * DD);
    tobf_k<<<256, 256>>>(evc, p_evcb, (long long)NN * KK);
    bfgemm_k<false, false, false, false, false><<<gD, 256, BF_SMEM>>>(
        p_xb, DD, p_gWbp, DD, 0, p_xw, DD, 0, nullptr, NN, DD, nullptr, 0);
    cudaEventRecord(ev_xw, 0);

    // s_gcn: gather + BN0 stats (needs xw)
    cudaStreamWaitEvent(s_gcn, ev_xw, 0);
    gather_k<<<NN, 128, 0, s_gcn>>>(x, gcn_b);
    stats0_k<<<MB, DD, 0, s_gcn>>>();
    cudaEventRecord(ev_join, s_gcn);

    // main: wave branch
    colsum_k<<<(NN + 499) / 500, KK>>>(evc);
    atb_k<true><<<gAtbX, 256, ATB_SMEM>>>(p_evct, x, DD, p_xe, DD);
    round_k<<<64, 256>>>(p_xe, p_xe, KK * DD);
    cudaStreamWaitEvent(0, ev_aux, 0);
    tcgemm_k<<<gTiny, 256, GEMM_SMEM>>>(p_xe, DD, p_linWp, DD, p_uraw, DD, KK, DD);
    post_u_k<<<((KK / 2) * DD + 255) / 256, 256>>>(fs, lin_b);
    // v[N,512] = relu(evc @ u) over all t in one launch
    bfgemm_k<false, true, true, false, false><<<gD, 256, BF_SMEM>>>(
        p_evcb, KK, p_ubp, DD, 0, p_v, DD, 0, nullptr, NN, KK, nullptr, 0);
    atb_k<false><<<gAtbU, 256, ATB_SMEM>>>(p_evct, p_v, DD, p_u2, DD);
    scale_u2_k<<<(KK * DD + 255) / 256, 256>>>(fs);
    tcgemm_k<<<gTiny, 256, GEMM_SMEM>>>(p_u2, DD, p_fWt, DD, p_W2, DD, KK, DD);
    packpairs_k<<<((KK / 2) * DD + 255) / 256, 256>>>(p_W2, p_W2bp, DD, (KK / 2) * DD);
    bfgemm_k<true, true, false, false, true><<<gD, 256, BF_SMEM>>>(
        p_evcb, KK, p_W2bp, DD, 0, p_bufA, DD, 0, fusion_b, NN, KK, x, 1);

    // ---- join + BN ----
    cudaStreamWaitEvent(0, ev_join, 0);
    finalize_k<<<1, DD>>>(0, bn1l_g, bn1l_b);
    finalize_k<<<1, DD>>>(1, bn1a_g, bn1a_b);
    apply_sum_k<<<(NN * DD / 2 + 255) / 256, 256>>>();

    // ---- feed-forward ----
    bfgemm_k<true, true, false, true, false><<<gF, 256, BF_SMEM>>>(
        p_hb, DD, p_f1Wbp, DD2, 0, p_midb, DD2, 0, ff1_b, NN, DD, nullptr, 0);
    bfgemm_k<true, false, false, false, true><<<gD, 256, BF_SMEM>>>(
        p_midb, DD2, p_f2Wbp, DD, 0, p_ff, DD, 0, ff2_b, NN, DD2, p_h, 2);
    finalize_k<<<1, DD>>>(2, bn2_g, bn2_b);
    bn2_apply_k<<<(NN * DD + 255) / 256, 256>>>(out);
}